// round 10
// baseline (speedup 1.0000x reference)
#include <cuda_runtime.h>
#include <cuda_bf16.h>
#include <mma.h>
#include <cstdint>

using namespace nvcuda;

#define NN 50000
#define EE 800000
#define LL 128
#define NSTEPS 10
#define NB_ENC 782          // ceil(NN/64)
#define EB_ENC 12500        // EE/64

// ---- scratch (device globals; no allocations allowed) ----
__device__ float g_nl[(size_t)NN * LL];
// el stored as bf16 hi/lo planes, tile-major: [tile(64 edges)][hi 64x128][lo 64x128]
__device__ __nv_bfloat16 g_el[(size_t)EE * 256];
__device__ float g_agg[(size_t)NN * LL];
__device__ float g_z[(size_t)NN * 256];
__device__ float g_deg[NN];
__device__ float g_center[3];

#define EW1A_HI 0
#define EW1A_LO 16384
#define EW2_HI  32768
#define EW2_LO  49152
#define PRJ_HI  65536
#define PRJ_LO  98304
#define NW1_HI  131072
#define NW1_LO  163840
#define NW2_HI  196608
#define NW2_LO  212992
#define STEP_W  229376
__device__ __nv_bfloat16 g_ws[(size_t)NSTEPS * STEP_W];

typedef wmma::fragment<wmma::matrix_a, 16, 16, 16, __nv_bfloat16, wmma::row_major> AF;
typedef wmma::fragment<wmma::matrix_b, 16, 16, 16, __nv_bfloat16, wmma::row_major> BF;
typedef wmma::fragment<wmma::accumulator, 16, 16, 16, float> CF;

__device__ __forceinline__ uint32_t smem_u32(const void* p) {
    uint32_t a;
    asm("{ .reg .u64 t; cvta.to.shared.u64 t, %1; cvt.u32.u64 %0, t; }" : "=r"(a) : "l"(p));
    return a;
}
__device__ __forceinline__ void cp_async16(uint32_t dst, const void* src) {
    asm volatile("cp.async.ca.shared.global [%0], [%1], 16;" :: "r"(dst), "l"(src) : "memory");
}
__device__ __forceinline__ void cp_commit() {
    asm volatile("cp.async.commit_group;" ::: "memory");
}
__device__ __forceinline__ void cp_wait0() {
    asm volatile("cp.async.wait_group 0;" ::: "memory");
}
__device__ __forceinline__ void cp_commit_wait() {
    cp_commit();
    cp_wait0();
}

__device__ __forceinline__ void split_store4(float4 v, __nv_bfloat16* hip, __nv_bfloat16* lop) {
    __nv_bfloat162 h0 = __floats2bfloat162_rn(v.x, v.y);
    __nv_bfloat162 h1 = __floats2bfloat162_rn(v.z, v.w);
    float2 f0 = __bfloat1622float2(h0);
    float2 f1 = __bfloat1622float2(h1);
    __nv_bfloat162 l0 = __floats2bfloat162_rn(v.x - f0.x, v.y - f0.y);
    __nv_bfloat162 l1 = __floats2bfloat162_rn(v.z - f1.x, v.w - f1.y);
    *(__nv_bfloat162*)(hip)     = h0;
    *(__nv_bfloat162*)(hip + 2) = h1;
    *(__nv_bfloat162*)(lop)     = l0;
    *(__nv_bfloat162*)(lop + 2) = l1;
}

__device__ __forceinline__ void red_add_v2(float* dst, float a, float b) {
    asm volatile("red.global.add.v2.f32 [%0], {%1,%2};"
                 :: "l"(dst), "f"(a), "f"(b) : "memory");
}

// ---------------------------------------------------------------- launch 0: weight prep + init
__global__ void __launch_bounds__(256) k_setup(
    const float* __restrict__ pe_w1, const float* __restrict__ pe_w2,
    const float* __restrict__ pn_w1, const float* __restrict__ pn_w2)
{
    if (blockIdx.x < 4480) {
        int idx = blockIdx.x * 256 + threadIdx.x;
        int s = idx / 114688;
        int e = idx % 114688;
        float v;
        size_t dhi, dlo;
        if (e < 16384) {
            v = pe_w1[(size_t)s * 384 * 128 + e];
            dhi = EW1A_HI + e; dlo = EW1A_LO + e;
        } else if (e < 32768) {
            int e2 = e - 16384;
            v = pe_w2[(size_t)s * 128 * 128 + e2];
            dhi = EW2_HI + e2; dlo = EW2_LO + e2;
        } else if (e < 65536) {
            int e2 = e - 32768;
            int k = e2 >> 8, n = e2 & 255;
            int srcrow = 128 + (n >> 7) * 128 + k;
            v = pe_w1[(size_t)s * 384 * 128 + (size_t)srcrow * 128 + (n & 127)];
            dhi = PRJ_HI + e2; dlo = PRJ_LO + e2;
        } else if (e < 98304) {
            int e2 = e - 65536;
            v = pn_w1[(size_t)s * 256 * 128 + e2];
            dhi = NW1_HI + e2; dlo = NW1_LO + e2;
        } else {
            int e2 = e - 98304;
            v = pn_w2[(size_t)s * 128 * 128 + e2];
            dhi = NW2_HI + e2; dlo = NW2_LO + e2;
        }
        __nv_bfloat16 h = __float2bfloat16(v);
        g_ws[(size_t)s * STEP_W + dhi] = h;
        g_ws[(size_t)s * STEP_W + dlo] = __float2bfloat16(v - __bfloat162float(h));
    } else {
        int i = (blockIdx.x - 4480) * 256 + threadIdx.x;
        if (i < NN) g_deg[i] = 0.f;
        if (i < 3) g_center[i] = 0.f;
    }
}

// ---------------------------------------------------------------- launch 1: degree + center
__global__ void __launch_bounds__(256) k_degcenter(
    const int* __restrict__ rcv, const float* __restrict__ pos)
{
    if (blockIdx.x < 3125) {
        int i = blockIdx.x * 256 + threadIdx.x;
        if (i < EE) atomicAdd(&g_deg[rcv[i]], 1.f);
    } else {
        float sx = 0.f, sy = 0.f, sz = 0.f;
        for (int i = (blockIdx.x - 3125) * 256 + threadIdx.x; i < NN; i += 104 * 256) {
            sx += pos[i * 3 + 0];
            sy += pos[i * 3 + 1];
            sz += pos[i * 3 + 2];
        }
#pragma unroll
        for (int o = 16; o > 0; o >>= 1) {
            sx += __shfl_down_sync(0xffffffffu, sx, o);
            sy += __shfl_down_sync(0xffffffffu, sy, o);
            sz += __shfl_down_sync(0xffffffffu, sz, o);
        }
        if ((threadIdx.x & 31) == 0) {
            atomicAdd(&g_center[0], sx);
            atomicAdd(&g_center[1], sy);
            atomicAdd(&g_center[2], sz);
        }
    }
}

// ---------------------------------------------------------------- launch 2: all encoders
#define ENC_SMEM 141312

__global__ void __launch_bounds__(256, 1) k_enc_all(
    const float* __restrict__ pos, const float* __restrict__ vel,
    const int* __restrict__ rid, const float* __restrict__ remb,
    const int* __restrict__ snd, const int* __restrict__ rcv,
    const float* __restrict__ nW1, const float* __restrict__ nB1,
    const float* __restrict__ nW2, const float* __restrict__ nB2,
    const float* __restrict__ eW1, const float* __restrict__ eB1,
    const float* __restrict__ eW2, const float* __restrict__ eB2)
{
    extern __shared__ char smc[];
    const int tid = threadIdx.x;

    if (blockIdx.x < NB_ENC) {
        // ===== node encoder (64 nodes) + projection step 0 =====
        float* F = (float*)(smc + 0);
        float* H = (float*)(smc + 8192);
        __nv_bfloat16* Ahi = (__nv_bfloat16*)(smc + 40960);
        __nv_bfloat16* Alo = (__nv_bfloat16*)(smc + 58368);
        __nv_bfloat16* Wch = (__nv_bfloat16*)(smc + 75776);
        __nv_bfloat16* Wcl = (__nv_bfloat16*)(smc + 93184);
        const int nbase = blockIdx.x * 64;
        const float inv = 1.f / (float)NN;
        const float cx = g_center[0] * inv, cy = g_center[1] * inv, cz = g_center[2] * inv;

        for (int i = tid; i < 64 * 23; i += 256) {
            int n = i / 23, k = i % 23;
            int gn = nbase + n;
            float v = 0.f;
            if (gn < NN) {
                if (k < 3) v = vel[gn * 3 + k];
                else if (k < 6) v = pos[gn * 3 + (k - 3)] - ((k == 3) ? cx : (k == 4) ? cy : cz);
                else if (k == 6) v = g_deg[gn];
                else v = remb[rid[gn] * 16 + (k - 7)];
            }
            F[n * 24 + k] = v;
        }
        __syncthreads();

        const int j = tid & 127;
        for (int n = tid >> 7; n < 64; n += 2) {
            float acc = nB1[j];
#pragma unroll
            for (int k = 0; k < 23; k++) acc += F[n * 24 + k] * nW1[k * 128 + j];
            H[n * 128 + j] = fmaxf(acc, 0.f);
        }
        __syncthreads();
        for (int n = tid >> 7; n < 64; n += 2) {
            int gn = nbase + n;
            float acc = nB2[j];
#pragma unroll 8
            for (int k = 0; k < 128; k++) acc += H[n * 128 + k] * nW2[k * 128 + j];
            float v = (gn < NN) ? acc : 0.f;
            if (gn < NN) g_nl[(size_t)gn * LL + j] = v;
            __nv_bfloat16 h = __float2bfloat16(v);
            Ahi[n * 136 + j] = h;
            Alo[n * 136 + j] = __float2bfloat16(v - __bfloat162float(h));
        }
        __syncthreads();

        // projection Z(0) = nl @ PRJ(0)
        const int w = tid >> 5, rt = w >> 1, cg = w & 1;
        const bool full = (nbase + 64 <= NN);
        const __nv_bfloat16* wn = g_ws;
        CF acc[4];
#pragma unroll 1
        for (int half = 0; half < 2; ++half) {
#pragma unroll
            for (int f = 0; f < 4; f++) wmma::fill_fragment(acc[f], 0.f);
            for (int kc = 0; kc < 128; kc += 64) {
                __syncthreads();
                for (int i = tid; i < 1024; i += 256) {
                    int rr = i >> 4, g = i & 15;
                    *(float4*)(Wch + rr * 136 + g * 8) =
                        ((const float4*)(wn + PRJ_HI + (size_t)(kc + rr) * 256 + half * 128))[g];
                    *(float4*)(Wcl + rr * 136 + g * 8) =
                        ((const float4*)(wn + PRJ_LO + (size_t)(kc + rr) * 256 + half * 128))[g];
                }
                __syncthreads();
                for (int kk = 0; kk < 64; kk += 16) {
                    AF ah, al;
                    wmma::load_matrix_sync(ah, Ahi + rt * 16 * 136 + kc + kk, 136);
                    wmma::load_matrix_sync(al, Alo + rt * 16 * 136 + kc + kk, 136);
#pragma unroll
                    for (int f = 0; f < 4; f++) {
                        BF bh, bl;
                        wmma::load_matrix_sync(bh, Wch + kk * 136 + cg * 64 + f * 16, 136);
                        wmma::load_matrix_sync(bl, Wcl + kk * 136 + cg * 64 + f * 16, 136);
                        wmma::mma_sync(acc[f], ah, bh, acc[f]);
                        wmma::mma_sync(acc[f], ah, bl, acc[f]);
                        wmma::mma_sync(acc[f], al, bh, acc[f]);
                    }
                }
            }
            if (full) {
#pragma unroll
                for (int f = 0; f < 4; f++)
                    wmma::store_matrix_sync(g_z + (size_t)(nbase + rt * 16) * 256 + half * 128 + cg * 64 + f * 16,
                                            acc[f], 256, wmma::mem_row_major);
            } else {
                float* Cf = (float*)(smc + 75776);   // dead W region; restaged next half
                __syncthreads();
#pragma unroll
                for (int f = 0; f < 4; f++)
                    wmma::store_matrix_sync(Cf + rt * 16 * 132 + cg * 64 + f * 16, acc[f], 132, wmma::mem_row_major);
                __syncthreads();
                for (int i = tid; i < 64 * 32; i += 256) {
                    int row = i >> 5, c4 = i & 31;
                    int n = nbase + row;
                    if (n < NN)
                        ((float4*)(g_z + (size_t)n * 256 + half * 128))[c4] =
                            *(float4*)(Cf + row * 132 + c4 * 4);
                }
            }
        }
        return;
    }

    // ===== edge encoder =====
    {
        const int LDF = 12, LDH = 132, LDHB = 136, LDWB = 136;
        float*         F   = (float*)(smc + 0);
        float*         Hf  = (float*)(smc + 3072);
        __nv_bfloat16* Hhi = (__nv_bfloat16*)(smc + 36864);
        __nv_bfloat16* Hlo = (__nv_bfloat16*)(smc + 54272);
        __nv_bfloat16* Whi = (__nv_bfloat16*)(smc + 71680);
        __nv_bfloat16* Wlo = (__nv_bfloat16*)(smc + 106496);
        const int w = tid >> 5, rt = w >> 1, cg = w & 1;
        const int tile = blockIdx.x - NB_ENC;
        const int ebase = tile * 64;

        if (tid < 64) {
            int e = ebase + tid;
            int s = snd[e], r = rcv[e];
            float rp0 = pos[s * 3 + 0] - pos[r * 3 + 0];
            float rp1 = pos[s * 3 + 1] - pos[r * 3 + 1];
            float rp2 = pos[s * 3 + 2] - pos[r * 3 + 2];
            float rv0 = vel[s * 3 + 0] - vel[r * 3 + 0];
            float rv1 = vel[s * 3 + 1] - vel[r * 3 + 1];
            float rv2 = vel[s * 3 + 2] - vel[r * 3 + 2];
            float sq = rp0 * rp0 + rp1 * rp1 + rp2 * rp2;
            float dist = sqrtf(sq);
            float same = (rid[s] == rid[r]) ? 1.f : 0.f;
            float* f = F + tid * LDF;
            f[0] = rp0; f[1] = rp1; f[2] = rp2;
            f[3] = rv0; f[4] = rv1; f[5] = rv2;
            f[6] = dist; f[7] = sq; f[8] = same;
        }
        for (int i = tid; i < 128 * 32; i += 256) {
            int rr = i >> 5, c4 = i & 31;
            float4 v = ((const float4*)(eW2 + rr * 128))[c4];
            split_store4(v, Whi + rr * LDWB + c4 * 4, Wlo + rr * LDWB + c4 * 4);
        }
        __syncthreads();

        for (int i = tid; i < 64 * 128; i += 256) {
            int e = i >> 7, jj = i & 127;
            const float* f = F + e * LDF;
            float acc = eB1[jj];
#pragma unroll
            for (int k = 0; k < 9; k++) acc += f[k] * eW1[k * 128 + jj];
            Hf[e * LDH + jj] = fmaxf(acc, 0.f);
        }
        __syncthreads();
        for (int i = tid; i < 64 * 32; i += 256) {
            int row = i >> 5, c4 = i & 31;
            float4 v = ((const float4*)(Hf + row * LDH))[c4];
            split_store4(v, Hhi + row * LDHB + c4 * 4, Hlo + row * LDHB + c4 * 4);
        }
        __syncthreads();

        CF acc[4];
#pragma unroll
        for (int f = 0; f < 4; f++) wmma::fill_fragment(acc[f], 0.f);

        for (int kk = 0; kk < 128; kk += 16) {
            AF ah, al;
            wmma::load_matrix_sync(ah, Hhi + rt * 16 * LDHB + kk, LDHB);
            wmma::load_matrix_sync(al, Hlo + rt * 16 * LDHB + kk, LDHB);
#pragma unroll
            for (int f = 0; f < 4; f++) {
                BF bh, bl;
                wmma::load_matrix_sync(bh, Whi + kk * LDWB + cg * 64 + f * 16, LDWB);
                wmma::load_matrix_sync(bl, Wlo + kk * LDWB + cg * 64 + f * 16, LDWB);
                wmma::mma_sync(acc[f], ah, bh, acc[f]);
                wmma::mma_sync(acc[f], ah, bl, acc[f]);
                wmma::mma_sync(acc[f], al, bh, acc[f]);
            }
        }
        __syncthreads();
#pragma unroll
        for (int f = 0; f < 4; f++)
            wmma::store_matrix_sync(Hf + rt * 16 * LDH + cg * 64 + f * 16, acc[f], LDH, wmma::mem_row_major);
        __syncthreads();

        __nv_bfloat16* elbase = g_el + (size_t)tile * 16384;
        for (int i = tid; i < 64 * 32; i += 256) {
            int e = i >> 5, c4 = i & 31;
            float4 c2 = ((const float4*)(Hf + e * LDH))[c4];
            float4 bb = ((const float4*)eB2)[c4];
            float4 nv = make_float4(c2.x + bb.x, c2.y + bb.y, c2.z + bb.z, c2.w + bb.w);
            __nv_bfloat16* hp = elbase + e * 128 + c4 * 4;
            split_store4(nv, hp, hp + 8192);
        }
    }
}

// ---------------------------------------------------------------- edge processor step
// 64 edges/block, 256 threads, 8 warps tiled 2x4 (warp = 32 rows x 32 cols).
// Register-resident epilogues via known m16n16k16 accumulator layout:
//   lane g=lane>>2, t=lane&3; x[0,1]=(g,2t..), x[2,3]=(g+8,..), x[4..7]=cols+8.
#define ES_SSH 0
#define ES_RSH 256
#define ES_AHI 1536
#define ES_ALO 18944
#define ES_W   36352
#define ES_WLO 53760
#define ES_SMEM 71168

__global__ void __launch_bounds__(256, 3) k_edge_step(
    const int* __restrict__ snd, const int* __restrict__ rcv, int step,
    const float* __restrict__ B1, const float* __restrict__ B2)
{
    extern __shared__ char smc[];
    int*   ssh = (int*)(smc + ES_SSH);
    int*   rsh = (int*)(smc + ES_RSH);
    __nv_bfloat16* Ahi = (__nv_bfloat16*)(smc + ES_AHI);   // 64 x 136
    __nv_bfloat16* Alo = (__nv_bfloat16*)(smc + ES_ALO);
    __nv_bfloat16* Whi = (__nv_bfloat16*)(smc + ES_W);     // 64 x 136 (K-chunk)
    __nv_bfloat16* Wlo = (__nv_bfloat16*)(smc + ES_WLO);
    const int tid = threadIdx.x;
    const int w = tid >> 5, rt = w & 1, cg = w >> 1;       // 2 x 4 tiling
    const int lane = tid & 31, gid = lane >> 2, tg = lane & 3;
    const int ebase = blockIdx.x * 64;
    const __nv_bfloat16* wbase = g_ws + (size_t)step * STEP_W;
    __nv_bfloat16* elbase = g_el + (size_t)blockIdx.x * 16384;
    const uint32_t whi_b = smem_u32(Whi), wlo_b = smem_u32(Wlo);
    const uint32_t ahi_b = smem_u32(Ahi), alo_b = smem_u32(Alo);

    if (tid < 64) {
        ssh[tid] = snd[ebase + tid];
        rsh[tid] = rcv[ebase + tid];
    }
    // cp.async el planes into A; W1a chunk 0
    for (int i = tid; i < 1024; i += 256) {
        int r = i >> 4, g = i & 15;
        cp_async16(ahi_b + (uint32_t)(r * 272 + g * 16), elbase + r * 128 + g * 8);
        cp_async16(alo_b + (uint32_t)(r * 272 + g * 16), elbase + 8192 + r * 128 + g * 8);
        cp_async16(whi_b + (uint32_t)(r * 272 + g * 16), wbase + EW1A_HI + r * 128 + g * 8);
        cp_async16(wlo_b + (uint32_t)(r * 272 + g * 16), wbase + EW1A_LO + r * 128 + g * 8);
    }
    cp_commit_wait();
    __syncthreads();

    // per-thread element coordinates (4 row slots x 4 col slots)
    int rows[4], svals[4], rvals[4], cols[4];
#pragma unroll
    for (int sr = 0; sr < 2; sr++) {
        rows[sr * 2 + 0] = rt * 32 + sr * 16 + gid;
        rows[sr * 2 + 1] = rt * 32 + sr * 16 + gid + 8;
    }
#pragma unroll
    for (int q = 0; q < 4; q++) { svals[q] = ssh[rows[q]]; rvals[q] = rsh[rows[q]]; }
#pragma unroll
    for (int sc = 0; sc < 2; sc++) {
        cols[sc * 2 + 0] = cg * 32 + sc * 16 + 2 * tg;
        cols[sc * 2 + 1] = cg * 32 + sc * 16 + 2 * tg + 8;
    }

    CF acc[2][2];
#pragma unroll
    for (int sr = 0; sr < 2; sr++)
#pragma unroll
        for (int sc = 0; sc < 2; sc++) wmma::fill_fragment(acc[sr][sc], 0.f);

    // ---- GEMM1: el @ W1a, K chunked by 64
#pragma unroll 1
    for (int kc = 0; kc < 128; kc += 64) {
        if (kc) {
            __syncthreads();
            for (int i = tid; i < 1024; i += 256) {
                int r = i >> 4, g = i & 15;
                cp_async16(whi_b + (uint32_t)(r * 272 + g * 16), wbase + EW1A_HI + (kc + r) * 128 + g * 8);
                cp_async16(wlo_b + (uint32_t)(r * 272 + g * 16), wbase + EW1A_LO + (kc + r) * 128 + g * 8);
            }
            cp_commit_wait();
            __syncthreads();
        }
        for (int kk = 0; kk < 64; kk += 16) {
            AF ah[2], al[2];
#pragma unroll
            for (int sr = 0; sr < 2; sr++) {
                wmma::load_matrix_sync(ah[sr], Ahi + (rt * 32 + sr * 16) * 136 + kc + kk, 136);
                wmma::load_matrix_sync(al[sr], Alo + (rt * 32 + sr * 16) * 136 + kc + kk, 136);
            }
#pragma unroll
            for (int sc = 0; sc < 2; sc++) {
                BF bh, bl;
                wmma::load_matrix_sync(bh, Whi + kk * 136 + cg * 32 + sc * 16, 136);
                wmma::load_matrix_sync(bl, Wlo + kk * 136 + cg * 32 + sc * 16, 136);
#pragma unroll
                for (int sr = 0; sr < 2; sr++) {
                    wmma::mma_sync(acc[sr][sc], ah[sr], bh, acc[sr][sc]);
                    wmma::mma_sync(acc[sr][sc], ah[sr], bl, acc[sr][sc]);
                    wmma::mma_sync(acc[sr][sc], al[sr], bh, acc[sr][sc]);
                }
            }
        }
    }
    __syncthreads();   // all GEMM1 reads of A and W done

    // issue W2 chunk 0 cp.async NOW (transfer hides under register epilogue 1)
    for (int i = tid; i < 1024; i += 256) {
        int r = i >> 4, g = i & 15;
        cp_async16(whi_b + (uint32_t)(r * 272 + g * 16), wbase + EW2_HI + r * 128 + g * 8);
        cp_async16(wlo_b + (uint32_t)(r * 272 + g * 16), wbase + EW2_LO + r * 128 + g * 8);
    }
    cp_commit();

    // ---- epilogue 1 (registers): v = relu(C1 + Z[s] + Z[r] + B1) -> H planes (overwrite A)
    {
        float2 b1v[4];
#pragma unroll
        for (int cq = 0; cq < 4; cq++) b1v[cq] = *(const float2*)(B1 + cols[cq]);
#pragma unroll
        for (int sr = 0; sr < 2; sr++)
#pragma unroll
            for (int sc = 0; sc < 2; sc++)
#pragma unroll
                for (int e = 0; e < 4; e++) {
                    int q = sr * 2 + (e & 1);
                    int cq = sc * 2 + (e >> 1);
                    int row = rows[q], col = cols[cq];
                    float2 zb = *(const float2*)(g_z + (size_t)svals[q] * 256 + col);
                    float2 zc = *(const float2*)(g_z + (size_t)rvals[q] * 256 + 128 + col);
                    float v0 = fmaxf(acc[sr][sc].x[2 * e]     + zb.x + zc.x + b1v[cq].x, 0.f);
                    float v1 = fmaxf(acc[sr][sc].x[2 * e + 1] + zb.y + zc.y + b1v[cq].y, 0.f);
                    __nv_bfloat162 h = __floats2bfloat162_rn(v0, v1);
                    float2 hf = __bfloat1622float2(h);
                    __nv_bfloat162 l = __floats2bfloat162_rn(v0 - hf.x, v1 - hf.y);
                    *(__nv_bfloat162*)(Ahi + row * 136 + col) = h;
                    *(__nv_bfloat162*)(Alo + row * 136 + col) = l;
                }
    }
    cp_wait0();
    __syncthreads();

    // ---- GEMM2: H @ W2, K chunked by 64
#pragma unroll
    for (int sr = 0; sr < 2; sr++)
#pragma unroll
        for (int sc = 0; sc < 2; sc++) wmma::fill_fragment(acc[sr][sc], 0.f);
#pragma unroll 1
    for (int kc = 0; kc < 128; kc += 64) {
        if (kc) {
            __syncthreads();
            for (int i = tid; i < 1024; i += 256) {
                int r = i >> 4, g = i & 15;
                cp_async16(whi_b + (uint32_t)(r * 272 + g * 16), wbase + EW2_HI + (kc + r) * 128 + g * 8);
                cp_async16(wlo_b + (uint32_t)(r * 272 + g * 16), wbase + EW2_LO + (kc + r) * 128 + g * 8);
            }
            cp_commit_wait();
            __syncthreads();
        }
        for (int kk = 0; kk < 64; kk += 16) {
            AF ah[2], al[2];
#pragma unroll
            for (int sr = 0; sr < 2; sr++) {
                wmma::load_matrix_sync(ah[sr], Ahi + (rt * 32 + sr * 16) * 136 + kc + kk, 136);
                wmma::load_matrix_sync(al[sr], Alo + (rt * 32 + sr * 16) * 136 + kc + kk, 136);
            }
#pragma unroll
            for (int sc = 0; sc < 2; sc++) {
                BF bh, bl;
                wmma::load_matrix_sync(bh, Whi + kk * 136 + cg * 32 + sc * 16, 136);
                wmma::load_matrix_sync(bl, Wlo + kk * 136 + cg * 32 + sc * 16, 136);
#pragma unroll
                for (int sr = 0; sr < 2; sr++) {
                    wmma::mma_sync(acc[sr][sc], ah[sr], bh, acc[sr][sc]);
                    wmma::mma_sync(acc[sr][sc], ah[sr], bl, acc[sr][sc]);
                    wmma::mma_sync(acc[sr][sc], al[sr], bh, acc[sr][sc]);
                }
            }
        }
    }

    // ---- epilogue 2 (registers): el_new = el_old + C2 + b2 -> global planes; red.add agg
    {
        float2 b2v[4];
#pragma unroll
        for (int cq = 0; cq < 4; cq++) b2v[cq] = *(const float2*)(B2 + cols[cq]);
#pragma unroll
        for (int sr = 0; sr < 2; sr++)
#pragma unroll
            for (int sc = 0; sc < 2; sc++)
#pragma unroll
                for (int e = 0; e < 4; e++) {
                    int q = sr * 2 + (e & 1);
                    int cq = sc * 2 + (e >> 1);
                    int row = rows[q], col = cols[cq];
                    __nv_bfloat16* hp = elbase + row * 128 + col;
                    float2 ho = __bfloat1622float2(*(__nv_bfloat162*)hp);
                    float2 lo = __bfloat1622float2(*(__nv_bfloat162*)(hp + 8192));
                    float v0 = acc[sr][sc].x[2 * e]     + ho.x + lo.x + b2v[cq].x;
                    float v1 = acc[sr][sc].x[2 * e + 1] + ho.y + lo.y + b2v[cq].y;
                    __nv_bfloat162 h = __floats2bfloat162_rn(v0, v1);
                    float2 hf = __bfloat1622float2(h);
                    __nv_bfloat162 l = __floats2bfloat162_rn(v0 - hf.x, v1 - hf.y);
                    *(__nv_bfloat162*)hp = h;
                    *(__nv_bfloat162*)(hp + 8192) = l;
                    red_add_v2(g_agg + (size_t)rvals[q] * LL + col, v0, v1);
                }
    }
}

// ---------------------------------------------------------------- node step (+fused projection)
#define NS_XHI 0
#define NS_XLO 33792
#define NS_CF  0
#define NS_HHI 33792
#define NS_HLO 51200
#define NS_W   68608
#define NS_WLO 86016
#define NS_SMEM 103424

__global__ void __launch_bounds__(256, 2) k_node_step(
    int step, const float* __restrict__ B1, const float* __restrict__ B2, int do_proj)
{
    extern __shared__ char smc[];
    __nv_bfloat16* Xhi = (__nv_bfloat16*)(smc + NS_XHI);
    __nv_bfloat16* Xlo = (__nv_bfloat16*)(smc + NS_XLO);
    __nv_bfloat16* Whi = (__nv_bfloat16*)(smc + NS_W);
    __nv_bfloat16* Wlo = (__nv_bfloat16*)(smc + NS_WLO);
    float*         Cf  = (float*)(smc + NS_CF);
    __nv_bfloat16* Hhi = (__nv_bfloat16*)(smc + NS_HHI);
    __nv_bfloat16* Hlo = (__nv_bfloat16*)(smc + NS_HLO);
    const int tid = threadIdx.x;
    const int w = tid >> 5, rt = w >> 1, cg = w & 1;
    const int nbase = blockIdx.x * 64;
    const bool full = (nbase + 64 <= NN);
    const __nv_bfloat16* wbase = g_ws + (size_t)step * STEP_W;
    const uint32_t whi_b = smem_u32(Whi), wlo_b = smem_u32(Wlo);

    for (int i = tid; i < 64 * 64; i += 256) {
        int row = i >> 6, c4 = i & 63;
        int n = nbase + row;
        float4 v = make_float4(0.f, 0.f, 0.f, 0.f);
        if (n < NN) {
            if (c4 < 32) {
                v = ((const float4*)(g_nl + (size_t)n * LL))[c4];
            } else {
                float4* ap = (float4*)(g_agg + (size_t)n * LL) + (c4 - 32);
                v = *ap;
                *ap = make_float4(0.f, 0.f, 0.f, 0.f);
            }
        }
        split_store4(v, Xhi + row * 264 + c4 * 4, Xlo + row * 264 + c4 * 4);
    }

    CF acc[4];
#pragma unroll
    for (int f = 0; f < 4; f++) wmma::fill_fragment(acc[f], 0.f);

    for (int kc = 0; kc < 256; kc += 64) {
        __syncthreads();
        for (int i = tid; i < 1024; i += 256) {
            int rr = i >> 4, g = i & 15;
            cp_async16(whi_b + (uint32_t)(rr * 136 + g * 8) * 2, wbase + NW1_HI + (kc + rr) * 128 + g * 8);
            cp_async16(wlo_b + (uint32_t)(rr * 136 + g * 8) * 2, wbase + NW1_LO + (kc + rr) * 128 + g * 8);
        }
        cp_commit_wait();
        __syncthreads();
        for (int kk = 0; kk < 64; kk += 16) {
            AF ah, al;
            wmma::load_matrix_sync(ah, Xhi + rt * 16 * 264 + kc + kk, 264);
            wmma::load_matrix_sync(al, Xlo + rt * 16 * 264 + kc + kk, 264);
#pragma unroll
            for (int f = 0; f < 4; f++) {
                BF bh, bl;
                wmma::load_matrix_sync(bh, Whi + kk * 136 + cg * 64 + f * 16, 136);
                wmma::load_matrix_sync(bl, Wlo + kk * 136 + cg * 64 + f * 16, 136);
                wmma::mma_sync(acc[f], ah, bh, acc[f]);
                wmma::mma_sync(acc[f], ah, bl, acc[f]);
                wmma::mma_sync(acc[f], al, bh, acc[f]);
            }
        }
    }
    __syncthreads();
#pragma unroll
    for (int f = 0; f < 4; f++)
        wmma::store_matrix_sync(Cf + rt * 16 * 132 + cg * 64 + f * 16, acc[f], 132, wmma::mem_row_major);
    __syncthreads();
    for (int i = tid; i < 64 * 32; i += 256) {
        int row = i >> 5, c4 = i & 31;
        float4 v = *(float4*)(Cf + row * 132 + c4 * 4);
        float4 bb = ((const float4*)B1)[c4];
        v.x = fmaxf(v.x + bb.x, 0.f);
        v.y = fmaxf(v.y + bb.y, 0.f);
        v.z = fmaxf(v.z + bb.z, 0.f);
        v.w = fmaxf(v.w + bb.w, 0.f);
        split_store4(v, Hhi + row * 136 + c4 * 4, Hlo + row * 136 + c4 * 4);
    }

#pragma unroll
    for (int f = 0; f < 4; f++) wmma::fill_fragment(acc[f], 0.f);
    for (int kc = 0; kc < 128; kc += 64) {
        __syncthreads();
        for (int i = tid; i < 1024; i += 256) {
            int rr = i >> 4, g = i & 15;
            cp_async16(whi_b + (uint32_t)(rr * 136 + g * 8) * 2, wbase + NW2_HI + (kc + rr) * 128 + g * 8);
            cp_async16(wlo_b + (uint32_t)(rr * 136 + g * 8) * 2, wbase + NW2_LO + (kc + rr) * 128 + g * 8);
        }
        cp_commit_wait();
        __syncthreads();
        for (int kk = 0; kk < 64; kk += 16) {
            AF ah, al;
            wmma::load_matrix_sync(ah, Hhi + rt * 16 * 136 + kc + kk, 136);
            wmma::load_matrix_sync(al, Hlo + rt * 16 * 136 + kc + kk, 136);
#pragma unroll
            for (int f = 0; f < 4; f++) {
                BF bh, bl;
                wmma::load_matrix_sync(bh, Whi + kk * 136 + cg * 64 + f * 16, 136);
                wmma::load_matrix_sync(bl, Wlo + kk * 136 + cg * 64 + f * 16, 136);
                wmma::mma_sync(acc[f], ah, bh, acc[f]);
                wmma::mma_sync(acc[f], ah, bl, acc[f]);
                wmma::mma_sync(acc[f], al, bh, acc[f]);
            }
        }
    }
    __syncthreads();
#pragma unroll
    for (int f = 0; f < 4; f++)
        wmma::store_matrix_sync(Cf + rt * 16 * 132 + cg * 64 + f * 16, acc[f], 132, wmma::mem_row_major);
    __syncthreads();

    for (int i = tid; i < 64 * 32; i += 256) {
        int row = i >> 5, c4 = i & 31;
        int n = nbase + row;
        float4 nv = make_float4(0.f, 0.f, 0.f, 0.f);
        if (n < NN) {
            float4 oldv = ((const float4*)(g_nl + (size_t)n * LL))[c4];
            float4 c2 = *(float4*)(Cf + row * 132 + c4 * 4);
            float4 bb = ((const float4*)B2)[c4];
            nv = make_float4(oldv.x + c2.x + bb.x, oldv.y + c2.y + bb.y,
                             oldv.z + c2.z + bb.z, oldv.w + c2.w + bb.w);
            ((float4*)(g_nl + (size_t)n * LL))[c4] = nv;
        }
        if (do_proj)
            split_store4(nv, Hhi + row * 136 + c4 * 4, Hlo + row * 136 + c4 * 4);
    }

    if (do_proj) {
        const __nv_bfloat16* wn = g_ws + (size_t)(step + 1) * STEP_W;
#pragma unroll 1
        for (int half = 0; half < 2; ++half) {
#pragma unroll
            for (int f = 0; f < 4; f++) wmma::fill_fragment(acc[f], 0.f);
            for (int kc = 0; kc < 128; kc += 64) {
                __syncthreads();
                for (int i = tid; i < 1024; i += 256) {
                    int rr = i >> 4, g = i & 15;
                    cp_async16(whi_b + (uint32_t)(rr * 136 + g * 8) * 2,
                               wn + PRJ_HI + (size_t)(kc + rr) * 256 + half * 128 + g * 8);
                    cp_async16(wlo_b + (uint32_t)(rr * 136 + g * 8) * 2,
                               wn + PRJ_LO + (size_t)(kc + rr) * 256 + half * 128 + g * 8);
                }
                cp_commit_wait();
                __syncthreads();
                for (int kk = 0; kk < 64; kk += 16) {
                    AF ah, al;
                    wmma::load_matrix_sync(ah, Hhi + rt * 16 * 136 + kc + kk, 136);
                    wmma::load_matrix_sync(al, Hlo + rt * 16 * 136 + kc + kk, 136);
#pragma unroll
                    for (int f = 0; f < 4; f++) {
                        BF bh, bl;
                        wmma::load_matrix_sync(bh, Whi + kk * 136 + cg * 64 + f * 16, 136);
                        wmma::load_matrix_sync(bl, Wlo + kk * 136 + cg * 64 + f * 16, 136);
                        wmma::mma_sync(acc[f], ah, bh, acc[f]);
                        wmma::mma_sync(acc[f], ah, bl, acc[f]);
                        wmma::mma_sync(acc[f], al, bh, acc[f]);
                    }
                }
            }
            if (full) {
#pragma unroll
                for (int f = 0; f < 4; f++)
                    wmma::store_matrix_sync(g_z + (size_t)(nbase + rt * 16) * 256 + half * 128 + cg * 64 + f * 16,
                                            acc[f], 256, wmma::mem_row_major);
            } else {
                __syncthreads();
#pragma unroll
                for (int f = 0; f < 4; f++)
                    wmma::store_matrix_sync(Cf + rt * 16 * 132 + cg * 64 + f * 16, acc[f], 132, wmma::mem_row_major);
                __syncthreads();
                for (int i = tid; i < 64 * 32; i += 256) {
                    int row = i >> 5, c4 = i & 31;
                    int n = nbase + row;
                    if (n < NN)
                        ((float4*)(g_z + (size_t)n * 256 + half * 128))[c4] =
                            *(float4*)(Cf + row * 132 + c4 * 4);
                }
            }
        }
    }
}

// ---------------------------------------------------------------- decoder (SIMT fp32; exact)
__global__ void __launch_bounds__(128) k_decoder(
    const float* __restrict__ W1, const float* __restrict__ B1,
    const float* __restrict__ W2, const float* __restrict__ B2,
    float* __restrict__ out)
{
    __shared__ float Xs[32][128];
    __shared__ float H[32][128];
    const int tid = threadIdx.x;
    const int nbase = blockIdx.x * 32;

    for (int i = tid; i < 32 * 32; i += 128) {
        int n = i >> 5, c4 = i & 31;
        int gn = nbase + n;
        float4 v = make_float4(0.f, 0.f, 0.f, 0.f);
        if (gn < NN) v = ((const float4*)(g_nl + (size_t)gn * LL))[c4];
        ((float4*)Xs[n])[c4] = v;
    }
    __syncthreads();

    const int j = tid;
#pragma unroll 1
    for (int n = 0; n < 32; n++) {
        float acc = B1[j];
#pragma unroll 8
        for (int k = 0; k < 128; k++) acc += Xs[n][k] * W1[k * 128 + j];
        H[n][j] = fmaxf(acc, 0.f);
    }
    __syncthreads();

    if (tid < 96) {
        int n = tid / 3, d = tid % 3;
        int gn = nbase + n;
        float acc = B2[d];
#pragma unroll 8
        for (int k = 0; k < 128; k++) acc += H[n][k] * W2[k * 3 + d];
        if (gn < NN) out[gn * 3 + d] = acc;
    }
}

// ---------------------------------------------------------------- launch
extern "C" void kernel_launch(void* const* d_in, const int* in_sizes, int n_in,
                              void* d_out, int out_size)
{
    const float* pos   = (const float*)d_in[0];
    const float* vel   = (const float*)d_in[1];
    const int*   rid   = (const int*)d_in[2];
    const int*   snd   = (const int*)d_in[3];
    const int*   rcv   = (const int*)d_in[4];
    const float* remb  = (const float*)d_in[5];
    const float* ne_w1 = (const float*)d_in[6];
    const float* ne_b1 = (const float*)d_in[7];
    const float* ne_w2 = (const float*)d_in[8];
    const float* ne_b2 = (const float*)d_in[9];
    const float* ee_w1 = (const float*)d_in[10];
    const float* ee_b1 = (const float*)d_in[11];
    const float* ee_w2 = (const float*)d_in[12];
    const float* ee_b2 = (const float*)d_in[13];
    const float* pe_w1 = (const float*)d_in[14];
    const float* pe_b1 = (const float*)d_in[15];
    const float* pe_w2 = (const float*)d_in[16];
    const float* pe_b2 = (const float*)d_in[17];
    const float* pn_w1 = (const float*)d_in[18];
    const float* pn_b1 = (const float*)d_in[19];
    const float* pn_w2 = (const float*)d_in[20];
    const float* pn_b2 = (const float*)d_in[21];
    const float* de_w1 = (const float*)d_in[22];
    const float* de_b1 = (const float*)d_in[23];
    const float* de_w2 = (const float*)d_in[24];
    const float* de_b2 = (const float*)d_in[25];

    cudaFuncSetAttribute(k_edge_step, cudaFuncAttributeMaxDynamicSharedMemorySize, ES_SMEM);
    cudaFuncSetAttribute(k_node_step, cudaFuncAttributeMaxDynamicSharedMemorySize, NS_SMEM);
    cudaFuncSetAttribute(k_enc_all, cudaFuncAttributeMaxDynamicSharedMemorySize, ENC_SMEM);

    k_setup<<<4676, 256>>>(pe_w1, pe_w2, pn_w1, pn_w2);
    k_degcenter<<<3229, 256>>>(rcv, pos);
    k_enc_all<<<NB_ENC + EB_ENC, 256, ENC_SMEM>>>(
        pos, vel, rid, remb, snd, rcv,
        ne_w1, ne_b1, ne_w2, ne_b2, ee_w1, ee_b1, ee_w2, ee_b2);

    // launch 3 = first k_edge_step (the profiled slot)
    for (int st = 0; st < NSTEPS; st++) {
        k_edge_step<<<EE / 64, 256, ES_SMEM>>>(
            snd, rcv, st, pe_b1 + (size_t)st * 128, pe_b2 + (size_t)st * 128);
        k_node_step<<<(NN + 63) / 64, 256, NS_SMEM>>>(
            st, pn_b1 + (size_t)st * 128, pn_b2 + (size_t)st * 128, (st < NSTEPS - 1) ? 1 : 0);
    }

    k_decoder<<<(NN + 31) / 32, 128>>>(de_w1, de_b1, de_w2, de_b2, (float*)d_out);
}

// round 11
// speedup vs baseline: 1.2609x; 1.2609x over previous
#include <cuda_runtime.h>
#include <cuda_bf16.h>
#include <mma.h>
#include <cstdint>

using namespace nvcuda;

#define NN 50000
#define EE 800000
#define LL 128
#define NSTEPS 10
#define NB_ENC 782          // ceil(NN/64)
#define EB_ENC 12500        // EE/64

// ---- scratch (device globals; no allocations allowed) ----
__device__ float g_nl[(size_t)NN * LL];
// el stored as bf16 hi/lo planes, tile-major: [tile(64 edges)][hi 64x128][lo 64x128]
__device__ __nv_bfloat16 g_el[(size_t)EE * 256];
__device__ float g_agg[(size_t)NN * LL];
__device__ float g_z[(size_t)NN * 256];
__device__ float g_deg[NN];
__device__ float g_center[3];

#define EW1A_HI 0
#define EW1A_LO 16384
#define EW2_HI  32768
#define EW2_LO  49152
#define PRJ_HI  65536
#define PRJ_LO  98304
#define NW1_HI  131072
#define NW1_LO  163840
#define NW2_HI  196608
#define NW2_LO  212992
#define STEP_W  229376
__device__ __nv_bfloat16 g_ws[(size_t)NSTEPS * STEP_W];
// encoder W2 planes: hi [0,16384), lo [16384,32768)
__device__ __nv_bfloat16 g_we2[32768];

typedef wmma::fragment<wmma::matrix_a, 16, 16, 16, __nv_bfloat16, wmma::row_major> AF;
typedef wmma::fragment<wmma::matrix_b, 16, 16, 16, __nv_bfloat16, wmma::row_major> BF;
typedef wmma::fragment<wmma::accumulator, 16, 16, 16, float> CF;

__device__ __forceinline__ uint32_t smem_u32(const void* p) {
    uint32_t a;
    asm("{ .reg .u64 t; cvta.to.shared.u64 t, %1; cvt.u32.u64 %0, t; }" : "=r"(a) : "l"(p));
    return a;
}
__device__ __forceinline__ void cp_async16(uint32_t dst, const void* src) {
    asm volatile("cp.async.ca.shared.global [%0], [%1], 16;" :: "r"(dst), "l"(src) : "memory");
}
__device__ __forceinline__ void cp_commit() {
    asm volatile("cp.async.commit_group;" ::: "memory");
}
__device__ __forceinline__ void cp_wait0() {
    asm volatile("cp.async.wait_group 0;" ::: "memory");
}
__device__ __forceinline__ void cp_commit_wait() {
    cp_commit();
    cp_wait0();
}

__device__ __forceinline__ void split_store4(float4 v, __nv_bfloat16* hip, __nv_bfloat16* lop) {
    __nv_bfloat162 h0 = __floats2bfloat162_rn(v.x, v.y);
    __nv_bfloat162 h1 = __floats2bfloat162_rn(v.z, v.w);
    float2 f0 = __bfloat1622float2(h0);
    float2 f1 = __bfloat1622float2(h1);
    __nv_bfloat162 l0 = __floats2bfloat162_rn(v.x - f0.x, v.y - f0.y);
    __nv_bfloat162 l1 = __floats2bfloat162_rn(v.z - f1.x, v.w - f1.y);
    *(__nv_bfloat162*)(hip)     = h0;
    *(__nv_bfloat162*)(hip + 2) = h1;
    *(__nv_bfloat162*)(lop)     = l0;
    *(__nv_bfloat162*)(lop + 2) = l1;
}

__device__ __forceinline__ float4 join4(const __nv_bfloat16* hip, const __nv_bfloat16* lop) {
    float2 a = __bfloat1622float2(*(const __nv_bfloat162*)hip);
    float2 b = __bfloat1622float2(*(const __nv_bfloat162*)(hip + 2));
    float2 c = __bfloat1622float2(*(const __nv_bfloat162*)lop);
    float2 d = __bfloat1622float2(*(const __nv_bfloat162*)(lop + 2));
    return make_float4(a.x + c.x, a.y + c.y, b.x + d.x, b.y + d.y);
}

__device__ __forceinline__ void red_add_v4(float* dst, float4 v) {
    asm volatile("red.global.add.v4.f32 [%0], {%1,%2,%3,%4};"
                 :: "l"(dst), "f"(v.x), "f"(v.y), "f"(v.z), "f"(v.w) : "memory");
}

// ---------------------------------------------------------------- launch 0: weight prep + init
__global__ void __launch_bounds__(256) k_setup(
    const float* __restrict__ pe_w1, const float* __restrict__ pe_w2,
    const float* __restrict__ pn_w1, const float* __restrict__ pn_w2,
    const float* __restrict__ ee_w2)
{
    if (blockIdx.x < 4480) {
        int idx = blockIdx.x * 256 + threadIdx.x;
        int s = idx / 114688;
        int e = idx % 114688;
        float v;
        size_t dhi, dlo;
        if (e < 16384) {
            v = pe_w1[(size_t)s * 384 * 128 + e];
            dhi = EW1A_HI + e; dlo = EW1A_LO + e;
        } else if (e < 32768) {
            int e2 = e - 16384;
            v = pe_w2[(size_t)s * 128 * 128 + e2];
            dhi = EW2_HI + e2; dlo = EW2_LO + e2;
        } else if (e < 65536) {
            int e2 = e - 32768;
            int k = e2 >> 8, n = e2 & 255;
            int srcrow = 128 + (n >> 7) * 128 + k;
            v = pe_w1[(size_t)s * 384 * 128 + (size_t)srcrow * 128 + (n & 127)];
            dhi = PRJ_HI + e2; dlo = PRJ_LO + e2;
        } else if (e < 98304) {
            int e2 = e - 65536;
            v = pn_w1[(size_t)s * 256 * 128 + e2];
            dhi = NW1_HI + e2; dlo = NW1_LO + e2;
        } else {
            int e2 = e - 98304;
            v = pn_w2[(size_t)s * 128 * 128 + e2];
            dhi = NW2_HI + e2; dlo = NW2_LO + e2;
        }
        __nv_bfloat16 h = __float2bfloat16(v);
        g_ws[(size_t)s * STEP_W + dhi] = h;
        g_ws[(size_t)s * STEP_W + dlo] = __float2bfloat16(v - __bfloat162float(h));
    } else if (blockIdx.x < 4544) {
        int i = (blockIdx.x - 4480) * 256 + threadIdx.x;   // < 16384
        float v = ee_w2[i];
        __nv_bfloat16 h = __float2bfloat16(v);
        g_we2[i] = h;
        g_we2[16384 + i] = __float2bfloat16(v - __bfloat162float(h));
    } else {
        int i = (blockIdx.x - 4544) * 256 + threadIdx.x;
        if (i < NN) g_deg[i] = 0.f;
        if (i < 3) g_center[i] = 0.f;
    }
}

// ---------------------------------------------------------------- launch 1: degree + center
__global__ void __launch_bounds__(256) k_degcenter(
    const int* __restrict__ rcv, const float* __restrict__ pos)
{
    if (blockIdx.x < 3125) {
        int i = blockIdx.x * 256 + threadIdx.x;
        if (i < EE) atomicAdd(&g_deg[rcv[i]], 1.f);
    } else {
        float sx = 0.f, sy = 0.f, sz = 0.f;
        for (int i = (blockIdx.x - 3125) * 256 + threadIdx.x; i < NN; i += 104 * 256) {
            sx += pos[i * 3 + 0];
            sy += pos[i * 3 + 1];
            sz += pos[i * 3 + 2];
        }
#pragma unroll
        for (int o = 16; o > 0; o >>= 1) {
            sx += __shfl_down_sync(0xffffffffu, sx, o);
            sy += __shfl_down_sync(0xffffffffu, sy, o);
            sz += __shfl_down_sync(0xffffffffu, sz, o);
        }
        if ((threadIdx.x & 31) == 0) {
            atomicAdd(&g_center[0], sx);
            atomicAdd(&g_center[1], sy);
            atomicAdd(&g_center[2], sz);
        }
    }
}

// ---------------------------------------------------------------- launch 2: node encoder + step-0 projection
#define NEP_SMEM 110592

__global__ void __launch_bounds__(256, 1) k_node_enc_proj(
    const float* __restrict__ pos, const float* __restrict__ vel,
    const int* __restrict__ rid, const float* __restrict__ remb,
    const float* __restrict__ nW1, const float* __restrict__ nB1,
    const float* __restrict__ nW2, const float* __restrict__ nB2)
{
    extern __shared__ char smc[];
    const int tid = threadIdx.x;
    float* F = (float*)(smc + 0);
    float* H = (float*)(smc + 8192);
    __nv_bfloat16* Ahi = (__nv_bfloat16*)(smc + 40960);
    __nv_bfloat16* Alo = (__nv_bfloat16*)(smc + 58368);
    __nv_bfloat16* Wch = (__nv_bfloat16*)(smc + 75776);
    __nv_bfloat16* Wcl = (__nv_bfloat16*)(smc + 93184);
    const int nbase = blockIdx.x * 64;
    const float inv = 1.f / (float)NN;
    const float cx = g_center[0] * inv, cy = g_center[1] * inv, cz = g_center[2] * inv;

    for (int i = tid; i < 64 * 23; i += 256) {
        int n = i / 23, k = i % 23;
        int gn = nbase + n;
        float v = 0.f;
        if (gn < NN) {
            if (k < 3) v = vel[gn * 3 + k];
            else if (k < 6) v = pos[gn * 3 + (k - 3)] - ((k == 3) ? cx : (k == 4) ? cy : cz);
            else if (k == 6) v = g_deg[gn];
            else v = remb[rid[gn] * 16 + (k - 7)];
        }
        F[n * 24 + k] = v;
    }
    __syncthreads();

    const int j = tid & 127;
    for (int n = tid >> 7; n < 64; n += 2) {
        float acc = nB1[j];
#pragma unroll
        for (int k = 0; k < 23; k++) acc += F[n * 24 + k] * nW1[k * 128 + j];
        H[n * 128 + j] = fmaxf(acc, 0.f);
    }
    __syncthreads();
    for (int n = tid >> 7; n < 64; n += 2) {
        int gn = nbase + n;
        float acc = nB2[j];
#pragma unroll 8
        for (int k = 0; k < 128; k++) acc += H[n * 128 + k] * nW2[k * 128 + j];
        float v = (gn < NN) ? acc : 0.f;
        if (gn < NN) g_nl[(size_t)gn * LL + j] = v;
        __nv_bfloat16 h = __float2bfloat16(v);
        Ahi[n * 136 + j] = h;
        Alo[n * 136 + j] = __float2bfloat16(v - __bfloat162float(h));
    }
    __syncthreads();

    // projection Z(0) = nl @ PRJ(0)
    const int w = tid >> 5, rt = w >> 1, cg = w & 1;
    const bool full = (nbase + 64 <= NN);
    const __nv_bfloat16* wn = g_ws;
    CF acc[4];
#pragma unroll 1
    for (int half = 0; half < 2; ++half) {
#pragma unroll
        for (int f = 0; f < 4; f++) wmma::fill_fragment(acc[f], 0.f);
        for (int kc = 0; kc < 128; kc += 64) {
            __syncthreads();
            for (int i = tid; i < 1024; i += 256) {
                int rr = i >> 4, g = i & 15;
                *(float4*)(Wch + rr * 136 + g * 8) =
                    ((const float4*)(wn + PRJ_HI + (size_t)(kc + rr) * 256 + half * 128))[g];
                *(float4*)(Wcl + rr * 136 + g * 8) =
                    ((const float4*)(wn + PRJ_LO + (size_t)(kc + rr) * 256 + half * 128))[g];
            }
            __syncthreads();
            for (int kk = 0; kk < 64; kk += 16) {
                AF ah, al;
                wmma::load_matrix_sync(ah, Ahi + rt * 16 * 136 + kc + kk, 136);
                wmma::load_matrix_sync(al, Alo + rt * 16 * 136 + kc + kk, 136);
#pragma unroll
                for (int f = 0; f < 4; f++) {
                    BF bh, bl;
                    wmma::load_matrix_sync(bh, Wch + kk * 136 + cg * 64 + f * 16, 136);
                    wmma::load_matrix_sync(bl, Wcl + kk * 136 + cg * 64 + f * 16, 136);
                    wmma::mma_sync(acc[f], ah, bh, acc[f]);
                    wmma::mma_sync(acc[f], ah, bl, acc[f]);
                    wmma::mma_sync(acc[f], al, bh, acc[f]);
                }
            }
        }
        if (full) {
#pragma unroll
            for (int f = 0; f < 4; f++)
                wmma::store_matrix_sync(g_z + (size_t)(nbase + rt * 16) * 256 + half * 128 + cg * 64 + f * 16,
                                        acc[f], 256, wmma::mem_row_major);
        } else {
            float* Cf = (float*)(smc + 75776);   // dead W region; restaged next half
            __syncthreads();
#pragma unroll
            for (int f = 0; f < 4; f++)
                wmma::store_matrix_sync(Cf + rt * 16 * 132 + cg * 64 + f * 16, acc[f], 132, wmma::mem_row_major);
            __syncthreads();
            for (int i = tid; i < 64 * 32; i += 256) {
                int row = i >> 5, c4 = i & 31;
                int n = nbase + row;
                if (n < NN)
                    ((float4*)(g_z + (size_t)n * 256 + half * 128))[c4] =
                        *(float4*)(Cf + row * 132 + c4 * 4);
            }
        }
    }
}

// ---------------------------------------------------------------- launch 3: edge encoder (3 blocks/SM)
#define EN_F   0        // 64 x 12 fp32
#define EN_HHI 4096     // 64 x 136 bf16
#define EN_HLO 21504
#define EN_W   38912    // 64 x 136 bf16 (K-chunk)
#define EN_WLO 56320
#define EN_SMEM 73728

__global__ void __launch_bounds__(256, 3) k_edge_enc2(
    const float* __restrict__ pos, const float* __restrict__ vel,
    const int* __restrict__ rid,
    const int* __restrict__ snd, const int* __restrict__ rcv,
    const float* __restrict__ eW1, const float* __restrict__ eB1,
    const float* __restrict__ eB2)
{
    extern __shared__ char smc[];
    float*         F   = (float*)(smc + EN_F);
    __nv_bfloat16* Hhi = (__nv_bfloat16*)(smc + EN_HHI);
    __nv_bfloat16* Hlo = (__nv_bfloat16*)(smc + EN_HLO);
    __nv_bfloat16* Whi = (__nv_bfloat16*)(smc + EN_W);
    __nv_bfloat16* Wlo = (__nv_bfloat16*)(smc + EN_WLO);
    float*         Cf  = (float*)(smc + EN_W);    // aliases W
    const int tid = threadIdx.x;
    const int w = tid >> 5, rt = w & 1, cg = w >> 1;   // 2 x 4 tiling
    const int tile = blockIdx.x;
    const int ebase = tile * 64;
    const uint32_t whi_b = smem_u32(Whi), wlo_b = smem_u32(Wlo);

    // stage W2 chunk 0 (K rows 0..63) while building F
    for (int i = tid; i < 1024; i += 256) {
        int r = i >> 4, g = i & 15;
        cp_async16(whi_b + (uint32_t)(r * 272 + g * 16), g_we2 + r * 128 + g * 8);
        cp_async16(wlo_b + (uint32_t)(r * 272 + g * 16), g_we2 + 16384 + r * 128 + g * 8);
    }
    cp_commit();
    if (tid < 64) {
        int e = ebase + tid;
        int s = snd[e], r = rcv[e];
        float rp0 = pos[s * 3 + 0] - pos[r * 3 + 0];
        float rp1 = pos[s * 3 + 1] - pos[r * 3 + 1];
        float rp2 = pos[s * 3 + 2] - pos[r * 3 + 2];
        float rv0 = vel[s * 3 + 0] - vel[r * 3 + 0];
        float rv1 = vel[s * 3 + 1] - vel[r * 3 + 1];
        float rv2 = vel[s * 3 + 2] - vel[r * 3 + 2];
        float sq = rp0 * rp0 + rp1 * rp1 + rp2 * rp2;
        float dist = sqrtf(sq);
        float same = (rid[s] == rid[r]) ? 1.f : 0.f;
        float* f = F + tid * 12;
        f[0] = rp0; f[1] = rp1; f[2] = rp2;
        f[3] = rv0; f[4] = rv1; f[5] = rv2;
        f[6] = dist; f[7] = sq; f[8] = same;
    }
    __syncthreads();

    // L1 SIMT: H = relu(F @ W1 + B1) -> planes directly
    {
        const int j = tid & 127;
        for (int n = tid >> 7; n < 64; n += 2) {
            float acc = eB1[j];
#pragma unroll
            for (int k = 0; k < 9; k++) acc += F[n * 12 + k] * eW1[k * 128 + j];
            acc = fmaxf(acc, 0.f);
            __nv_bfloat16 h = __float2bfloat16(acc);
            Hhi[n * 136 + j] = h;
            Hlo[n * 136 + j] = __float2bfloat16(acc - __bfloat162float(h));
        }
    }
    cp_wait0();
    __syncthreads();

    // GEMM: H[64x128] @ W2, K chunked by 64
    CF acc[2][2];
#pragma unroll
    for (int sr = 0; sr < 2; sr++)
#pragma unroll
        for (int sc = 0; sc < 2; sc++) wmma::fill_fragment(acc[sr][sc], 0.f);
#pragma unroll 1
    for (int kc = 0; kc < 128; kc += 64) {
        if (kc) {
            __syncthreads();
            for (int i = tid; i < 1024; i += 256) {
                int r = i >> 4, g = i & 15;
                cp_async16(whi_b + (uint32_t)(r * 272 + g * 16), g_we2 + (kc + r) * 128 + g * 8);
                cp_async16(wlo_b + (uint32_t)(r * 272 + g * 16), g_we2 + 16384 + (kc + r) * 128 + g * 8);
            }
            cp_commit_wait();
            __syncthreads();
        }
        for (int kk = 0; kk < 64; kk += 16) {
            AF ah[2], al[2];
#pragma unroll
            for (int sr = 0; sr < 2; sr++) {
                wmma::load_matrix_sync(ah[sr], Hhi + (rt * 32 + sr * 16) * 136 + kc + kk, 136);
                wmma::load_matrix_sync(al[sr], Hlo + (rt * 32 + sr * 16) * 136 + kc + kk, 136);
            }
#pragma unroll
            for (int sc = 0; sc < 2; sc++) {
                BF bh, bl;
                wmma::load_matrix_sync(bh, Whi + kk * 136 + cg * 32 + sc * 16, 136);
                wmma::load_matrix_sync(bl, Wlo + kk * 136 + cg * 32 + sc * 16, 136);
#pragma unroll
                for (int sr = 0; sr < 2; sr++) {
                    wmma::mma_sync(acc[sr][sc], ah[sr], bh, acc[sr][sc]);
                    wmma::mma_sync(acc[sr][sc], ah[sr], bl, acc[sr][sc]);
                    wmma::mma_sync(acc[sr][sc], al[sr], bh, acc[sr][sc]);
                }
            }
        }
    }
    __syncthreads();
#pragma unroll
    for (int sr = 0; sr < 2; sr++)
#pragma unroll
        for (int sc = 0; sc < 2; sc++)
            wmma::store_matrix_sync(Cf + (rt * 32 + sr * 16) * 132 + cg * 32 + sc * 16,
                                    acc[sr][sc], 132, wmma::mem_row_major);
    __syncthreads();

    // epilogue: el = C + b2 -> bf16 planes
    __nv_bfloat16* elbase = g_el + (size_t)tile * 16384;
    for (int i = tid; i < 2048; i += 256) {
        int row = i >> 5, c4 = i & 31;
        float4 c = *(float4*)(Cf + row * 132 + c4 * 4);
        float4 b = ((const float4*)eB2)[c4];
        float4 nv = make_float4(c.x + b.x, c.y + b.y, c.z + b.z, c.w + b.w);
        __nv_bfloat16* hp = elbase + row * 128 + c4 * 4;
        split_store4(nv, hp, hp + 8192);
    }
}

// ---------------------------------------------------------------- edge processor step (R9 exact)
#define ES_SSH 0
#define ES_RSH 256
#define ES_B1  512
#define ES_B2  1024
#define ES_AHI 1536
#define ES_ALO 18944
#define ES_W   36352
#define ES_WLO 53760
#define ES_SMEM 71168

__global__ void __launch_bounds__(256, 3) k_edge_step(
    const int* __restrict__ snd, const int* __restrict__ rcv, int step,
    const float* __restrict__ B1, const float* __restrict__ B2)
{
    extern __shared__ char smc[];
    int*   ssh = (int*)(smc + ES_SSH);
    int*   rsh = (int*)(smc + ES_RSH);
    float* B1s = (float*)(smc + ES_B1);
    float* B2s = (float*)(smc + ES_B2);
    __nv_bfloat16* Ahi = (__nv_bfloat16*)(smc + ES_AHI);
    __nv_bfloat16* Alo = (__nv_bfloat16*)(smc + ES_ALO);
    __nv_bfloat16* Whi = (__nv_bfloat16*)(smc + ES_W);
    __nv_bfloat16* Wlo = (__nv_bfloat16*)(smc + ES_WLO);
    float*         Cf  = (float*)(smc + ES_W);
    const int tid = threadIdx.x;
    const int w = tid >> 5, rt = w & 1, cg = w >> 1;
    const int ebase = blockIdx.x * 64;
    const __nv_bfloat16* wbase = g_ws + (size_t)step * STEP_W;
    __nv_bfloat16* elbase = g_el + (size_t)blockIdx.x * 16384;
    const uint32_t whi_b = smem_u32(Whi), wlo_b = smem_u32(Wlo);
    const uint32_t ahi_b = smem_u32(Ahi), alo_b = smem_u32(Alo);

    if (tid < 64) {
        ssh[tid] = snd[ebase + tid];
        rsh[tid] = rcv[ebase + tid];
    }
    if (tid < 128) {
        B1s[tid] = B1[tid];
        B2s[tid] = B2[tid];
    }
    for (int i = tid; i < 1024; i += 256) {
        int r = i >> 4, g = i & 15;
        cp_async16(ahi_b + (uint32_t)(r * 272 + g * 16), elbase + r * 128 + g * 8);
        cp_async16(alo_b + (uint32_t)(r * 272 + g * 16), elbase + 8192 + r * 128 + g * 8);
        cp_async16(whi_b + (uint32_t)(r * 272 + g * 16), wbase + EW1A_HI + r * 128 + g * 8);
        cp_async16(wlo_b + (uint32_t)(r * 272 + g * 16), wbase + EW1A_LO + r * 128 + g * 8);
    }
    cp_commit_wait();
    __syncthreads();

    CF acc[2][2];
#pragma unroll
    for (int sr = 0; sr < 2; sr++)
#pragma unroll
        for (int sc = 0; sc < 2; sc++) wmma::fill_fragment(acc[sr][sc], 0.f);

#pragma unroll 1
    for (int kc = 0; kc < 128; kc += 64) {
        if (kc) {
            __syncthreads();
            for (int i = tid; i < 1024; i += 256) {
                int r = i >> 4, g = i & 15;
                cp_async16(whi_b + (uint32_t)(r * 272 + g * 16), wbase + EW1A_HI + (kc + r) * 128 + g * 8);
                cp_async16(wlo_b + (uint32_t)(r * 272 + g * 16), wbase + EW1A_LO + (kc + r) * 128 + g * 8);
            }
            cp_commit_wait();
            __syncthreads();
        }
        for (int kk = 0; kk < 64; kk += 16) {
            AF ah[2], al[2];
#pragma unroll
            for (int sr = 0; sr < 2; sr++) {
                wmma::load_matrix_sync(ah[sr], Ahi + (rt * 32 + sr * 16) * 136 + kc + kk, 136);
                wmma::load_matrix_sync(al[sr], Alo + (rt * 32 + sr * 16) * 136 + kc + kk, 136);
            }
#pragma unroll
            for (int sc = 0; sc < 2; sc++) {
                BF bh, bl;
                wmma::load_matrix_sync(bh, Whi + kk * 136 + cg * 32 + sc * 16, 136);
                wmma::load_matrix_sync(bl, Wlo + kk * 136 + cg * 32 + sc * 16, 136);
#pragma unroll
                for (int sr = 0; sr < 2; sr++) {
                    wmma::mma_sync(acc[sr][sc], ah[sr], bh, acc[sr][sc]);
                    wmma::mma_sync(acc[sr][sc], ah[sr], bl, acc[sr][sc]);
                    wmma::mma_sync(acc[sr][sc], al[sr], bh, acc[sr][sc]);
                }
            }
        }
    }
    __syncthreads();
#pragma unroll
    for (int sr = 0; sr < 2; sr++)
#pragma unroll
        for (int sc = 0; sc < 2; sc++)
            wmma::store_matrix_sync(Cf + (rt * 32 + sr * 16) * 132 + cg * 32 + sc * 16,
                                    acc[sr][sc], 132, wmma::mem_row_major);
    __syncthreads();

    for (int i = tid; i < 2048; i += 256) {
        int row = i >> 5, c4 = i & 31;
        int s = ssh[row], r = rsh[row];
        float4 c = *(float4*)(Cf + row * 132 + c4 * 4);
        float4 zb = ((const float4*)(g_z + (size_t)s * 256))[c4];
        float4 zc = ((const float4*)(g_z + (size_t)r * 256 + 128))[c4];
        float4 b = ((const float4*)B1s)[c4];
        float4 v = make_float4(
            fmaxf(c.x + zb.x + zc.x + b.x, 0.f),
            fmaxf(c.y + zb.y + zc.y + b.y, 0.f),
            fmaxf(c.z + zb.z + zc.z + b.z, 0.f),
            fmaxf(c.w + zb.w + zc.w + b.w, 0.f));
        split_store4(v, Ahi + row * 136 + c4 * 4, Alo + row * 136 + c4 * 4);
    }
    __syncthreads();

#pragma unroll
    for (int sr = 0; sr < 2; sr++)
#pragma unroll
        for (int sc = 0; sc < 2; sc++) wmma::fill_fragment(acc[sr][sc], 0.f);
#pragma unroll 1
    for (int kc = 0; kc < 128; kc += 64) {
        for (int i = tid; i < 1024; i += 256) {
            int r = i >> 4, g = i & 15;
            cp_async16(whi_b + (uint32_t)(r * 272 + g * 16), wbase + EW2_HI + (kc + r) * 128 + g * 8);
            cp_async16(wlo_b + (uint32_t)(r * 272 + g * 16), wbase + EW2_LO + (kc + r) * 128 + g * 8);
        }
        cp_commit_wait();
        __syncthreads();
        for (int kk = 0; kk < 64; kk += 16) {
            AF ah[2], al[2];
#pragma unroll
            for (int sr = 0; sr < 2; sr++) {
                wmma::load_matrix_sync(ah[sr], Ahi + (rt * 32 + sr * 16) * 136 + kc + kk, 136);
                wmma::load_matrix_sync(al[sr], Alo + (rt * 32 + sr * 16) * 136 + kc + kk, 136);
            }
#pragma unroll
            for (int sc = 0; sc < 2; sc++) {
                BF bh, bl;
                wmma::load_matrix_sync(bh, Whi + kk * 136 + cg * 32 + sc * 16, 136);
                wmma::load_matrix_sync(bl, Wlo + kk * 136 + cg * 32 + sc * 16, 136);
#pragma unroll
                for (int sr = 0; sr < 2; sr++) {
                    wmma::mma_sync(acc[sr][sc], ah[sr], bh, acc[sr][sc]);
                    wmma::mma_sync(acc[sr][sc], ah[sr], bl, acc[sr][sc]);
                    wmma::mma_sync(acc[sr][sc], al[sr], bh, acc[sr][sc]);
                }
            }
        }
        __syncthreads();
    }
#pragma unroll
    for (int sr = 0; sr < 2; sr++)
#pragma unroll
        for (int sc = 0; sc < 2; sc++)
            wmma::store_matrix_sync(Cf + (rt * 32 + sr * 16) * 132 + cg * 32 + sc * 16,
                                    acc[sr][sc], 132, wmma::mem_row_major);
    __syncthreads();

    for (int i = tid; i < 2048; i += 256) {
        int row = i >> 5, c4 = i & 31;
        __nv_bfloat16* hp = elbase + row * 128 + c4 * 4;
        float4 oldv = join4(hp, hp + 8192);
        float4 c = *(float4*)(Cf + row * 132 + c4 * 4);
        float4 b = ((const float4*)B2s)[c4];
        float4 nv = make_float4(oldv.x + c.x + b.x, oldv.y + c.y + b.y,
                                oldv.z + c.z + b.z, oldv.w + c.w + b.w);
        split_store4(nv, hp, hp + 8192);
        red_add_v4(g_agg + (size_t)rsh[row] * LL + c4 * 4, nv);
    }
}

// ---------------------------------------------------------------- node step (+fused projection) (R9 exact)
#define NS_XHI 0
#define NS_XLO 33792
#define NS_CF  0
#define NS_HHI 33792
#define NS_HLO 51200
#define NS_W   68608
#define NS_WLO 86016
#define NS_SMEM 103424

__global__ void __launch_bounds__(256, 2) k_node_step(
    int step, const float* __restrict__ B1, const float* __restrict__ B2, int do_proj)
{
    extern __shared__ char smc[];
    __nv_bfloat16* Xhi = (__nv_bfloat16*)(smc + NS_XHI);
    __nv_bfloat16* Xlo = (__nv_bfloat16*)(smc + NS_XLO);
    __nv_bfloat16* Whi = (__nv_bfloat16*)(smc + NS_W);
    __nv_bfloat16* Wlo = (__nv_bfloat16*)(smc + NS_WLO);
    float*         Cf  = (float*)(smc + NS_CF);
    __nv_bfloat16* Hhi = (__nv_bfloat16*)(smc + NS_HHI);
    __nv_bfloat16* Hlo = (__nv_bfloat16*)(smc + NS_HLO);
    const int tid = threadIdx.x;
    const int w = tid >> 5, rt = w >> 1, cg = w & 1;
    const int nbase = blockIdx.x * 64;
    const bool full = (nbase + 64 <= NN);
    const __nv_bfloat16* wbase = g_ws + (size_t)step * STEP_W;
    const uint32_t whi_b = smem_u32(Whi), wlo_b = smem_u32(Wlo);

    for (int i = tid; i < 64 * 64; i += 256) {
        int row = i >> 6, c4 = i & 63;
        int n = nbase + row;
        float4 v = make_float4(0.f, 0.f, 0.f, 0.f);
        if (n < NN) {
            if (c4 < 32) {
                v = ((const float4*)(g_nl + (size_t)n * LL))[c4];
            } else {
                float4* ap = (float4*)(g_agg + (size_t)n * LL) + (c4 - 32);
                v = *ap;
                *ap = make_float4(0.f, 0.f, 0.f, 0.f);
            }
        }
        split_store4(v, Xhi + row * 264 + c4 * 4, Xlo + row * 264 + c4 * 4);
    }

    CF acc[4];
#pragma unroll
    for (int f = 0; f < 4; f++) wmma::fill_fragment(acc[f], 0.f);

    for (int kc = 0; kc < 256; kc += 64) {
        __syncthreads();
        for (int i = tid; i < 1024; i += 256) {
            int rr = i >> 4, g = i & 15;
            cp_async16(whi_b + (uint32_t)(rr * 136 + g * 8) * 2, wbase + NW1_HI + (kc + rr) * 128 + g * 8);
            cp_async16(wlo_b + (uint32_t)(rr * 136 + g * 8) * 2, wbase + NW1_LO + (kc + rr) * 128 + g * 8);
        }
        cp_commit_wait();
        __syncthreads();
        for (int kk = 0; kk < 64; kk += 16) {
            AF ah, al;
            wmma::load_matrix_sync(ah, Xhi + rt * 16 * 264 + kc + kk, 264);
            wmma::load_matrix_sync(al, Xlo + rt * 16 * 264 + kc + kk, 264);
#pragma unroll
            for (int f = 0; f < 4; f++) {
                BF bh, bl;
                wmma::load_matrix_sync(bh, Whi + kk * 136 + cg * 64 + f * 16, 136);
                wmma::load_matrix_sync(bl, Wlo + kk * 136 + cg * 64 + f * 16, 136);
                wmma::mma_sync(acc[f], ah, bh, acc[f]);
                wmma::mma_sync(acc[f], ah, bl, acc[f]);
                wmma::mma_sync(acc[f], al, bh, acc[f]);
            }
        }
    }
    __syncthreads();
#pragma unroll
    for (int f = 0; f < 4; f++)
        wmma::store_matrix_sync(Cf + rt * 16 * 132 + cg * 64 + f * 16, acc[f], 132, wmma::mem_row_major);
    __syncthreads();
    for (int i = tid; i < 64 * 32; i += 256) {
        int row = i >> 5, c4 = i & 31;
        float4 v = *(float4*)(Cf + row * 132 + c4 * 4);
        float4 bb = ((const float4*)B1)[c4];
        v.x = fmaxf(v.x + bb.x, 0.f);
        v.y = fmaxf(v.y + bb.y, 0.f);
        v.z = fmaxf(v.z + bb.z, 0.f);
        v.w = fmaxf(v.w + bb.w, 0.f);
        split_store4(v, Hhi + row * 136 + c4 * 4, Hlo + row * 136 + c4 * 4);
    }

#pragma unroll
    for (int f = 0; f < 4; f++) wmma::fill_fragment(acc[f], 0.f);
    for (int kc = 0; kc < 128; kc += 64) {
        __syncthreads();
        for (int i = tid; i < 1024; i += 256) {
            int rr = i >> 4, g = i & 15;
            cp_async16(whi_b + (uint32_t)(rr * 136 + g * 8) * 2, wbase + NW2_HI + (kc + rr) * 128 + g * 8);
            cp_async16(wlo_b + (uint32_t)(rr * 136 + g * 8) * 2, wbase + NW2_LO + (kc + rr) * 128 + g * 8);
        }
        cp_commit_wait();
        __syncthreads();
        for (int kk = 0; kk < 64; kk += 16) {
            AF ah, al;
            wmma::load_matrix_sync(ah, Hhi + rt * 16 * 136 + kc + kk, 136);
            wmma::load_matrix_sync(al, Hlo + rt * 16 * 136 + kc + kk, 136);
#pragma unroll
            for (int f = 0; f < 4; f++) {
                BF bh, bl;
                wmma::load_matrix_sync(bh, Whi + kk * 136 + cg * 64 + f * 16, 136);
                wmma::load_matrix_sync(bl, Wlo + kk * 136 + cg * 64 + f * 16, 136);
                wmma::mma_sync(acc[f], ah, bh, acc[f]);
                wmma::mma_sync(acc[f], ah, bl, acc[f]);
                wmma::mma_sync(acc[f], al, bh, acc[f]);
            }
        }
    }
    __syncthreads();
#pragma unroll
    for (int f = 0; f < 4; f++)
        wmma::store_matrix_sync(Cf + rt * 16 * 132 + cg * 64 + f * 16, acc[f], 132, wmma::mem_row_major);
    __syncthreads();

    for (int i = tid; i < 64 * 32; i += 256) {
        int row = i >> 5, c4 = i & 31;
        int n = nbase + row;
        float4 nv = make_float4(0.f, 0.f, 0.f, 0.f);
        if (n < NN) {
            float4 oldv = ((const float4*)(g_nl + (size_t)n * LL))[c4];
            float4 c2 = *(float4*)(Cf + row * 132 + c4 * 4);
            float4 bb = ((const float4*)B2)[c4];
            nv = make_float4(oldv.x + c2.x + bb.x, oldv.y + c2.y + bb.y,
                             oldv.z + c2.z + bb.z, oldv.w + c2.w + bb.w);
            ((float4*)(g_nl + (size_t)n * LL))[c4] = nv;
        }
        if (do_proj)
            split_store4(nv, Hhi + row * 136 + c4 * 4, Hlo + row * 136 + c4 * 4);
    }

    if (do_proj) {
        const __nv_bfloat16* wn = g_ws + (size_t)(step + 1) * STEP_W;
#pragma unroll 1
        for (int half = 0; half < 2; ++half) {
#pragma unroll
            for (int f = 0; f < 4; f++) wmma::fill_fragment(acc[f], 0.f);
            for (int kc = 0; kc < 128; kc += 64) {
                __syncthreads();
                for (int i = tid; i < 1024; i += 256) {
                    int rr = i >> 4, g = i & 15;
                    cp_async16(whi_b + (uint32_t)(rr * 136 + g * 8) * 2,
                               wn + PRJ_HI + (size_t)(kc + rr) * 256 + half * 128 + g * 8);
                    cp_async16(wlo_b + (uint32_t)(rr * 136 + g * 8) * 2,
                               wn + PRJ_LO + (size_t)(kc + rr) * 256 + half * 128 + g * 8);
                }
                cp_commit_wait();
                __syncthreads();
                for (int kk = 0; kk < 64; kk += 16) {
                    AF ah, al;
                    wmma::load_matrix_sync(ah, Hhi + rt * 16 * 136 + kc + kk, 136);
                    wmma::load_matrix_sync(al, Hlo + rt * 16 * 136 + kc + kk, 136);
#pragma unroll
                    for (int f = 0; f < 4; f++) {
                        BF bh, bl;
                        wmma::load_matrix_sync(bh, Whi + kk * 136 + cg * 64 + f * 16, 136);
                        wmma::load_matrix_sync(bl, Wlo + kk * 136 + cg * 64 + f * 16, 136);
                        wmma::mma_sync(acc[f], ah, bh, acc[f]);
                        wmma::mma_sync(acc[f], ah, bl, acc[f]);
                        wmma::mma_sync(acc[f], al, bh, acc[f]);
                    }
                }
            }
            if (full) {
#pragma unroll
                for (int f = 0; f < 4; f++)
                    wmma::store_matrix_sync(g_z + (size_t)(nbase + rt * 16) * 256 + half * 128 + cg * 64 + f * 16,
                                            acc[f], 256, wmma::mem_row_major);
            } else {
                __syncthreads();
#pragma unroll
                for (int f = 0; f < 4; f++)
                    wmma::store_matrix_sync(Cf + rt * 16 * 132 + cg * 64 + f * 16, acc[f], 132, wmma::mem_row_major);
                __syncthreads();
                for (int i = tid; i < 64 * 32; i += 256) {
                    int row = i >> 5, c4 = i & 31;
                    int n = nbase + row;
                    if (n < NN)
                        ((float4*)(g_z + (size_t)n * 256 + half * 128))[c4] =
                            *(float4*)(Cf + row * 132 + c4 * 4);
                }
            }
        }
    }
}

// ---------------------------------------------------------------- decoder (SIMT fp32; exact)
__global__ void __launch_bounds__(128) k_decoder(
    const float* __restrict__ W1, const float* __restrict__ B1,
    const float* __restrict__ W2, const float* __restrict__ B2,
    float* __restrict__ out)
{
    __shared__ float Xs[32][128];
    __shared__ float H[32][128];
    const int tid = threadIdx.x;
    const int nbase = blockIdx.x * 32;

    for (int i = tid; i < 32 * 32; i += 128) {
        int n = i >> 5, c4 = i & 31;
        int gn = nbase + n;
        float4 v = make_float4(0.f, 0.f, 0.f, 0.f);
        if (gn < NN) v = ((const float4*)(g_nl + (size_t)gn * LL))[c4];
        ((float4*)Xs[n])[c4] = v;
    }
    __syncthreads();

    const int j = tid;
#pragma unroll 1
    for (int n = 0; n < 32; n++) {
        float acc = B1[j];
#pragma unroll 8
        for (int k = 0; k < 128; k++) acc += Xs[n][k] * W1[k * 128 + j];
        H[n][j] = fmaxf(acc, 0.f);
    }
    __syncthreads();

    if (tid < 96) {
        int n = tid / 3, d = tid % 3;
        int gn = nbase + n;
        float acc = B2[d];
#pragma unroll 8
        for (int k = 0; k < 128; k++) acc += H[n][k] * W2[k * 3 + d];
        if (gn < NN) out[gn * 3 + d] = acc;
    }
}

// ---------------------------------------------------------------- launch
extern "C" void kernel_launch(void* const* d_in, const int* in_sizes, int n_in,
                              void* d_out, int out_size)
{
    const float* pos   = (const float*)d_in[0];
    const float* vel   = (const float*)d_in[1];
    const int*   rid   = (const int*)d_in[2];
    const int*   snd   = (const int*)d_in[3];
    const int*   rcv   = (const int*)d_in[4];
    const float* remb  = (const float*)d_in[5];
    const float* ne_w1 = (const float*)d_in[6];
    const float* ne_b1 = (const float*)d_in[7];
    const float* ne_w2 = (const float*)d_in[8];
    const float* ne_b2 = (const float*)d_in[9];
    const float* ee_w1 = (const float*)d_in[10];
    const float* ee_b1 = (const float*)d_in[11];
    const float* ee_w2 = (const float*)d_in[12];
    const float* ee_b2 = (const float*)d_in[13];
    const float* pe_w1 = (const float*)d_in[14];
    const float* pe_b1 = (const float*)d_in[15];
    const float* pe_w2 = (const float*)d_in[16];
    const float* pe_b2 = (const float*)d_in[17];
    const float* pn_w1 = (const float*)d_in[18];
    const float* pn_b1 = (const float*)d_in[19];
    const float* pn_w2 = (const float*)d_in[20];
    const float* pn_b2 = (const float*)d_in[21];
    const float* de_w1 = (const float*)d_in[22];
    const float* de_b1 = (const float*)d_in[23];
    const float* de_w2 = (const float*)d_in[24];
    const float* de_b2 = (const float*)d_in[25];

    cudaFuncSetAttribute(k_edge_step, cudaFuncAttributeMaxDynamicSharedMemorySize, ES_SMEM);
    cudaFuncSetAttribute(k_node_step, cudaFuncAttributeMaxDynamicSharedMemorySize, NS_SMEM);
    cudaFuncSetAttribute(k_node_enc_proj, cudaFuncAttributeMaxDynamicSharedMemorySize, NEP_SMEM);
    cudaFuncSetAttribute(k_edge_enc2, cudaFuncAttributeMaxDynamicSharedMemorySize, EN_SMEM);

    k_setup<<<4740, 256>>>(pe_w1, pe_w2, pn_w1, pn_w2, ee_w2);
    k_degcenter<<<3229, 256>>>(rcv, pos);
    k_node_enc_proj<<<NB_ENC, 256, NEP_SMEM>>>(pos, vel, rid, remb, ne_w1, ne_b1, ne_w2, ne_b2);
    k_edge_enc2<<<EB_ENC, 256, EN_SMEM>>>(pos, vel, rid, snd, rcv, ee_w1, ee_b1, ee_b2);

    for (int st = 0; st < NSTEPS; st++) {
        k_edge_step<<<EE / 64, 256, ES_SMEM>>>(
            snd, rcv, st, pe_b1 + (size_t)st * 128, pe_b2 + (size_t)st * 128);
        k_node_step<<<(NN + 63) / 64, 256, NS_SMEM>>>(
            st, pn_b1 + (size_t)st * 128, pn_b2 + (size_t)st * 128, (st < NSTEPS - 1) ? 1 : 0);
    }

    k_decoder<<<(NN + 31) / 32, 128>>>(de_w1, de_b1, de_w2, de_b2, (float*)d_out);
}

// round 12
// speedup vs baseline: 1.3245x; 1.0504x over previous
#include <cuda_runtime.h>
#include <cuda_bf16.h>
#include <mma.h>
#include <cstdint>

using namespace nvcuda;

#define NN 50000
#define EE 800000
#define LL 128
#define NSTEPS 10
#define NB_ENC 782          // ceil(NN/64)
#define EB_ENC 12500        // EE/64

// ---- scratch (device globals; no allocations allowed) ----
__device__ float g_nl[(size_t)NN * LL];
// el stored as bf16 hi/lo planes, tile-major: [tile(64 edges)][hi 64x128][lo 64x128]
__device__ __nv_bfloat16 g_el[(size_t)EE * 256];
__device__ float g_agg[(size_t)NN * LL];
__device__ float g_z[(size_t)NN * 256];
__device__ float g_deg[NN];
__device__ float g_center[3];

#define EW1A_HI 0
#define EW1A_LO 16384
#define EW2_HI  32768
#define EW2_LO  49152
#define PRJ_HI  65536
#define PRJ_LO  98304
#define NW1_HI  131072
#define NW1_LO  163840
#define NW2_HI  196608
#define NW2_LO  212992
#define STEP_W  229376
__device__ __nv_bfloat16 g_ws[(size_t)NSTEPS * STEP_W];
// encoder W2 planes: hi [0,16384), lo [16384,32768)
__device__ __nv_bfloat16 g_we2[32768];

typedef wmma::fragment<wmma::matrix_a, 16, 16, 16, __nv_bfloat16, wmma::row_major> AF;
typedef wmma::fragment<wmma::matrix_b, 16, 16, 16, __nv_bfloat16, wmma::row_major> BF;
typedef wmma::fragment<wmma::accumulator, 16, 16, 16, float> CF;

__device__ __forceinline__ uint32_t smem_u32(const void* p) {
    uint32_t a;
    asm("{ .reg .u64 t; cvta.to.shared.u64 t, %1; cvt.u32.u64 %0, t; }" : "=r"(a) : "l"(p));
    return a;
}
__device__ __forceinline__ void cp_async16(uint32_t dst, const void* src) {
    asm volatile("cp.async.ca.shared.global [%0], [%1], 16;" :: "r"(dst), "l"(src) : "memory");
}
__device__ __forceinline__ void cp_commit() {
    asm volatile("cp.async.commit_group;" ::: "memory");
}
__device__ __forceinline__ void cp_wait0() {
    asm volatile("cp.async.wait_group 0;" ::: "memory");
}
__device__ __forceinline__ void cp_commit_wait() {
    cp_commit();
    cp_wait0();
}

__device__ __forceinline__ void split_store4(float4 v, __nv_bfloat16* hip, __nv_bfloat16* lop) {
    __nv_bfloat162 h0 = __floats2bfloat162_rn(v.x, v.y);
    __nv_bfloat162 h1 = __floats2bfloat162_rn(v.z, v.w);
    float2 f0 = __bfloat1622float2(h0);
    float2 f1 = __bfloat1622float2(h1);
    __nv_bfloat162 l0 = __floats2bfloat162_rn(v.x - f0.x, v.y - f0.y);
    __nv_bfloat162 l1 = __floats2bfloat162_rn(v.z - f1.x, v.w - f1.y);
    *(__nv_bfloat162*)(hip)     = h0;
    *(__nv_bfloat162*)(hip + 2) = h1;
    *(__nv_bfloat162*)(lop)     = l0;
    *(__nv_bfloat162*)(lop + 2) = l1;
}

__device__ __forceinline__ float4 join4(const __nv_bfloat16* hip, const __nv_bfloat16* lop) {
    float2 a = __bfloat1622float2(*(const __nv_bfloat162*)hip);
    float2 b = __bfloat1622float2(*(const __nv_bfloat162*)(hip + 2));
    float2 c = __bfloat1622float2(*(const __nv_bfloat162*)lop);
    float2 d = __bfloat1622float2(*(const __nv_bfloat162*)(lop + 2));
    return make_float4(a.x + c.x, a.y + c.y, b.x + d.x, b.y + d.y);
}

__device__ __forceinline__ void red_add_v4(float* dst, float4 v) {
    asm volatile("red.global.add.v4.f32 [%0], {%1,%2,%3,%4};"
                 :: "l"(dst), "f"(v.x), "f"(v.y), "f"(v.z), "f"(v.w) : "memory");
}

// ---------------------------------------------------------------- launch 0: weight prep + init
__global__ void __launch_bounds__(256) k_setup(
    const float* __restrict__ pe_w1, const float* __restrict__ pe_w2,
    const float* __restrict__ pn_w1, const float* __restrict__ pn_w2,
    const float* __restrict__ ee_w2)
{
    if (blockIdx.x < 4480) {
        int idx = blockIdx.x * 256 + threadIdx.x;
        int s = idx / 114688;
        int e = idx % 114688;
        float v;
        size_t dhi, dlo;
        if (e < 16384) {
            v = pe_w1[(size_t)s * 384 * 128 + e];
            dhi = EW1A_HI + e; dlo = EW1A_LO + e;
        } else if (e < 32768) {
            int e2 = e - 16384;
            v = pe_w2[(size_t)s * 128 * 128 + e2];
            dhi = EW2_HI + e2; dlo = EW2_LO + e2;
        } else if (e < 65536) {
            int e2 = e - 32768;
            int k = e2 >> 8, n = e2 & 255;
            int srcrow = 128 + (n >> 7) * 128 + k;
            v = pe_w1[(size_t)s * 384 * 128 + (size_t)srcrow * 128 + (n & 127)];
            dhi = PRJ_HI + e2; dlo = PRJ_LO + e2;
        } else if (e < 98304) {
            int e2 = e - 65536;
            v = pn_w1[(size_t)s * 256 * 128 + e2];
            dhi = NW1_HI + e2; dlo = NW1_LO + e2;
        } else {
            int e2 = e - 98304;
            v = pn_w2[(size_t)s * 128 * 128 + e2];
            dhi = NW2_HI + e2; dlo = NW2_LO + e2;
        }
        __nv_bfloat16 h = __float2bfloat16(v);
        g_ws[(size_t)s * STEP_W + dhi] = h;
        g_ws[(size_t)s * STEP_W + dlo] = __float2bfloat16(v - __bfloat162float(h));
    } else if (blockIdx.x < 4544) {
        int i = (blockIdx.x - 4480) * 256 + threadIdx.x;   // < 16384
        float v = ee_w2[i];
        __nv_bfloat16 h = __float2bfloat16(v);
        g_we2[i] = h;
        g_we2[16384 + i] = __float2bfloat16(v - __bfloat162float(h));
    } else {
        int i = (blockIdx.x - 4544) * 256 + threadIdx.x;
        if (i < NN) g_deg[i] = 0.f;
        if (i < 3) g_center[i] = 0.f;
    }
}

// ---------------------------------------------------------------- launch 1: degree + center
__global__ void __launch_bounds__(256) k_degcenter(
    const int* __restrict__ rcv, const float* __restrict__ pos)
{
    if (blockIdx.x < 3125) {
        int i = blockIdx.x * 256 + threadIdx.x;
        if (i < EE) atomicAdd(&g_deg[rcv[i]], 1.f);
    } else {
        float sx = 0.f, sy = 0.f, sz = 0.f;
        for (int i = (blockIdx.x - 3125) * 256 + threadIdx.x; i < NN; i += 104 * 256) {
            sx += pos[i * 3 + 0];
            sy += pos[i * 3 + 1];
            sz += pos[i * 3 + 2];
        }
#pragma unroll
        for (int o = 16; o > 0; o >>= 1) {
            sx += __shfl_down_sync(0xffffffffu, sx, o);
            sy += __shfl_down_sync(0xffffffffu, sy, o);
            sz += __shfl_down_sync(0xffffffffu, sz, o);
        }
        if ((threadIdx.x & 31) == 0) {
            atomicAdd(&g_center[0], sx);
            atomicAdd(&g_center[1], sy);
            atomicAdd(&g_center[2], sz);
        }
    }
}

// ---------------------------------------------------------------- launch 2: node encoder + step-0 projection
#define NEP_SMEM 110592

__global__ void __launch_bounds__(256, 1) k_node_enc_proj(
    const float* __restrict__ pos, const float* __restrict__ vel,
    const int* __restrict__ rid, const float* __restrict__ remb,
    const float* __restrict__ nW1, const float* __restrict__ nB1,
    const float* __restrict__ nW2, const float* __restrict__ nB2)
{
    extern __shared__ char smc[];
    const int tid = threadIdx.x;
    float* F = (float*)(smc + 0);
    float* H = (float*)(smc + 8192);
    __nv_bfloat16* Ahi = (__nv_bfloat16*)(smc + 40960);
    __nv_bfloat16* Alo = (__nv_bfloat16*)(smc + 58368);
    __nv_bfloat16* Wch = (__nv_bfloat16*)(smc + 75776);
    __nv_bfloat16* Wcl = (__nv_bfloat16*)(smc + 93184);
    const int nbase = blockIdx.x * 64;
    const float inv = 1.f / (float)NN;
    const float cx = g_center[0] * inv, cy = g_center[1] * inv, cz = g_center[2] * inv;

    for (int i = tid; i < 64 * 23; i += 256) {
        int n = i / 23, k = i % 23;
        int gn = nbase + n;
        float v = 0.f;
        if (gn < NN) {
            if (k < 3) v = vel[gn * 3 + k];
            else if (k < 6) v = pos[gn * 3 + (k - 3)] - ((k == 3) ? cx : (k == 4) ? cy : cz);
            else if (k == 6) v = g_deg[gn];
            else v = remb[rid[gn] * 16 + (k - 7)];
        }
        F[n * 24 + k] = v;
    }
    __syncthreads();

    const int j = tid & 127;
    for (int n = tid >> 7; n < 64; n += 2) {
        float acc = nB1[j];
#pragma unroll
        for (int k = 0; k < 23; k++) acc += F[n * 24 + k] * nW1[k * 128 + j];
        H[n * 128 + j] = fmaxf(acc, 0.f);
    }
    __syncthreads();
    for (int n = tid >> 7; n < 64; n += 2) {
        int gn = nbase + n;
        float acc = nB2[j];
#pragma unroll 8
        for (int k = 0; k < 128; k++) acc += H[n * 128 + k] * nW2[k * 128 + j];
        float v = (gn < NN) ? acc : 0.f;
        if (gn < NN) g_nl[(size_t)gn * LL + j] = v;
        __nv_bfloat16 h = __float2bfloat16(v);
        Ahi[n * 136 + j] = h;
        Alo[n * 136 + j] = __float2bfloat16(v - __bfloat162float(h));
    }
    __syncthreads();

    // projection Z(0) = nl @ PRJ(0)
    const int w = tid >> 5, rt = w >> 1, cg = w & 1;
    const bool full = (nbase + 64 <= NN);
    const __nv_bfloat16* wn = g_ws;
    CF acc[4];
#pragma unroll 1
    for (int half = 0; half < 2; ++half) {
#pragma unroll
        for (int f = 0; f < 4; f++) wmma::fill_fragment(acc[f], 0.f);
        for (int kc = 0; kc < 128; kc += 64) {
            __syncthreads();
            for (int i = tid; i < 1024; i += 256) {
                int rr = i >> 4, g = i & 15;
                *(float4*)(Wch + rr * 136 + g * 8) =
                    ((const float4*)(wn + PRJ_HI + (size_t)(kc + rr) * 256 + half * 128))[g];
                *(float4*)(Wcl + rr * 136 + g * 8) =
                    ((const float4*)(wn + PRJ_LO + (size_t)(kc + rr) * 256 + half * 128))[g];
            }
            __syncthreads();
            for (int kk = 0; kk < 64; kk += 16) {
                AF ah, al;
                wmma::load_matrix_sync(ah, Ahi + rt * 16 * 136 + kc + kk, 136);
                wmma::load_matrix_sync(al, Alo + rt * 16 * 136 + kc + kk, 136);
#pragma unroll
                for (int f = 0; f < 4; f++) {
                    BF bh, bl;
                    wmma::load_matrix_sync(bh, Wch + kk * 136 + cg * 64 + f * 16, 136);
                    wmma::load_matrix_sync(bl, Wcl + kk * 136 + cg * 64 + f * 16, 136);
                    wmma::mma_sync(acc[f], ah, bh, acc[f]);
                    wmma::mma_sync(acc[f], ah, bl, acc[f]);
                    wmma::mma_sync(acc[f], al, bh, acc[f]);
                }
            }
        }
        if (full) {
#pragma unroll
            for (int f = 0; f < 4; f++)
                wmma::store_matrix_sync(g_z + (size_t)(nbase + rt * 16) * 256 + half * 128 + cg * 64 + f * 16,
                                        acc[f], 256, wmma::mem_row_major);
        } else {
            float* Cf = (float*)(smc + 75776);   // dead W region; restaged next half
            __syncthreads();
#pragma unroll
            for (int f = 0; f < 4; f++)
                wmma::store_matrix_sync(Cf + rt * 16 * 132 + cg * 64 + f * 16, acc[f], 132, wmma::mem_row_major);
            __syncthreads();
            for (int i = tid; i < 64 * 32; i += 256) {
                int row = i >> 5, c4 = i & 31;
                int n = nbase + row;
                if (n < NN)
                    ((float4*)(g_z + (size_t)n * 256 + half * 128))[c4] =
                        *(float4*)(Cf + row * 132 + c4 * 4);
            }
        }
    }
}

// ---------------------------------------------------------------- launch 3: edge encoder (3 blocks/SM)
#define EN_F   0        // 64 x 12 fp32
#define EN_HHI 4096     // 64 x 136 bf16
#define EN_HLO 21504
#define EN_W   38912    // 64 x 136 bf16 (K-chunk)
#define EN_WLO 56320
#define EN_SMEM 73728

__global__ void __launch_bounds__(256, 3) k_edge_enc2(
    const float* __restrict__ pos, const float* __restrict__ vel,
    const int* __restrict__ rid,
    const int* __restrict__ snd, const int* __restrict__ rcv,
    const float* __restrict__ eW1, const float* __restrict__ eB1,
    const float* __restrict__ eB2)
{
    extern __shared__ char smc[];
    float*         F   = (float*)(smc + EN_F);
    __nv_bfloat16* Hhi = (__nv_bfloat16*)(smc + EN_HHI);
    __nv_bfloat16* Hlo = (__nv_bfloat16*)(smc + EN_HLO);
    __nv_bfloat16* Whi = (__nv_bfloat16*)(smc + EN_W);
    __nv_bfloat16* Wlo = (__nv_bfloat16*)(smc + EN_WLO);
    float*         Cf  = (float*)(smc + EN_W);    // aliases W
    const int tid = threadIdx.x;
    const int w = tid >> 5, rt = w & 1, cg = w >> 1;   // 2 x 4 tiling
    const int tile = blockIdx.x;
    const int ebase = tile * 64;
    const uint32_t whi_b = smem_u32(Whi), wlo_b = smem_u32(Wlo);

    for (int i = tid; i < 1024; i += 256) {
        int r = i >> 4, g = i & 15;
        cp_async16(whi_b + (uint32_t)(r * 272 + g * 16), g_we2 + r * 128 + g * 8);
        cp_async16(wlo_b + (uint32_t)(r * 272 + g * 16), g_we2 + 16384 + r * 128 + g * 8);
    }
    cp_commit();
    if (tid < 64) {
        int e = ebase + tid;
        int s = snd[e], r = rcv[e];
        float rp0 = pos[s * 3 + 0] - pos[r * 3 + 0];
        float rp1 = pos[s * 3 + 1] - pos[r * 3 + 1];
        float rp2 = pos[s * 3 + 2] - pos[r * 3 + 2];
        float rv0 = vel[s * 3 + 0] - vel[r * 3 + 0];
        float rv1 = vel[s * 3 + 1] - vel[r * 3 + 1];
        float rv2 = vel[s * 3 + 2] - vel[r * 3 + 2];
        float sq = rp0 * rp0 + rp1 * rp1 + rp2 * rp2;
        float dist = sqrtf(sq);
        float same = (rid[s] == rid[r]) ? 1.f : 0.f;
        float* f = F + tid * 12;
        f[0] = rp0; f[1] = rp1; f[2] = rp2;
        f[3] = rv0; f[4] = rv1; f[5] = rv2;
        f[6] = dist; f[7] = sq; f[8] = same;
    }
    __syncthreads();

    {
        const int j = tid & 127;
        for (int n = tid >> 7; n < 64; n += 2) {
            float acc = eB1[j];
#pragma unroll
            for (int k = 0; k < 9; k++) acc += F[n * 12 + k] * eW1[k * 128 + j];
            acc = fmaxf(acc, 0.f);
            __nv_bfloat16 h = __float2bfloat16(acc);
            Hhi[n * 136 + j] = h;
            Hlo[n * 136 + j] = __float2bfloat16(acc - __bfloat162float(h));
        }
    }
    cp_wait0();
    __syncthreads();

    CF acc[2][2];
#pragma unroll
    for (int sr = 0; sr < 2; sr++)
#pragma unroll
        for (int sc = 0; sc < 2; sc++) wmma::fill_fragment(acc[sr][sc], 0.f);
#pragma unroll 1
    for (int kc = 0; kc < 128; kc += 64) {
        if (kc) {
            __syncthreads();
            for (int i = tid; i < 1024; i += 256) {
                int r = i >> 4, g = i & 15;
                cp_async16(whi_b + (uint32_t)(r * 272 + g * 16), g_we2 + (kc + r) * 128 + g * 8);
                cp_async16(wlo_b + (uint32_t)(r * 272 + g * 16), g_we2 + 16384 + (kc + r) * 128 + g * 8);
            }
            cp_commit_wait();
            __syncthreads();
        }
        for (int kk = 0; kk < 64; kk += 16) {
            AF ah[2], al[2];
#pragma unroll
            for (int sr = 0; sr < 2; sr++) {
                wmma::load_matrix_sync(ah[sr], Hhi + (rt * 32 + sr * 16) * 136 + kc + kk, 136);
                wmma::load_matrix_sync(al[sr], Hlo + (rt * 32 + sr * 16) * 136 + kc + kk, 136);
            }
#pragma unroll
            for (int sc = 0; sc < 2; sc++) {
                BF bh, bl;
                wmma::load_matrix_sync(bh, Whi + kk * 136 + cg * 32 + sc * 16, 136);
                wmma::load_matrix_sync(bl, Wlo + kk * 136 + cg * 32 + sc * 16, 136);
#pragma unroll
                for (int sr = 0; sr < 2; sr++) {
                    wmma::mma_sync(acc[sr][sc], ah[sr], bh, acc[sr][sc]);
                    wmma::mma_sync(acc[sr][sc], ah[sr], bl, acc[sr][sc]);
                    wmma::mma_sync(acc[sr][sc], al[sr], bh, acc[sr][sc]);
                }
            }
        }
    }
    __syncthreads();
#pragma unroll
    for (int sr = 0; sr < 2; sr++)
#pragma unroll
        for (int sc = 0; sc < 2; sc++)
            wmma::store_matrix_sync(Cf + (rt * 32 + sr * 16) * 132 + cg * 32 + sc * 16,
                                    acc[sr][sc], 132, wmma::mem_row_major);
    __syncthreads();

    __nv_bfloat16* elbase = g_el + (size_t)tile * 16384;
    for (int i = tid; i < 2048; i += 256) {
        int row = i >> 5, c4 = i & 31;
        float4 c = *(float4*)(Cf + row * 132 + c4 * 4);
        float4 b = ((const float4*)eB2)[c4];
        float4 nv = make_float4(c.x + b.x, c.y + b.y, c.z + b.z, c.w + b.w);
        __nv_bfloat16* hp = elbase + row * 128 + c4 * 4;
        split_store4(nv, hp, hp + 8192);
    }
}

// ---------------------------------------------------------------- edge processor step (R9 exact)
#define ES_SSH 0
#define ES_RSH 256
#define ES_B1  512
#define ES_B2  1024
#define ES_AHI 1536
#define ES_ALO 18944
#define ES_W   36352
#define ES_WLO 53760
#define ES_SMEM 71168

__global__ void __launch_bounds__(256, 3) k_edge_step(
    const int* __restrict__ snd, const int* __restrict__ rcv, int step,
    const float* __restrict__ B1, const float* __restrict__ B2)
{
    extern __shared__ char smc[];
    int*   ssh = (int*)(smc + ES_SSH);
    int*   rsh = (int*)(smc + ES_RSH);
    float* B1s = (float*)(smc + ES_B1);
    float* B2s = (float*)(smc + ES_B2);
    __nv_bfloat16* Ahi = (__nv_bfloat16*)(smc + ES_AHI);
    __nv_bfloat16* Alo = (__nv_bfloat16*)(smc + ES_ALO);
    __nv_bfloat16* Whi = (__nv_bfloat16*)(smc + ES_W);
    __nv_bfloat16* Wlo = (__nv_bfloat16*)(smc + ES_WLO);
    float*         Cf  = (float*)(smc + ES_W);
    const int tid = threadIdx.x;
    const int w = tid >> 5, rt = w & 1, cg = w >> 1;
    const int ebase = blockIdx.x * 64;
    const __nv_bfloat16* wbase = g_ws + (size_t)step * STEP_W;
    __nv_bfloat16* elbase = g_el + (size_t)blockIdx.x * 16384;
    const uint32_t whi_b = smem_u32(Whi), wlo_b = smem_u32(Wlo);
    const uint32_t ahi_b = smem_u32(Ahi), alo_b = smem_u32(Alo);

    if (tid < 64) {
        ssh[tid] = snd[ebase + tid];
        rsh[tid] = rcv[ebase + tid];
    }
    if (tid < 128) {
        B1s[tid] = B1[tid];
        B2s[tid] = B2[tid];
    }
    for (int i = tid; i < 1024; i += 256) {
        int r = i >> 4, g = i & 15;
        cp_async16(ahi_b + (uint32_t)(r * 272 + g * 16), elbase + r * 128 + g * 8);
        cp_async16(alo_b + (uint32_t)(r * 272 + g * 16), elbase + 8192 + r * 128 + g * 8);
        cp_async16(whi_b + (uint32_t)(r * 272 + g * 16), wbase + EW1A_HI + r * 128 + g * 8);
        cp_async16(wlo_b + (uint32_t)(r * 272 + g * 16), wbase + EW1A_LO + r * 128 + g * 8);
    }
    cp_commit_wait();
    __syncthreads();

    CF acc[2][2];
#pragma unroll
    for (int sr = 0; sr < 2; sr++)
#pragma unroll
        for (int sc = 0; sc < 2; sc++) wmma::fill_fragment(acc[sr][sc], 0.f);

#pragma unroll 1
    for (int kc = 0; kc < 128; kc += 64) {
        if (kc) {
            __syncthreads();
            for (int i = tid; i < 1024; i += 256) {
                int r = i >> 4, g = i & 15;
                cp_async16(whi_b + (uint32_t)(r * 272 + g * 16), wbase + EW1A_HI + (kc + r) * 128 + g * 8);
                cp_async16(wlo_b + (uint32_t)(r * 272 + g * 16), wbase + EW1A_LO + (kc + r) * 128 + g * 8);
            }
            cp_commit_wait();
            __syncthreads();
        }
        for (int kk = 0; kk < 64; kk += 16) {
            AF ah[2], al[2];
#pragma unroll
            for (int sr = 0; sr < 2; sr++) {
                wmma::load_matrix_sync(ah[sr], Ahi + (rt * 32 + sr * 16) * 136 + kc + kk, 136);
                wmma::load_matrix_sync(al[sr], Alo + (rt * 32 + sr * 16) * 136 + kc + kk, 136);
            }
#pragma unroll
            for (int sc = 0; sc < 2; sc++) {
                BF bh, bl;
                wmma::load_matrix_sync(bh, Whi + kk * 136 + cg * 32 + sc * 16, 136);
                wmma::load_matrix_sync(bl, Wlo + kk * 136 + cg * 32 + sc * 16, 136);
#pragma unroll
                for (int sr = 0; sr < 2; sr++) {
                    wmma::mma_sync(acc[sr][sc], ah[sr], bh, acc[sr][sc]);
                    wmma::mma_sync(acc[sr][sc], ah[sr], bl, acc[sr][sc]);
                    wmma::mma_sync(acc[sr][sc], al[sr], bh, acc[sr][sc]);
                }
            }
        }
    }
    __syncthreads();
#pragma unroll
    for (int sr = 0; sr < 2; sr++)
#pragma unroll
        for (int sc = 0; sc < 2; sc++)
            wmma::store_matrix_sync(Cf + (rt * 32 + sr * 16) * 132 + cg * 32 + sc * 16,
                                    acc[sr][sc], 132, wmma::mem_row_major);
    __syncthreads();

    for (int i = tid; i < 2048; i += 256) {
        int row = i >> 5, c4 = i & 31;
        int s = ssh[row], r = rsh[row];
        float4 c = *(float4*)(Cf + row * 132 + c4 * 4);
        float4 zb = ((const float4*)(g_z + (size_t)s * 256))[c4];
        float4 zc = ((const float4*)(g_z + (size_t)r * 256 + 128))[c4];
        float4 b = ((const float4*)B1s)[c4];
        float4 v = make_float4(
            fmaxf(c.x + zb.x + zc.x + b.x, 0.f),
            fmaxf(c.y + zb.y + zc.y + b.y, 0.f),
            fmaxf(c.z + zb.z + zc.z + b.z, 0.f),
            fmaxf(c.w + zb.w + zc.w + b.w, 0.f));
        split_store4(v, Ahi + row * 136 + c4 * 4, Alo + row * 136 + c4 * 4);
    }
    __syncthreads();

#pragma unroll
    for (int sr = 0; sr < 2; sr++)
#pragma unroll
        for (int sc = 0; sc < 2; sc++) wmma::fill_fragment(acc[sr][sc], 0.f);
#pragma unroll 1
    for (int kc = 0; kc < 128; kc += 64) {
        for (int i = tid; i < 1024; i += 256) {
            int r = i >> 4, g = i & 15;
            cp_async16(whi_b + (uint32_t)(r * 272 + g * 16), wbase + EW2_HI + (kc + r) * 128 + g * 8);
            cp_async16(wlo_b + (uint32_t)(r * 272 + g * 16), wbase + EW2_LO + (kc + r) * 128 + g * 8);
        }
        cp_commit_wait();
        __syncthreads();
        for (int kk = 0; kk < 64; kk += 16) {
            AF ah[2], al[2];
#pragma unroll
            for (int sr = 0; sr < 2; sr++) {
                wmma::load_matrix_sync(ah[sr], Ahi + (rt * 32 + sr * 16) * 136 + kc + kk, 136);
                wmma::load_matrix_sync(al[sr], Alo + (rt * 32 + sr * 16) * 136 + kc + kk, 136);
            }
#pragma unroll
            for (int sc = 0; sc < 2; sc++) {
                BF bh, bl;
                wmma::load_matrix_sync(bh, Whi + kk * 136 + cg * 32 + sc * 16, 136);
                wmma::load_matrix_sync(bl, Wlo + kk * 136 + cg * 32 + sc * 16, 136);
#pragma unroll
                for (int sr = 0; sr < 2; sr++) {
                    wmma::mma_sync(acc[sr][sc], ah[sr], bh, acc[sr][sc]);
                    wmma::mma_sync(acc[sr][sc], ah[sr], bl, acc[sr][sc]);
                    wmma::mma_sync(acc[sr][sc], al[sr], bh, acc[sr][sc]);
                }
            }
        }
        __syncthreads();
    }
#pragma unroll
    for (int sr = 0; sr < 2; sr++)
#pragma unroll
        for (int sc = 0; sc < 2; sc++)
            wmma::store_matrix_sync(Cf + (rt * 32 + sr * 16) * 132 + cg * 32 + sc * 16,
                                    acc[sr][sc], 132, wmma::mem_row_major);
    __syncthreads();

    for (int i = tid; i < 2048; i += 256) {
        int row = i >> 5, c4 = i & 31;
        __nv_bfloat16* hp = elbase + row * 128 + c4 * 4;
        float4 oldv = join4(hp, hp + 8192);
        float4 c = *(float4*)(Cf + row * 132 + c4 * 4);
        float4 b = ((const float4*)B2s)[c4];
        float4 nv = make_float4(oldv.x + c.x + b.x, oldv.y + c.y + b.y,
                                oldv.z + c.z + b.z, oldv.w + c.w + b.w);
        split_store4(nv, hp, hp + 8192);
        red_add_v4(g_agg + (size_t)rsh[row] * LL + c4 * 4, nv);
    }
}

// ---------------------------------------------------------------- node step (+fused projection), 3 blocks/SM
// Region A @0: X K-chunk (64x64 in 64x136 planes) during GEMM1, then H planes (64x128).
// Region B @34816: W K-chunk planes; Cf fp32 aliases B.
#define N2_AHI 0
#define N2_ALO 17408
#define N2_W   34816
#define N2_WLO 52224
#define N2_SMEM 69632

__global__ void __launch_bounds__(256, 3) k_node_step(
    int step, const float* __restrict__ B1, const float* __restrict__ B2, int do_proj)
{
    extern __shared__ char smc[];
    __nv_bfloat16* Ahi = (__nv_bfloat16*)(smc + N2_AHI);
    __nv_bfloat16* Alo = (__nv_bfloat16*)(smc + N2_ALO);
    __nv_bfloat16* Whi = (__nv_bfloat16*)(smc + N2_W);
    __nv_bfloat16* Wlo = (__nv_bfloat16*)(smc + N2_WLO);
    float*         Cf  = (float*)(smc + N2_W);
    const int tid = threadIdx.x;
    const int w = tid >> 5, rt = w >> 1, cg = w & 1;
    const int nbase = blockIdx.x * 64;
    const bool full = (nbase + 64 <= NN);
    const __nv_bfloat16* wbase = g_ws + (size_t)step * STEP_W;
    const uint32_t whi_b = smem_u32(Whi), wlo_b = smem_u32(Wlo);

    CF acc[4];
#pragma unroll
    for (int f = 0; f < 4; f++) wmma::fill_fragment(acc[f], 0.f);

    // ---- GEMM1: X[64x256] @ NW1, X staged per 64-K chunk (single-use)
#pragma unroll 1
    for (int kc = 0; kc < 256; kc += 64) {
        __syncthreads();   // region A + B reuse
        // gather X chunk cols [kc, kc+64): nl for kc<128, agg (zeroed) otherwise
        for (int i = tid; i < 1024; i += 256) {
            int row = i >> 4, g = i & 15;
            int n = nbase + row;
            float4 v = make_float4(0.f, 0.f, 0.f, 0.f);
            if (n < NN) {
                if (kc < 128) {
                    v = ((const float4*)(g_nl + (size_t)n * LL))[(kc >> 2) + g];
                } else {
                    float4* ap = (float4*)(g_agg + (size_t)n * LL) + (((kc - 128) >> 2) + g);
                    v = *ap;
                    *ap = make_float4(0.f, 0.f, 0.f, 0.f);
                }
            }
            split_store4(v, Ahi + row * 136 + g * 4, Alo + row * 136 + g * 4);
        }
        // stage NW1 K-chunk
        for (int i = tid; i < 1024; i += 256) {
            int rr = i >> 4, g = i & 15;
            cp_async16(whi_b + (uint32_t)(rr * 272 + g * 16), wbase + NW1_HI + (kc + rr) * 128 + g * 8);
            cp_async16(wlo_b + (uint32_t)(rr * 272 + g * 16), wbase + NW1_LO + (kc + rr) * 128 + g * 8);
        }
        cp_commit_wait();
        __syncthreads();
        for (int kk = 0; kk < 64; kk += 16) {
            AF ah, al;
            wmma::load_matrix_sync(ah, Ahi + rt * 16 * 136 + kk, 136);
            wmma::load_matrix_sync(al, Alo + rt * 16 * 136 + kk, 136);
#pragma unroll
            for (int f = 0; f < 4; f++) {
                BF bh, bl;
                wmma::load_matrix_sync(bh, Whi + kk * 136 + cg * 64 + f * 16, 136);
                wmma::load_matrix_sync(bl, Wlo + kk * 136 + cg * 64 + f * 16, 136);
                wmma::mma_sync(acc[f], ah, bh, acc[f]);
                wmma::mma_sync(acc[f], ah, bl, acc[f]);
                wmma::mma_sync(acc[f], al, bh, acc[f]);
            }
        }
    }
    __syncthreads();
#pragma unroll
    for (int f = 0; f < 4; f++)
        wmma::store_matrix_sync(Cf + rt * 16 * 132 + cg * 64 + f * 16, acc[f], 132, wmma::mem_row_major);
    __syncthreads();
    // bias + relu -> H planes (region A; X fully consumed)
    for (int i = tid; i < 64 * 32; i += 256) {
        int row = i >> 5, c4 = i & 31;
        float4 v = *(float4*)(Cf + row * 132 + c4 * 4);
        float4 bb = ((const float4*)B1)[c4];
        v.x = fmaxf(v.x + bb.x, 0.f);
        v.y = fmaxf(v.y + bb.y, 0.f);
        v.z = fmaxf(v.z + bb.z, 0.f);
        v.w = fmaxf(v.w + bb.w, 0.f);
        split_store4(v, Ahi + row * 136 + c4 * 4, Alo + row * 136 + c4 * 4);
    }
    __syncthreads();

    // ---- GEMM2: H[64x128] @ NW2, K chunked
#pragma unroll
    for (int f = 0; f < 4; f++) wmma::fill_fragment(acc[f], 0.f);
#pragma unroll 1
    for (int kc = 0; kc < 128; kc += 64) {
        for (int i = tid; i < 1024; i += 256) {
            int rr = i >> 4, g = i & 15;
            cp_async16(whi_b + (uint32_t)(rr * 272 + g * 16), wbase + NW2_HI + (kc + rr) * 128 + g * 8);
            cp_async16(wlo_b + (uint32_t)(rr * 272 + g * 16), wbase + NW2_LO + (kc + rr) * 128 + g * 8);
        }
        cp_commit_wait();
        __syncthreads();
        for (int kk = 0; kk < 64; kk += 16) {
            AF ah, al;
            wmma::load_matrix_sync(ah, Ahi + rt * 16 * 136 + kc + kk, 136);
            wmma::load_matrix_sync(al, Alo + rt * 16 * 136 + kc + kk, 136);
#pragma unroll
            for (int f = 0; f < 4; f++) {
                BF bh, bl;
                wmma::load_matrix_sync(bh, Whi + kk * 136 + cg * 64 + f * 16, 136);
                wmma::load_matrix_sync(bl, Wlo + kk * 136 + cg * 64 + f * 16, 136);
                wmma::mma_sync(acc[f], ah, bh, acc[f]);
                wmma::mma_sync(acc[f], ah, bl, acc[f]);
                wmma::mma_sync(acc[f], al, bh, acc[f]);
            }
        }
        __syncthreads();
    }
#pragma unroll
    for (int f = 0; f < 4; f++)
        wmma::store_matrix_sync(Cf + rt * 16 * 132 + cg * 64 + f * 16, acc[f], 132, wmma::mem_row_major);
    __syncthreads();

    // ---- epilogue: nl += C2 + b2; write back; H planes (region A) for projection
    for (int i = tid; i < 64 * 32; i += 256) {
        int row = i >> 5, c4 = i & 31;
        int n = nbase + row;
        float4 nv = make_float4(0.f, 0.f, 0.f, 0.f);
        if (n < NN) {
            float4 oldv = ((const float4*)(g_nl + (size_t)n * LL))[c4];
            float4 c2 = *(float4*)(Cf + row * 132 + c4 * 4);
            float4 bb = ((const float4*)B2)[c4];
            nv = make_float4(oldv.x + c2.x + bb.x, oldv.y + c2.y + bb.y,
                             oldv.z + c2.z + bb.z, oldv.w + c2.w + bb.w);
            ((float4*)(g_nl + (size_t)n * LL))[c4] = nv;
        }
        if (do_proj)
            split_store4(nv, Ahi + row * 136 + c4 * 4, Alo + row * 136 + c4 * 4);
    }

    if (do_proj) {
        const __nv_bfloat16* wn = g_ws + (size_t)(step + 1) * STEP_W;
#pragma unroll 1
        for (int half = 0; half < 2; ++half) {
#pragma unroll
            for (int f = 0; f < 4; f++) wmma::fill_fragment(acc[f], 0.f);
#pragma unroll 1
            for (int kc = 0; kc < 128; kc += 64) {
                __syncthreads();
                for (int i = tid; i < 1024; i += 256) {
                    int rr = i >> 4, g = i & 15;
                    cp_async16(whi_b + (uint32_t)(rr * 272 + g * 16),
                               wn + PRJ_HI + (size_t)(kc + rr) * 256 + half * 128 + g * 8);
                    cp_async16(wlo_b + (uint32_t)(rr * 272 + g * 16),
                               wn + PRJ_LO + (size_t)(kc + rr) * 256 + half * 128 + g * 8);
                }
                cp_commit_wait();
                __syncthreads();
                for (int kk = 0; kk < 64; kk += 16) {
                    AF ah, al;
                    wmma::load_matrix_sync(ah, Ahi + rt * 16 * 136 + kc + kk, 136);
                    wmma::load_matrix_sync(al, Alo + rt * 16 * 136 + kc + kk, 136);
#pragma unroll
                    for (int f = 0; f < 4; f++) {
                        BF bh, bl;
                        wmma::load_matrix_sync(bh, Whi + kk * 136 + cg * 64 + f * 16, 136);
                        wmma::load_matrix_sync(bl, Wlo + kk * 136 + cg * 64 + f * 16, 136);
                        wmma::mma_sync(acc[f], ah, bh, acc[f]);
                        wmma::mma_sync(acc[f], ah, bl, acc[f]);
                        wmma::mma_sync(acc[f], al, bh, acc[f]);
                    }
                }
            }
            if (full) {
#pragma unroll
                for (int f = 0; f < 4; f++)
                    wmma::store_matrix_sync(g_z + (size_t)(nbase + rt * 16) * 256 + half * 128 + cg * 64 + f * 16,
                                            acc[f], 256, wmma::mem_row_major);
            } else {
                __syncthreads();
#pragma unroll
                for (int f = 0; f < 4; f++)
                    wmma::store_matrix_sync(Cf + rt * 16 * 132 + cg * 64 + f * 16, acc[f], 132, wmma::mem_row_major);
                __syncthreads();
                for (int i = tid; i < 64 * 32; i += 256) {
                    int row = i >> 5, c4 = i & 31;
                    int n = nbase + row;
                    if (n < NN)
                        ((float4*)(g_z + (size_t)n * 256 + half * 128))[c4] =
                            *(float4*)(Cf + row * 132 + c4 * 4);
                }
            }
        }
    }
}

// ---------------------------------------------------------------- decoder (SIMT fp32; exact)
__global__ void __launch_bounds__(128) k_decoder(
    const float* __restrict__ W1, const float* __restrict__ B1,
    const float* __restrict__ W2, const float* __restrict__ B2,
    float* __restrict__ out)
{
    __shared__ float Xs[32][128];
    __shared__ float H[32][128];
    const int tid = threadIdx.x;
    const int nbase = blockIdx.x * 32;

    for (int i = tid; i < 32 * 32; i += 128) {
        int n = i >> 5, c4 = i & 31;
        int gn = nbase + n;
        float4 v = make_float4(0.f, 0.f, 0.f, 0.f);
        if (gn < NN) v = ((const float4*)(g_nl + (size_t)gn * LL))[c4];
        ((float4*)Xs[n])[c4] = v;
    }
    __syncthreads();

    const int j = tid;
#pragma unroll 1
    for (int n = 0; n < 32; n++) {
        float acc = B1[j];
#pragma unroll 8
        for (int k = 0; k < 128; k++) acc += Xs[n][k] * W1[k * 128 + j];
        H[n][j] = fmaxf(acc, 0.f);
    }
    __syncthreads();

    if (tid < 96) {
        int n = tid / 3, d = tid % 3;
        int gn = nbase + n;
        float acc = B2[d];
#pragma unroll 8
        for (int k = 0; k < 128; k++) acc += H[n][k] * W2[k * 3 + d];
        if (gn < NN) out[gn * 3 + d] = acc;
    }
}

// ---------------------------------------------------------------- launch
extern "C" void kernel_launch(void* const* d_in, const int* in_sizes, int n_in,
                              void* d_out, int out_size)
{
    const float* pos   = (const float*)d_in[0];
    const float* vel   = (const float*)d_in[1];
    const int*   rid   = (const int*)d_in[2];
    const int*   snd   = (const int*)d_in[3];
    const int*   rcv   = (const int*)d_in[4];
    const float* remb  = (const float*)d_in[5];
    const float* ne_w1 = (const float*)d_in[6];
    const float* ne_b1 = (const float*)d_in[7];
    const float* ne_w2 = (const float*)d_in[8];
    const float* ne_b2 = (const float*)d_in[9];
    const float* ee_w1 = (const float*)d_in[10];
    const float* ee_b1 = (const float*)d_in[11];
    const float* ee_w2 = (const float*)d_in[12];
    const float* ee_b2 = (const float*)d_in[13];
    const float* pe_w1 = (const float*)d_in[14];
    const float* pe_b1 = (const float*)d_in[15];
    const float* pe_w2 = (const float*)d_in[16];
    const float* pe_b2 = (const float*)d_in[17];
    const float* pn_w1 = (const float*)d_in[18];
    const float* pn_b1 = (const float*)d_in[19];
    const float* pn_w2 = (const float*)d_in[20];
    const float* pn_b2 = (const float*)d_in[21];
    const float* de_w1 = (const float*)d_in[22];
    const float* de_b1 = (const float*)d_in[23];
    const float* de_w2 = (const float*)d_in[24];
    const float* de_b2 = (const float*)d_in[25];

    cudaFuncSetAttribute(k_edge_step, cudaFuncAttributeMaxDynamicSharedMemorySize, ES_SMEM);
    cudaFuncSetAttribute(k_node_step, cudaFuncAttributeMaxDynamicSharedMemorySize, N2_SMEM);
    cudaFuncSetAttribute(k_node_enc_proj, cudaFuncAttributeMaxDynamicSharedMemorySize, NEP_SMEM);
    cudaFuncSetAttribute(k_edge_enc2, cudaFuncAttributeMaxDynamicSharedMemorySize, EN_SMEM);

    k_setup<<<4740, 256>>>(pe_w1, pe_w2, pn_w1, pn_w2, ee_w2);
    k_degcenter<<<3229, 256>>>(rcv, pos);
    k_node_enc_proj<<<NB_ENC, 256, NEP_SMEM>>>(pos, vel, rid, remb, ne_w1, ne_b1, ne_w2, ne_b2);
    k_edge_enc2<<<EB_ENC, 256, EN_SMEM>>>(pos, vel, rid, snd, rcv, ee_w1, ee_b1, ee_b2);

    for (int st = 0; st < NSTEPS; st++) {
        k_edge_step<<<EE / 64, 256, ES_SMEM>>>(
            snd, rcv, st, pe_b1 + (size_t)st * 128, pe_b2 + (size_t)st * 128);
        k_node_step<<<(NN + 63) / 64, 256, N2_SMEM>>>(
            st, pn_b1 + (size_t)st * 128, pn_b2 + (size_t)st * 128, (st < NSTEPS - 1) ? 1 : 0);
    }

    k_decoder<<<(NN + 31) / 32, 128>>>(de_w1, de_b1, de_w2, de_b2, (float*)d_out);
}

// round 13
// speedup vs baseline: 1.3920x; 1.0510x over previous
#include <cuda_runtime.h>
#include <cuda_bf16.h>
#include <mma.h>
#include <cstdint>

using namespace nvcuda;

#define NN 50000
#define EE 800000
#define LL 128
#define NSTEPS 10
#define NB_ENC 782          // ceil(NN/64)
#define EB_ENC 12500        // EE/64

// ---- scratch (device globals; no allocations allowed) ----
__device__ float g_nl[(size_t)NN * LL];
// el stored as bf16 hi/lo planes, tile-major: [tile(64 edges)][hi 64x128][lo 64x128]
__device__ __nv_bfloat16 g_el[(size_t)EE * 256];
__device__ float g_agg[(size_t)NN * LL];
__device__ float g_z[(size_t)NN * 256];
__device__ float g_deg[NN];
__device__ float g_center[3];

#define EW1A_HI 0
#define EW1A_LO 16384
#define EW2_HI  32768
#define EW2_LO  49152
#define PRJ_HI  65536
#define PRJ_LO  98304
#define NW1_HI  131072
#define NW1_LO  163840
#define NW2_HI  196608
#define NW2_LO  212992
#define STEP_W  229376
__device__ __nv_bfloat16 g_ws[(size_t)NSTEPS * STEP_W];
// encoder W2 planes: hi [0,16384), lo [16384,32768)
__device__ __nv_bfloat16 g_we2[32768];

typedef wmma::fragment<wmma::matrix_a, 16, 16, 16, __nv_bfloat16, wmma::row_major> AF;
typedef wmma::fragment<wmma::matrix_b, 16, 16, 16, __nv_bfloat16, wmma::row_major> BF;
typedef wmma::fragment<wmma::accumulator, 16, 16, 16, float> CF;

__device__ __forceinline__ uint32_t smem_u32(const void* p) {
    uint32_t a;
    asm("{ .reg .u64 t; cvta.to.shared.u64 t, %1; cvt.u32.u64 %0, t; }" : "=r"(a) : "l"(p));
    return a;
}
// .cg: bypass L1 allocation (single-use staging data)
__device__ __forceinline__ void cp_async16(uint32_t dst, const void* src) {
    asm volatile("cp.async.cg.shared.global [%0], [%1], 16;" :: "r"(dst), "l"(src) : "memory");
}
__device__ __forceinline__ void cp_commit() {
    asm volatile("cp.async.commit_group;" ::: "memory");
}
__device__ __forceinline__ void cp_wait0() {
    asm volatile("cp.async.wait_group 0;" ::: "memory");
}
__device__ __forceinline__ void cp_commit_wait() {
    cp_commit();
    cp_wait0();
}

__device__ __forceinline__ void split_store4(float4 v, __nv_bfloat16* hip, __nv_bfloat16* lop) {
    __nv_bfloat162 h0 = __floats2bfloat162_rn(v.x, v.y);
    __nv_bfloat162 h1 = __floats2bfloat162_rn(v.z, v.w);
    float2 f0 = __bfloat1622float2(h0);
    float2 f1 = __bfloat1622float2(h1);
    __nv_bfloat162 l0 = __floats2bfloat162_rn(v.x - f0.x, v.y - f0.y);
    __nv_bfloat162 l1 = __floats2bfloat162_rn(v.z - f1.x, v.w - f1.y);
    *(__nv_bfloat162*)(hip)     = h0;
    *(__nv_bfloat162*)(hip + 2) = h1;
    *(__nv_bfloat162*)(lop)     = l0;
    *(__nv_bfloat162*)(lop + 2) = l1;
}

__device__ __forceinline__ float4 join4(const __nv_bfloat16* hip, const __nv_bfloat16* lop) {
    float2 a = __bfloat1622float2(*(const __nv_bfloat162*)hip);
    float2 b = __bfloat1622float2(*(const __nv_bfloat162*)(hip + 2));
    float2 c = __bfloat1622float2(*(const __nv_bfloat162*)lop);
    float2 d = __bfloat1622float2(*(const __nv_bfloat162*)(lop + 2));
    return make_float4(a.x + c.x, a.y + c.y, b.x + d.x, b.y + d.y);
}

__device__ __forceinline__ void red_add_v4(float* dst, float4 v) {
    asm volatile("red.global.add.v4.f32 [%0], {%1,%2,%3,%4};"
                 :: "l"(dst), "f"(v.x), "f"(v.y), "f"(v.z), "f"(v.w) : "memory");
}

// ---------------------------------------------------------------- launch 0: weight prep + init
__global__ void __launch_bounds__(256) k_setup(
    const float* __restrict__ pe_w1, const float* __restrict__ pe_w2,
    const float* __restrict__ pn_w1, const float* __restrict__ pn_w2,
    const float* __restrict__ ee_w2)
{
    if (blockIdx.x < 4480) {
        int idx = blockIdx.x * 256 + threadIdx.x;
        int s = idx / 114688;
        int e = idx % 114688;
        float v;
        size_t dhi, dlo;
        if (e < 16384) {
            v = pe_w1[(size_t)s * 384 * 128 + e];
            dhi = EW1A_HI + e; dlo = EW1A_LO + e;
        } else if (e < 32768) {
            int e2 = e - 16384;
            v = pe_w2[(size_t)s * 128 * 128 + e2];
            dhi = EW2_HI + e2; dlo = EW2_LO + e2;
        } else if (e < 65536) {
            int e2 = e - 32768;
            int k = e2 >> 8, n = e2 & 255;
            int srcrow = 128 + (n >> 7) * 128 + k;
            v = pe_w1[(size_t)s * 384 * 128 + (size_t)srcrow * 128 + (n & 127)];
            dhi = PRJ_HI + e2; dlo = PRJ_LO + e2;
        } else if (e < 98304) {
            int e2 = e - 65536;
            v = pn_w1[(size_t)s * 256 * 128 + e2];
            dhi = NW1_HI + e2; dlo = NW1_LO + e2;
        } else {
            int e2 = e - 98304;
            v = pn_w2[(size_t)s * 128 * 128 + e2];
            dhi = NW2_HI + e2; dlo = NW2_LO + e2;
        }
        __nv_bfloat16 h = __float2bfloat16(v);
        g_ws[(size_t)s * STEP_W + dhi] = h;
        g_ws[(size_t)s * STEP_W + dlo] = __float2bfloat16(v - __bfloat162float(h));
    } else if (blockIdx.x < 4544) {
        int i = (blockIdx.x - 4480) * 256 + threadIdx.x;   // < 16384
        float v = ee_w2[i];
        __nv_bfloat16 h = __float2bfloat16(v);
        g_we2[i] = h;
        g_we2[16384 + i] = __float2bfloat16(v - __bfloat162float(h));
    } else {
        int i = (blockIdx.x - 4544) * 256 + threadIdx.x;
        if (i < NN) g_deg[i] = 0.f;
        if (i < 3) g_center[i] = 0.f;
    }
}

// ---------------------------------------------------------------- launch 1: degree + center
__global__ void __launch_bounds__(256) k_degcenter(
    const int* __restrict__ rcv, const float* __restrict__ pos)
{
    if (blockIdx.x < 3125) {
        int i = blockIdx.x * 256 + threadIdx.x;
        if (i < EE) atomicAdd(&g_deg[rcv[i]], 1.f);
    } else {
        float sx = 0.f, sy = 0.f, sz = 0.f;
        for (int i = (blockIdx.x - 3125) * 256 + threadIdx.x; i < NN; i += 104 * 256) {
            sx += pos[i * 3 + 0];
            sy += pos[i * 3 + 1];
            sz += pos[i * 3 + 2];
        }
#pragma unroll
        for (int o = 16; o > 0; o >>= 1) {
            sx += __shfl_down_sync(0xffffffffu, sx, o);
            sy += __shfl_down_sync(0xffffffffu, sy, o);
            sz += __shfl_down_sync(0xffffffffu, sz, o);
        }
        if ((threadIdx.x & 31) == 0) {
            atomicAdd(&g_center[0], sx);
            atomicAdd(&g_center[1], sy);
            atomicAdd(&g_center[2], sz);
        }
    }
}

// ---------------------------------------------------------------- launch 2: node encoder + step-0 projection
#define NEP_SMEM 110592

__global__ void __launch_bounds__(256, 2) k_node_enc_proj(
    const float* __restrict__ pos, const float* __restrict__ vel,
    const int* __restrict__ rid, const float* __restrict__ remb,
    const float* __restrict__ nW1, const float* __restrict__ nB1,
    const float* __restrict__ nW2, const float* __restrict__ nB2)
{
    extern __shared__ char smc[];
    const int tid = threadIdx.x;
    float* F = (float*)(smc + 0);
    float* H = (float*)(smc + 8192);
    __nv_bfloat16* Ahi = (__nv_bfloat16*)(smc + 40960);
    __nv_bfloat16* Alo = (__nv_bfloat16*)(smc + 58368);
    __nv_bfloat16* Wch = (__nv_bfloat16*)(smc + 75776);
    __nv_bfloat16* Wcl = (__nv_bfloat16*)(smc + 93184);
    const int nbase = blockIdx.x * 64;
    const float inv = 1.f / (float)NN;
    const float cx = g_center[0] * inv, cy = g_center[1] * inv, cz = g_center[2] * inv;

    for (int i = tid; i < 64 * 23; i += 256) {
        int n = i / 23, k = i % 23;
        int gn = nbase + n;
        float v = 0.f;
        if (gn < NN) {
            if (k < 3) v = vel[gn * 3 + k];
            else if (k < 6) v = pos[gn * 3 + (k - 3)] - ((k == 3) ? cx : (k == 4) ? cy : cz);
            else if (k == 6) v = g_deg[gn];
            else v = remb[rid[gn] * 16 + (k - 7)];
        }
        F[n * 24 + k] = v;
    }
    __syncthreads();

    const int j = tid & 127;
    for (int n = tid >> 7; n < 64; n += 2) {
        float acc = nB1[j];
#pragma unroll
        for (int k = 0; k < 23; k++) acc += F[n * 24 + k] * nW1[k * 128 + j];
        H[n * 128 + j] = fmaxf(acc, 0.f);
    }
    __syncthreads();
    for (int n = tid >> 7; n < 64; n += 2) {
        int gn = nbase + n;
        float acc = nB2[j];
#pragma unroll 8
        for (int k = 0; k < 128; k++) acc += H[n * 128 + k] * nW2[k * 128 + j];
        float v = (gn < NN) ? acc : 0.f;
        if (gn < NN) g_nl[(size_t)gn * LL + j] = v;
        __nv_bfloat16 h = __float2bfloat16(v);
        Ahi[n * 136 + j] = h;
        Alo[n * 136 + j] = __float2bfloat16(v - __bfloat162float(h));
    }
    __syncthreads();

    // projection Z(0) = nl @ PRJ(0)
    const int w = tid >> 5, rt = w >> 1, cg = w & 1;
    const bool full = (nbase + 64 <= NN);
    const __nv_bfloat16* wn = g_ws;
    CF acc[4];
#pragma unroll 1
    for (int half = 0; half < 2; ++half) {
#pragma unroll
        for (int f = 0; f < 4; f++) wmma::fill_fragment(acc[f], 0.f);
        for (int kc = 0; kc < 128; kc += 64) {
            __syncthreads();
            for (int i = tid; i < 1024; i += 256) {
                int rr = i >> 4, g = i & 15;
                *(float4*)(Wch + rr * 136 + g * 8) =
                    ((const float4*)(wn + PRJ_HI + (size_t)(kc + rr) * 256 + half * 128))[g];
                *(float4*)(Wcl + rr * 136 + g * 8) =
                    ((const float4*)(wn + PRJ_LO + (size_t)(kc + rr) * 256 + half * 128))[g];
            }
            __syncthreads();
            for (int kk = 0; kk < 64; kk += 16) {
                AF ah, al;
                wmma::load_matrix_sync(ah, Ahi + rt * 16 * 136 + kc + kk, 136);
                wmma::load_matrix_sync(al, Alo + rt * 16 * 136 + kc + kk, 136);
#pragma unroll
                for (int f = 0; f < 4; f++) {
                    BF bh, bl;
                    wmma::load_matrix_sync(bh, Wch + kk * 136 + cg * 64 + f * 16, 136);
                    wmma::load_matrix_sync(bl, Wcl + kk * 136 + cg * 64 + f * 16, 136);
                    wmma::mma_sync(acc[f], ah, bh, acc[f]);
                    wmma::mma_sync(acc[f], ah, bl, acc[f]);
                    wmma::mma_sync(acc[f], al, bh, acc[f]);
                }
            }
        }
        if (full) {
#pragma unroll
            for (int f = 0; f < 4; f++)
                wmma::store_matrix_sync(g_z + (size_t)(nbase + rt * 16) * 256 + half * 128 + cg * 64 + f * 16,
                                        acc[f], 256, wmma::mem_row_major);
        } else {
            float* Cf = (float*)(smc + 75776);   // dead W region; restaged next half
            __syncthreads();
#pragma unroll
            for (int f = 0; f < 4; f++)
                wmma::store_matrix_sync(Cf + rt * 16 * 132 + cg * 64 + f * 16, acc[f], 132, wmma::mem_row_major);
            __syncthreads();
            for (int i = tid; i < 64 * 32; i += 256) {
                int row = i >> 5, c4 = i & 31;
                int n = nbase + row;
                if (n < NN)
                    ((float4*)(g_z + (size_t)n * 256 + half * 128))[c4] =
                        *(float4*)(Cf + row * 132 + c4 * 4);
            }
        }
    }
}

// ---------------------------------------------------------------- launch 3: edge encoder (3 blocks/SM)
#define EN_F   0        // 64 x 12 fp32
#define EN_HHI 4096     // 64 x 136 bf16
#define EN_HLO 21504
#define EN_W   38912    // 64 x 136 bf16 (K-chunk)
#define EN_WLO 56320
#define EN_SMEM 73728

__global__ void __launch_bounds__(256, 3) k_edge_enc2(
    const float* __restrict__ pos, const float* __restrict__ vel,
    const int* __restrict__ rid,
    const int* __restrict__ snd, const int* __restrict__ rcv,
    const float* __restrict__ eW1, const float* __restrict__ eB1,
    const float* __restrict__ eB2)
{
    extern __shared__ char smc[];
    float*         F   = (float*)(smc + EN_F);
    __nv_bfloat16* Hhi = (__nv_bfloat16*)(smc + EN_HHI);
    __nv_bfloat16* Hlo = (__nv_bfloat16*)(smc + EN_HLO);
    __nv_bfloat16* Whi = (__nv_bfloat16*)(smc + EN_W);
    __nv_bfloat16* Wlo = (__nv_bfloat16*)(smc + EN_WLO);
    float*         Cf  = (float*)(smc + EN_W);    // aliases W
    const int tid = threadIdx.x;
    const int w = tid >> 5, rt = w & 1, cg = w >> 1;   // 2 x 4 tiling
    const int tile = blockIdx.x;
    const int ebase = tile * 64;
    const uint32_t whi_b = smem_u32(Whi), wlo_b = smem_u32(Wlo);

    for (int i = tid; i < 1024; i += 256) {
        int r = i >> 4, g = i & 15;
        cp_async16(whi_b + (uint32_t)(r * 272 + g * 16), g_we2 + r * 128 + g * 8);
        cp_async16(wlo_b + (uint32_t)(r * 272 + g * 16), g_we2 + 16384 + r * 128 + g * 8);
    }
    cp_commit();
    if (tid < 64) {
        int e = ebase + tid;
        int s = snd[e], r = rcv[e];
        float rp0 = pos[s * 3 + 0] - pos[r * 3 + 0];
        float rp1 = pos[s * 3 + 1] - pos[r * 3 + 1];
        float rp2 = pos[s * 3 + 2] - pos[r * 3 + 2];
        float rv0 = vel[s * 3 + 0] - vel[r * 3 + 0];
        float rv1 = vel[s * 3 + 1] - vel[r * 3 + 1];
        float rv2 = vel[s * 3 + 2] - vel[r * 3 + 2];
        float sq = rp0 * rp0 + rp1 * rp1 + rp2 * rp2;
        float dist = sqrtf(sq);
        float same = (rid[s] == rid[r]) ? 1.f : 0.f;
        float* f = F + tid * 12;
        f[0] = rp0; f[1] = rp1; f[2] = rp2;
        f[3] = rv0; f[4] = rv1; f[5] = rv2;
        f[6] = dist; f[7] = sq; f[8] = same;
    }
    __syncthreads();

    {
        const int j = tid & 127;
        for (int n = tid >> 7; n < 64; n += 2) {
            float acc = eB1[j];
#pragma unroll
            for (int k = 0; k < 9; k++) acc += F[n * 12 + k] * eW1[k * 128 + j];
            acc = fmaxf(acc, 0.f);
            __nv_bfloat16 h = __float2bfloat16(acc);
            Hhi[n * 136 + j] = h;
            Hlo[n * 136 + j] = __float2bfloat16(acc - __bfloat162float(h));
        }
    }
    cp_wait0();
    __syncthreads();

    CF acc[2][2];
#pragma unroll
    for (int sr = 0; sr < 2; sr++)
#pragma unroll
        for (int sc = 0; sc < 2; sc++) wmma::fill_fragment(acc[sr][sc], 0.f);
#pragma unroll 1
    for (int kc = 0; kc < 128; kc += 64) {
        if (kc) {
            __syncthreads();
            for (int i = tid; i < 1024; i += 256) {
                int r = i >> 4, g = i & 15;
                cp_async16(whi_b + (uint32_t)(r * 272 + g * 16), g_we2 + (kc + r) * 128 + g * 8);
                cp_async16(wlo_b + (uint32_t)(r * 272 + g * 16), g_we2 + 16384 + (kc + r) * 128 + g * 8);
            }
            cp_commit_wait();
            __syncthreads();
        }
        for (int kk = 0; kk < 64; kk += 16) {
            AF ah[2], al[2];
#pragma unroll
            for (int sr = 0; sr < 2; sr++) {
                wmma::load_matrix_sync(ah[sr], Hhi + (rt * 32 + sr * 16) * 136 + kc + kk, 136);
                wmma::load_matrix_sync(al[sr], Hlo + (rt * 32 + sr * 16) * 136 + kc + kk, 136);
            }
#pragma unroll
            for (int sc = 0; sc < 2; sc++) {
                BF bh, bl;
                wmma::load_matrix_sync(bh, Whi + kk * 136 + cg * 32 + sc * 16, 136);
                wmma::load_matrix_sync(bl, Wlo + kk * 136 + cg * 32 + sc * 16, 136);
#pragma unroll
                for (int sr = 0; sr < 2; sr++) {
                    wmma::mma_sync(acc[sr][sc], ah[sr], bh, acc[sr][sc]);
                    wmma::mma_sync(acc[sr][sc], ah[sr], bl, acc[sr][sc]);
                    wmma::mma_sync(acc[sr][sc], al[sr], bh, acc[sr][sc]);
                }
            }
        }
    }
    __syncthreads();
#pragma unroll
    for (int sr = 0; sr < 2; sr++)
#pragma unroll
        for (int sc = 0; sc < 2; sc++)
            wmma::store_matrix_sync(Cf + (rt * 32 + sr * 16) * 132 + cg * 32 + sc * 16,
                                    acc[sr][sc], 132, wmma::mem_row_major);
    __syncthreads();

    __nv_bfloat16* elbase = g_el + (size_t)tile * 16384;
    for (int i = tid; i < 2048; i += 256) {
        int row = i >> 5, c4 = i & 31;
        float4 c = *(float4*)(Cf + row * 132 + c4 * 4);
        float4 b = ((const float4*)eB2)[c4];
        float4 nv = make_float4(c.x + b.x, c.y + b.y, c.z + b.z, c.w + b.w);
        __nv_bfloat16* hp = elbase + row * 128 + c4 * 4;
        split_store4(nv, hp, hp + 8192);
    }
}

// ---------------------------------------------------------------- edge processor step
#define ES_SSH 0
#define ES_RSH 256
#define ES_B1  512
#define ES_B2  1024
#define ES_AHI 1536
#define ES_ALO 18944
#define ES_W   36352
#define ES_WLO 53760
#define ES_SMEM 71168

__global__ void __launch_bounds__(256, 3) k_edge_step(
    const int* __restrict__ snd, const int* __restrict__ rcv, int step,
    const float* __restrict__ B1, const float* __restrict__ B2)
{
    extern __shared__ char smc[];
    int*   ssh = (int*)(smc + ES_SSH);
    int*   rsh = (int*)(smc + ES_RSH);
    float* B1s = (float*)(smc + ES_B1);
    float* B2s = (float*)(smc + ES_B2);
    __nv_bfloat16* Ahi = (__nv_bfloat16*)(smc + ES_AHI);
    __nv_bfloat16* Alo = (__nv_bfloat16*)(smc + ES_ALO);
    __nv_bfloat16* Whi = (__nv_bfloat16*)(smc + ES_W);
    __nv_bfloat16* Wlo = (__nv_bfloat16*)(smc + ES_WLO);
    float*         Cf  = (float*)(smc + ES_W);
    const int tid = threadIdx.x;
    const int w = tid >> 5, rt = w & 1, cg = w >> 1;
    const int ebase = blockIdx.x * 64;
    const __nv_bfloat16* wbase = g_ws + (size_t)step * STEP_W;
    __nv_bfloat16* elbase = g_el + (size_t)blockIdx.x * 16384;
    const uint32_t whi_b = smem_u32(Whi), wlo_b = smem_u32(Wlo);
    const uint32_t ahi_b = smem_u32(Ahi), alo_b = smem_u32(Alo);

    if (tid < 64) {
        ssh[tid] = snd[ebase + tid];
        rsh[tid] = rcv[ebase + tid];
    }
    if (tid < 128) {
        B1s[tid] = B1[tid];
        B2s[tid] = B2[tid];
    }
    for (int i = tid; i < 1024; i += 256) {
        int r = i >> 4, g = i & 15;
        cp_async16(ahi_b + (uint32_t)(r * 272 + g * 16), elbase + r * 128 + g * 8);
        cp_async16(alo_b + (uint32_t)(r * 272 + g * 16), elbase + 8192 + r * 128 + g * 8);
        cp_async16(whi_b + (uint32_t)(r * 272 + g * 16), wbase + EW1A_HI + r * 128 + g * 8);
        cp_async16(wlo_b + (uint32_t)(r * 272 + g * 16), wbase + EW1A_LO + r * 128 + g * 8);
    }
    cp_commit_wait();
    __syncthreads();

    CF acc[2][2];
#pragma unroll
    for (int sr = 0; sr < 2; sr++)
#pragma unroll
        for (int sc = 0; sc < 2; sc++) wmma::fill_fragment(acc[sr][sc], 0.f);

#pragma unroll 1
    for (int kc = 0; kc < 128; kc += 64) {
        if (kc) {
            __syncthreads();
            for (int i = tid; i < 1024; i += 256) {
                int r = i >> 4, g = i & 15;
                cp_async16(whi_b + (uint32_t)(r * 272 + g * 16), wbase + EW1A_HI + (kc + r) * 128 + g * 8);
                cp_async16(wlo_b + (uint32_t)(r * 272 + g * 16), wbase + EW1A_LO + (kc + r) * 128 + g * 8);
            }
            cp_commit_wait();
            __syncthreads();
        }
        for (int kk = 0; kk < 64; kk += 16) {
            AF ah[2], al[2];
#pragma unroll
            for (int sr = 0; sr < 2; sr++) {
                wmma::load_matrix_sync(ah[sr], Ahi + (rt * 32 + sr * 16) * 136 + kc + kk, 136);
                wmma::load_matrix_sync(al[sr], Alo + (rt * 32 + sr * 16) * 136 + kc + kk, 136);
            }
#pragma unroll
            for (int sc = 0; sc < 2; sc++) {
                BF bh, bl;
                wmma::load_matrix_sync(bh, Whi + kk * 136 + cg * 32 + sc * 16, 136);
                wmma::load_matrix_sync(bl, Wlo + kk * 136 + cg * 32 + sc * 16, 136);
#pragma unroll
                for (int sr = 0; sr < 2; sr++) {
                    wmma::mma_sync(acc[sr][sc], ah[sr], bh, acc[sr][sc]);
                    wmma::mma_sync(acc[sr][sc], ah[sr], bl, acc[sr][sc]);
                    wmma::mma_sync(acc[sr][sc], al[sr], bh, acc[sr][sc]);
                }
            }
        }
    }
    __syncthreads();
#pragma unroll
    for (int sr = 0; sr < 2; sr++)
#pragma unroll
        for (int sc = 0; sc < 2; sc++)
            wmma::store_matrix_sync(Cf + (rt * 32 + sr * 16) * 132 + cg * 32 + sc * 16,
                                    acc[sr][sc], 132, wmma::mem_row_major);
    __syncthreads();

    for (int i = tid; i < 2048; i += 256) {
        int row = i >> 5, c4 = i & 31;
        int s = ssh[row], r = rsh[row];
        float4 c = *(float4*)(Cf + row * 132 + c4 * 4);
        float4 zb = ((const float4*)(g_z + (size_t)s * 256))[c4];
        float4 zc = ((const float4*)(g_z + (size_t)r * 256 + 128))[c4];
        float4 b = ((const float4*)B1s)[c4];
        float4 v = make_float4(
            fmaxf(c.x + zb.x + zc.x + b.x, 0.f),
            fmaxf(c.y + zb.y + zc.y + b.y, 0.f),
            fmaxf(c.z + zb.z + zc.z + b.z, 0.f),
            fmaxf(c.w + zb.w + zc.w + b.w, 0.f));
        split_store4(v, Ahi + row * 136 + c4 * 4, Alo + row * 136 + c4 * 4);
    }
    __syncthreads();

#pragma unroll
    for (int sr = 0; sr < 2; sr++)
#pragma unroll
        for (int sc = 0; sc < 2; sc++) wmma::fill_fragment(acc[sr][sc], 0.f);
#pragma unroll 1
    for (int kc = 0; kc < 128; kc += 64) {
        for (int i = tid; i < 1024; i += 256) {
            int r = i >> 4, g = i & 15;
            cp_async16(whi_b + (uint32_t)(r * 272 + g * 16), wbase + EW2_HI + (kc + r) * 128 + g * 8);
            cp_async16(wlo_b + (uint32_t)(r * 272 + g * 16), wbase + EW2_LO + (kc + r) * 128 + g * 8);
        }
        cp_commit_wait();
        __syncthreads();
        for (int kk = 0; kk < 64; kk += 16) {
            AF ah[2], al[2];
#pragma unroll
            for (int sr = 0; sr < 2; sr++) {
                wmma::load_matrix_sync(ah[sr], Ahi + (rt * 32 + sr * 16) * 136 + kc + kk, 136);
                wmma::load_matrix_sync(al[sr], Alo + (rt * 32 + sr * 16) * 136 + kc + kk, 136);
            }
#pragma unroll
            for (int sc = 0; sc < 2; sc++) {
                BF bh, bl;
                wmma::load_matrix_sync(bh, Whi + kk * 136 + cg * 32 + sc * 16, 136);
                wmma::load_matrix_sync(bl, Wlo + kk * 136 + cg * 32 + sc * 16, 136);
#pragma unroll
                for (int sr = 0; sr < 2; sr++) {
                    wmma::mma_sync(acc[sr][sc], ah[sr], bh, acc[sr][sc]);
                    wmma::mma_sync(acc[sr][sc], ah[sr], bl, acc[sr][sc]);
                    wmma::mma_sync(acc[sr][sc], al[sr], bh, acc[sr][sc]);
                }
            }
        }
        __syncthreads();
    }
#pragma unroll
    for (int sr = 0; sr < 2; sr++)
#pragma unroll
        for (int sc = 0; sc < 2; sc++)
            wmma::store_matrix_sync(Cf + (rt * 32 + sr * 16) * 132 + cg * 32 + sc * 16,
                                    acc[sr][sc], 132, wmma::mem_row_major);
    __syncthreads();

    for (int i = tid; i < 2048; i += 256) {
        int row = i >> 5, c4 = i & 31;
        __nv_bfloat16* hp = elbase + row * 128 + c4 * 4;
        float4 oldv = join4(hp, hp + 8192);
        float4 c = *(float4*)(Cf + row * 132 + c4 * 4);
        float4 b = ((const float4*)B2s)[c4];
        float4 nv = make_float4(oldv.x + c.x + b.x, oldv.y + c.y + b.y,
                                oldv.z + c.z + b.z, oldv.w + c.w + b.w);
        split_store4(nv, hp, hp + 8192);
        red_add_v4(g_agg + (size_t)rsh[row] * LL + c4 * 4, nv);
    }
}

// ---------------------------------------------------------------- node step (+fused projection), 3 blocks/SM
#define N2_AHI 0
#define N2_ALO 17408
#define N2_W   34816
#define N2_WLO 52224
#define N2_SMEM 69632

__global__ void __launch_bounds__(256, 3) k_node_step(
    int step, const float* __restrict__ B1, const float* __restrict__ B2, int do_proj)
{
    extern __shared__ char smc[];
    __nv_bfloat16* Ahi = (__nv_bfloat16*)(smc + N2_AHI);
    __nv_bfloat16* Alo = (__nv_bfloat16*)(smc + N2_ALO);
    __nv_bfloat16* Whi = (__nv_bfloat16*)(smc + N2_W);
    __nv_bfloat16* Wlo = (__nv_bfloat16*)(smc + N2_WLO);
    float*         Cf  = (float*)(smc + N2_W);
    const int tid = threadIdx.x;
    const int w = tid >> 5, rt = w >> 1, cg = w & 1;
    const int nbase = blockIdx.x * 64;
    const bool full = (nbase + 64 <= NN);
    const __nv_bfloat16* wbase = g_ws + (size_t)step * STEP_W;
    const uint32_t whi_b = smem_u32(Whi), wlo_b = smem_u32(Wlo);

    CF acc[4];
#pragma unroll
    for (int f = 0; f < 4; f++) wmma::fill_fragment(acc[f], 0.f);

    // ---- GEMM1: X[64x256] @ NW1, X staged per 64-K chunk (single-use)
#pragma unroll 1
    for (int kc = 0; kc < 256; kc += 64) {
        __syncthreads();
        for (int i = tid; i < 1024; i += 256) {
            int row = i >> 4, g = i & 15;
            int n = nbase + row;
            float4 v = make_float4(0.f, 0.f, 0.f, 0.f);
            if (n < NN) {
                if (kc < 128) {
                    v = ((const float4*)(g_nl + (size_t)n * LL))[(kc >> 2) + g];
                } else {
                    float4* ap = (float4*)(g_agg + (size_t)n * LL) + (((kc - 128) >> 2) + g);
                    v = *ap;
                    *ap = make_float4(0.f, 0.f, 0.f, 0.f);
                }
            }
            split_store4(v, Ahi + row * 136 + g * 4, Alo + row * 136 + g * 4);
        }
        for (int i = tid; i < 1024; i += 256) {
            int rr = i >> 4, g = i & 15;
            cp_async16(whi_b + (uint32_t)(rr * 272 + g * 16), wbase + NW1_HI + (kc + rr) * 128 + g * 8);
            cp_async16(wlo_b + (uint32_t)(rr * 272 + g * 16), wbase + NW1_LO + (kc + rr) * 128 + g * 8);
        }
        cp_commit_wait();
        __syncthreads();
        for (int kk = 0; kk < 64; kk += 16) {
            AF ah, al;
            wmma::load_matrix_sync(ah, Ahi + rt * 16 * 136 + kk, 136);
            wmma::load_matrix_sync(al, Alo + rt * 16 * 136 + kk, 136);
#pragma unroll
            for (int f = 0; f < 4; f++) {
                BF bh, bl;
                wmma::load_matrix_sync(bh, Whi + kk * 136 + cg * 64 + f * 16, 136);
                wmma::load_matrix_sync(bl, Wlo + kk * 136 + cg * 64 + f * 16, 136);
                wmma::mma_sync(acc[f], ah, bh, acc[f]);
                wmma::mma_sync(acc[f], ah, bl, acc[f]);
                wmma::mma_sync(acc[f], al, bh, acc[f]);
            }
        }
    }
    __syncthreads();
#pragma unroll
    for (int f = 0; f < 4; f++)
        wmma::store_matrix_sync(Cf + rt * 16 * 132 + cg * 64 + f * 16, acc[f], 132, wmma::mem_row_major);
    __syncthreads();
    for (int i = tid; i < 64 * 32; i += 256) {
        int row = i >> 5, c4 = i & 31;
        float4 v = *(float4*)(Cf + row * 132 + c4 * 4);
        float4 bb = ((const float4*)B1)[c4];
        v.x = fmaxf(v.x + bb.x, 0.f);
        v.y = fmaxf(v.y + bb.y, 0.f);
        v.z = fmaxf(v.z + bb.z, 0.f);
        v.w = fmaxf(v.w + bb.w, 0.f);
        split_store4(v, Ahi + row * 136 + c4 * 4, Alo + row * 136 + c4 * 4);
    }
    __syncthreads();

    // ---- GEMM2: H[64x128] @ NW2, K chunked
#pragma unroll
    for (int f = 0; f < 4; f++) wmma::fill_fragment(acc[f], 0.f);
#pragma unroll 1
    for (int kc = 0; kc < 128; kc += 64) {
        for (int i = tid; i < 1024; i += 256) {
            int rr = i >> 4, g = i & 15;
            cp_async16(whi_b + (uint32_t)(rr * 272 + g * 16), wbase + NW2_HI + (kc + rr) * 128 + g * 8);
            cp_async16(wlo_b + (uint32_t)(rr * 272 + g * 16), wbase + NW2_LO + (kc + rr) * 128 + g * 8);
        }
        cp_commit_wait();
        __syncthreads();
        for (int kk = 0; kk < 64; kk += 16) {
            AF ah, al;
            wmma::load_matrix_sync(ah, Ahi + rt * 16 * 136 + kc + kk, 136);
            wmma::load_matrix_sync(al, Alo + rt * 16 * 136 + kc + kk, 136);
#pragma unroll
            for (int f = 0; f < 4; f++) {
                BF bh, bl;
                wmma::load_matrix_sync(bh, Whi + kk * 136 + cg * 64 + f * 16, 136);
                wmma::load_matrix_sync(bl, Wlo + kk * 136 + cg * 64 + f * 16, 136);
                wmma::mma_sync(acc[f], ah, bh, acc[f]);
                wmma::mma_sync(acc[f], ah, bl, acc[f]);
                wmma::mma_sync(acc[f], al, bh, acc[f]);
            }
        }
        __syncthreads();
    }
#pragma unroll
    for (int f = 0; f < 4; f++)
        wmma::store_matrix_sync(Cf + rt * 16 * 132 + cg * 64 + f * 16, acc[f], 132, wmma::mem_row_major);
    __syncthreads();

    for (int i = tid; i < 64 * 32; i += 256) {
        int row = i >> 5, c4 = i & 31;
        int n = nbase + row;
        float4 nv = make_float4(0.f, 0.f, 0.f, 0.f);
        if (n < NN) {
            float4 oldv = ((const float4*)(g_nl + (size_t)n * LL))[c4];
            float4 c2 = *(float4*)(Cf + row * 132 + c4 * 4);
            float4 bb = ((const float4*)B2)[c4];
            nv = make_float4(oldv.x + c2.x + bb.x, oldv.y + c2.y + bb.y,
                             oldv.z + c2.z + bb.z, oldv.w + c2.w + bb.w);
            ((float4*)(g_nl + (size_t)n * LL))[c4] = nv;
        }
        if (do_proj)
            split_store4(nv, Ahi + row * 136 + c4 * 4, Alo + row * 136 + c4 * 4);
    }

    if (do_proj) {
        const __nv_bfloat16* wn = g_ws + (size_t)(step + 1) * STEP_W;
#pragma unroll 1
        for (int half = 0; half < 2; ++half) {
#pragma unroll
            for (int f = 0; f < 4; f++) wmma::fill_fragment(acc[f], 0.f);
#pragma unroll 1
            for (int kc = 0; kc < 128; kc += 64) {
                __syncthreads();
                for (int i = tid; i < 1024; i += 256) {
                    int rr = i >> 4, g = i & 15;
                    cp_async16(whi_b + (uint32_t)(rr * 272 + g * 16),
                               wn + PRJ_HI + (size_t)(kc + rr) * 256 + half * 128 + g * 8);
                    cp_async16(wlo_b + (uint32_t)(rr * 272 + g * 16),
                               wn + PRJ_LO + (size_t)(kc + rr) * 256 + half * 128 + g * 8);
                }
                cp_commit_wait();
                __syncthreads();
                for (int kk = 0; kk < 64; kk += 16) {
                    AF ah, al;
                    wmma::load_matrix_sync(ah, Ahi + rt * 16 * 136 + kc + kk, 136);
                    wmma::load_matrix_sync(al, Alo + rt * 16 * 136 + kc + kk, 136);
#pragma unroll
                    for (int f = 0; f < 4; f++) {
                        BF bh, bl;
                        wmma::load_matrix_sync(bh, Whi + kk * 136 + cg * 64 + f * 16, 136);
                        wmma::load_matrix_sync(bl, Wlo + kk * 136 + cg * 64 + f * 16, 136);
                        wmma::mma_sync(acc[f], ah, bh, acc[f]);
                        wmma::mma_sync(acc[f], ah, bl, acc[f]);
                        wmma::mma_sync(acc[f], al, bh, acc[f]);
                    }
                }
            }
            if (full) {
#pragma unroll
                for (int f = 0; f < 4; f++)
                    wmma::store_matrix_sync(g_z + (size_t)(nbase + rt * 16) * 256 + half * 128 + cg * 64 + f * 16,
                                            acc[f], 256, wmma::mem_row_major);
            } else {
                __syncthreads();
#pragma unroll
                for (int f = 0; f < 4; f++)
                    wmma::store_matrix_sync(Cf + rt * 16 * 132 + cg * 64 + f * 16, acc[f], 132, wmma::mem_row_major);
                __syncthreads();
                for (int i = tid; i < 64 * 32; i += 256) {
                    int row = i >> 5, c4 = i & 31;
                    int n = nbase + row;
                    if (n < NN)
                        ((float4*)(g_z + (size_t)n * 256 + half * 128))[c4] =
                            *(float4*)(Cf + row * 132 + c4 * 4);
                }
            }
        }
    }
}

// ---------------------------------------------------------------- decoder (SIMT fp32; exact)
__global__ void __launch_bounds__(128) k_decoder(
    const float* __restrict__ W1, const float* __restrict__ B1,
    const float* __restrict__ W2, const float* __restrict__ B2,
    float* __restrict__ out)
{
    __shared__ float Xs[32][128];
    __shared__ float H[32][128];
    const int tid = threadIdx.x;
    const int nbase = blockIdx.x * 32;

    for (int i = tid; i < 32 * 32; i += 128) {
        int n = i >> 5, c4 = i & 31;
        int gn = nbase + n;
        float4 v = make_float4(0.f, 0.f, 0.f, 0.f);
        if (gn < NN) v = ((const float4*)(g_nl + (size_t)gn * LL))[c4];
        ((float4*)Xs[n])[c4] = v;
    }
    __syncthreads();

    const int j = tid;
#pragma unroll 1
    for (int n = 0; n < 32; n++) {
        float acc = B1[j];
#pragma unroll 8
        for (int k = 0; k < 128; k++) acc += Xs[n][k] * W1[k * 128 + j];
        H[n][j] = fmaxf(acc, 0.f);
    }
    __syncthreads();

    if (tid < 96) {
        int n = tid / 3, d = tid % 3;
        int gn = nbase + n;
        float acc = B2[d];
#pragma unroll 8
        for (int k = 0; k < 128; k++) acc += H[n][k] * W2[k * 3 + d];
        if (gn < NN) out[gn * 3 + d] = acc;
    }
}

// ---------------------------------------------------------------- launch
extern "C" void kernel_launch(void* const* d_in, const int* in_sizes, int n_in,
                              void* d_out, int out_size)
{
    const float* pos   = (const float*)d_in[0];
    const float* vel   = (const float*)d_in[1];
    const int*   rid   = (const int*)d_in[2];
    const int*   snd   = (const int*)d_in[3];
    const int*   rcv   = (const int*)d_in[4];
    const float* remb  = (const float*)d_in[5];
    const float* ne_w1 = (const float*)d_in[6];
    const float* ne_b1 = (const float*)d_in[7];
    const float* ne_w2 = (const float*)d_in[8];
    const float* ne_b2 = (const float*)d_in[9];
    const float* ee_w1 = (const float*)d_in[10];
    const float* ee_b1 = (const float*)d_in[11];
    const float* ee_w2 = (const float*)d_in[12];
    const float* ee_b2 = (const float*)d_in[13];
    const float* pe_w1 = (const float*)d_in[14];
    const float* pe_b1 = (const float*)d_in[15];
    const float* pe_w2 = (const float*)d_in[16];
    const float* pe_b2 = (const float*)d_in[17];
    const float* pn_w1 = (const float*)d_in[18];
    const float* pn_b1 = (const float*)d_in[19];
    const float* pn_w2 = (const float*)d_in[20];
    const float* pn_b2 = (const float*)d_in[21];
    const float* de_w1 = (const float*)d_in[22];
    const float* de_b1 = (const float*)d_in[23];
    const float* de_w2 = (const float*)d_in[24];
    const float* de_b2 = (const float*)d_in[25];

    cudaFuncSetAttribute(k_edge_step, cudaFuncAttributeMaxDynamicSharedMemorySize, ES_SMEM);
    cudaFuncSetAttribute(k_node_step, cudaFuncAttributeMaxDynamicSharedMemorySize, N2_SMEM);
    cudaFuncSetAttribute(k_node_enc_proj, cudaFuncAttributeMaxDynamicSharedMemorySize, NEP_SMEM);
    cudaFuncSetAttribute(k_edge_enc2, cudaFuncAttributeMaxDynamicSharedMemorySize, EN_SMEM);

    k_setup<<<4740, 256>>>(pe_w1, pe_w2, pn_w1, pn_w2, ee_w2);
    k_degcenter<<<3229, 256>>>(rcv, pos);
    k_node_enc_proj<<<NB_ENC, 256, NEP_SMEM>>>(pos, vel, rid, remb, ne_w1, ne_b1, ne_w2, ne_b2);
    k_edge_enc2<<<EB_ENC, 256, EN_SMEM>>>(pos, vel, rid, snd, rcv, ee_w1, ee_b1, ee_b2);

    for (int st = 0; st < NSTEPS; st++) {
        k_edge_step<<<EE / 64, 256, ES_SMEM>>>(
            snd, rcv, st, pe_b1 + (size_t)st * 128, pe_b2 + (size_t)st * 128);
        k_node_step<<<(NN + 63) / 64, 256, N2_SMEM>>>(
            st, pn_b1 + (size_t)st * 128, pn_b2 + (size_t)st * 128, (st < NSTEPS - 1) ? 1 : 0);
    }

    k_decoder<<<(NN + 31) / 32, 128>>>(de_w1, de_b1, de_w2, de_b2, (float*)d_out);
}

// round 14
// speedup vs baseline: 1.4248x; 1.0236x over previous
#include <cuda_runtime.h>
#include <cuda_bf16.h>
#include <mma.h>
#include <cstdint>

using namespace nvcuda;

#define NN 50000
#define EE 800000
#define LL 128
#define NSTEPS 10
#define NB_ENC 782          // ceil(NN/64)
#define EB_ENC 12500        // EE/64

// ---- scratch (device globals; no allocations allowed) ----
__device__ float g_nl[(size_t)NN * LL];
// el stored as bf16 hi/lo planes, tile-major: [tile(64 edges)][hi 64x128][lo 64x128]
__device__ __nv_bfloat16 g_el[(size_t)EE * 256];
__device__ float g_agg[(size_t)NN * LL];
__device__ float g_z[(size_t)NN * 256];
__device__ float g_deg[NN];
__device__ float g_center[3];

#define EW1A_HI 0
#define EW1A_LO 16384
#define EW2_HI  32768
#define EW2_LO  49152
#define PRJ_HI  65536
#define PRJ_LO  98304
#define NW1_HI  131072
#define NW1_LO  163840
#define NW2_HI  196608
#define NW2_LO  212992
#define STEP_W  229376
__device__ __nv_bfloat16 g_ws[(size_t)NSTEPS * STEP_W];
// encoder W2 planes: hi [0,16384), lo [16384,32768)
__device__ __nv_bfloat16 g_we2[32768];

typedef wmma::fragment<wmma::matrix_a, 16, 16, 16, __nv_bfloat16, wmma::row_major> AF;
typedef wmma::fragment<wmma::matrix_b, 16, 16, 16, __nv_bfloat16, wmma::row_major> BF;
typedef wmma::fragment<wmma::accumulator, 16, 16, 16, float> CF;

__device__ __forceinline__ uint32_t smem_u32(const void* p) {
    uint32_t a;
    asm("{ .reg .u64 t; cvta.to.shared.u64 t, %1; cvt.u32.u64 %0, t; }" : "=r"(a) : "l"(p));
    return a;
}
// .cg: bypass L1 allocation (single-use staging data)
__device__ __forceinline__ void cp_async16(uint32_t dst, const void* src) {
    asm volatile("cp.async.cg.shared.global [%0], [%1], 16;" :: "r"(dst), "l"(src) : "memory");
}
__device__ __forceinline__ void cp_commit() {
    asm volatile("cp.async.commit_group;" ::: "memory");
}
__device__ __forceinline__ void cp_wait0() {
    asm volatile("cp.async.wait_group 0;" ::: "memory");
}
__device__ __forceinline__ void cp_wait1() {
    asm volatile("cp.async.wait_group 1;" ::: "memory");
}
__device__ __forceinline__ void cp_commit_wait() {
    cp_commit();
    cp_wait0();
}

__device__ __forceinline__ void split_store4(float4 v, __nv_bfloat16* hip, __nv_bfloat16* lop) {
    __nv_bfloat162 h0 = __floats2bfloat162_rn(v.x, v.y);
    __nv_bfloat162 h1 = __floats2bfloat162_rn(v.z, v.w);
    float2 f0 = __bfloat1622float2(h0);
    float2 f1 = __bfloat1622float2(h1);
    __nv_bfloat162 l0 = __floats2bfloat162_rn(v.x - f0.x, v.y - f0.y);
    __nv_bfloat162 l1 = __floats2bfloat162_rn(v.z - f1.x, v.w - f1.y);
    *(__nv_bfloat162*)(hip)     = h0;
    *(__nv_bfloat162*)(hip + 2) = h1;
    *(__nv_bfloat162*)(lop)     = l0;
    *(__nv_bfloat162*)(lop + 2) = l1;
}

__device__ __forceinline__ float4 join4(const __nv_bfloat16* hip, const __nv_bfloat16* lop) {
    float2 a = __bfloat1622float2(*(const __nv_bfloat162*)hip);
    float2 b = __bfloat1622float2(*(const __nv_bfloat162*)(hip + 2));
    float2 c = __bfloat1622float2(*(const __nv_bfloat162*)lop);
    float2 d = __bfloat1622float2(*(const __nv_bfloat162*)(lop + 2));
    return make_float4(a.x + c.x, a.y + c.y, b.x + d.x, b.y + d.y);
}

__device__ __forceinline__ void red_add_v4(float* dst, float4 v) {
    asm volatile("red.global.add.v4.f32 [%0], {%1,%2,%3,%4};"
                 :: "l"(dst), "f"(v.x), "f"(v.y), "f"(v.z), "f"(v.w) : "memory");
}

// ---------------------------------------------------------------- launch 0: weight prep + init
__global__ void __launch_bounds__(256) k_setup(
    const float* __restrict__ pe_w1, const float* __restrict__ pe_w2,
    const float* __restrict__ pn_w1, const float* __restrict__ pn_w2,
    const float* __restrict__ ee_w2)
{
    if (blockIdx.x < 4480) {
        int idx = blockIdx.x * 256 + threadIdx.x;
        int s = idx / 114688;
        int e = idx % 114688;
        float v;
        size_t dhi, dlo;
        if (e < 16384) {
            v = pe_w1[(size_t)s * 384 * 128 + e];
            dhi = EW1A_HI + e; dlo = EW1A_LO + e;
        } else if (e < 32768) {
            int e2 = e - 16384;
            v = pe_w2[(size_t)s * 128 * 128 + e2];
            dhi = EW2_HI + e2; dlo = EW2_LO + e2;
        } else if (e < 65536) {
            int e2 = e - 32768;
            int k = e2 >> 8, n = e2 & 255;
            int srcrow = 128 + (n >> 7) * 128 + k;
            v = pe_w1[(size_t)s * 384 * 128 + (size_t)srcrow * 128 + (n & 127)];
            dhi = PRJ_HI + e2; dlo = PRJ_LO + e2;
        } else if (e < 98304) {
            int e2 = e - 65536;
            v = pn_w1[(size_t)s * 256 * 128 + e2];
            dhi = NW1_HI + e2; dlo = NW1_LO + e2;
        } else {
            int e2 = e - 98304;
            v = pn_w2[(size_t)s * 128 * 128 + e2];
            dhi = NW2_HI + e2; dlo = NW2_LO + e2;
        }
        __nv_bfloat16 h = __float2bfloat16(v);
        g_ws[(size_t)s * STEP_W + dhi] = h;
        g_ws[(size_t)s * STEP_W + dlo] = __float2bfloat16(v - __bfloat162float(h));
    } else if (blockIdx.x < 4544) {
        int i = (blockIdx.x - 4480) * 256 + threadIdx.x;   // < 16384
        float v = ee_w2[i];
        __nv_bfloat16 h = __float2bfloat16(v);
        g_we2[i] = h;
        g_we2[16384 + i] = __float2bfloat16(v - __bfloat162float(h));
    } else {
        int i = (blockIdx.x - 4544) * 256 + threadIdx.x;
        if (i < NN) g_deg[i] = 0.f;
        if (i < 3) g_center[i] = 0.f;
    }
}

// ---------------------------------------------------------------- launch 1: degree + center
__global__ void __launch_bounds__(256) k_degcenter(
    const int* __restrict__ rcv, const float* __restrict__ pos)
{
    if (blockIdx.x < 3125) {
        int i = blockIdx.x * 256 + threadIdx.x;
        if (i < EE) atomicAdd(&g_deg[rcv[i]], 1.f);
    } else {
        float sx = 0.f, sy = 0.f, sz = 0.f;
        for (int i = (blockIdx.x - 3125) * 256 + threadIdx.x; i < NN; i += 104 * 256) {
            sx += pos[i * 3 + 0];
            sy += pos[i * 3 + 1];
            sz += pos[i * 3 + 2];
        }
#pragma unroll
        for (int o = 16; o > 0; o >>= 1) {
            sx += __shfl_down_sync(0xffffffffu, sx, o);
            sy += __shfl_down_sync(0xffffffffu, sy, o);
            sz += __shfl_down_sync(0xffffffffu, sz, o);
        }
        if ((threadIdx.x & 31) == 0) {
            atomicAdd(&g_center[0], sx);
            atomicAdd(&g_center[1], sy);
            atomicAdd(&g_center[2], sz);
        }
    }
}

// ---------------------------------------------------------------- launch 2: node encoder + step-0 projection
#define NEP_SMEM 110592

__global__ void __launch_bounds__(256, 2) k_node_enc_proj(
    const float* __restrict__ pos, const float* __restrict__ vel,
    const int* __restrict__ rid, const float* __restrict__ remb,
    const float* __restrict__ nW1, const float* __restrict__ nB1,
    const float* __restrict__ nW2, const float* __restrict__ nB2)
{
    extern __shared__ char smc[];
    const int tid = threadIdx.x;
    float* F = (float*)(smc + 0);
    float* H = (float*)(smc + 8192);
    __nv_bfloat16* Ahi = (__nv_bfloat16*)(smc + 40960);
    __nv_bfloat16* Alo = (__nv_bfloat16*)(smc + 58368);
    __nv_bfloat16* Wch = (__nv_bfloat16*)(smc + 75776);
    __nv_bfloat16* Wcl = (__nv_bfloat16*)(smc + 93184);
    const int nbase = blockIdx.x * 64;
    const float inv = 1.f / (float)NN;
    const float cx = g_center[0] * inv, cy = g_center[1] * inv, cz = g_center[2] * inv;

    for (int i = tid; i < 64 * 23; i += 256) {
        int n = i / 23, k = i % 23;
        int gn = nbase + n;
        float v = 0.f;
        if (gn < NN) {
            if (k < 3) v = vel[gn * 3 + k];
            else if (k < 6) v = pos[gn * 3 + (k - 3)] - ((k == 3) ? cx : (k == 4) ? cy : cz);
            else if (k == 6) v = g_deg[gn];
            else v = remb[rid[gn] * 16 + (k - 7)];
        }
        F[n * 24 + k] = v;
    }
    __syncthreads();

    const int j = tid & 127;
    for (int n = tid >> 7; n < 64; n += 2) {
        float acc = nB1[j];
#pragma unroll
        for (int k = 0; k < 23; k++) acc += F[n * 24 + k] * nW1[k * 128 + j];
        H[n * 128 + j] = fmaxf(acc, 0.f);
    }
    __syncthreads();
    for (int n = tid >> 7; n < 64; n += 2) {
        int gn = nbase + n;
        float acc = nB2[j];
#pragma unroll 8
        for (int k = 0; k < 128; k++) acc += H[n * 128 + k] * nW2[k * 128 + j];
        float v = (gn < NN) ? acc : 0.f;
        if (gn < NN) g_nl[(size_t)gn * LL + j] = v;
        __nv_bfloat16 h = __float2bfloat16(v);
        Ahi[n * 136 + j] = h;
        Alo[n * 136 + j] = __float2bfloat16(v - __bfloat162float(h));
    }
    __syncthreads();

    // projection Z(0) = nl @ PRJ(0)
    const int w = tid >> 5, rt = w >> 1, cg = w & 1;
    const bool full = (nbase + 64 <= NN);
    const __nv_bfloat16* wn = g_ws;
    CF acc[4];
#pragma unroll 1
    for (int half = 0; half < 2; ++half) {
#pragma unroll
        for (int f = 0; f < 4; f++) wmma::fill_fragment(acc[f], 0.f);
        for (int kc = 0; kc < 128; kc += 64) {
            __syncthreads();
            for (int i = tid; i < 1024; i += 256) {
                int rr = i >> 4, g = i & 15;
                *(float4*)(Wch + rr * 136 + g * 8) =
                    ((const float4*)(wn + PRJ_HI + (size_t)(kc + rr) * 256 + half * 128))[g];
                *(float4*)(Wcl + rr * 136 + g * 8) =
                    ((const float4*)(wn + PRJ_LO + (size_t)(kc + rr) * 256 + half * 128))[g];
            }
            __syncthreads();
            for (int kk = 0; kk < 64; kk += 16) {
                AF ah, al;
                wmma::load_matrix_sync(ah, Ahi + rt * 16 * 136 + kc + kk, 136);
                wmma::load_matrix_sync(al, Alo + rt * 16 * 136 + kc + kk, 136);
#pragma unroll
                for (int f = 0; f < 4; f++) {
                    BF bh, bl;
                    wmma::load_matrix_sync(bh, Wch + kk * 136 + cg * 64 + f * 16, 136);
                    wmma::load_matrix_sync(bl, Wcl + kk * 136 + cg * 64 + f * 16, 136);
                    wmma::mma_sync(acc[f], ah, bh, acc[f]);
                    wmma::mma_sync(acc[f], ah, bl, acc[f]);
                    wmma::mma_sync(acc[f], al, bh, acc[f]);
                }
            }
        }
        if (full) {
#pragma unroll
            for (int f = 0; f < 4; f++)
                wmma::store_matrix_sync(g_z + (size_t)(nbase + rt * 16) * 256 + half * 128 + cg * 64 + f * 16,
                                        acc[f], 256, wmma::mem_row_major);
        } else {
            float* Cf = (float*)(smc + 75776);   // dead W region; restaged next half
            __syncthreads();
#pragma unroll
            for (int f = 0; f < 4; f++)
                wmma::store_matrix_sync(Cf + rt * 16 * 132 + cg * 64 + f * 16, acc[f], 132, wmma::mem_row_major);
            __syncthreads();
            for (int i = tid; i < 64 * 32; i += 256) {
                int row = i >> 5, c4 = i & 31;
                int n = nbase + row;
                if (n < NN)
                    ((float4*)(g_z + (size_t)n * 256 + half * 128))[c4] =
                        *(float4*)(Cf + row * 132 + c4 * 4);
            }
        }
    }
}

// ---------------------------------------------------------------- launch 3: edge encoder (3 blocks/SM)
#define EN_F   0        // 64 x 12 fp32
#define EN_HHI 4096     // 64 x 136 bf16
#define EN_HLO 21504
#define EN_W   38912    // 64 x 136 bf16 (K-chunk)
#define EN_WLO 56320
#define EN_SMEM 73728

__global__ void __launch_bounds__(256, 3) k_edge_enc2(
    const float* __restrict__ pos, const float* __restrict__ vel,
    const int* __restrict__ rid,
    const int* __restrict__ snd, const int* __restrict__ rcv,
    const float* __restrict__ eW1, const float* __restrict__ eB1,
    const float* __restrict__ eB2)
{
    extern __shared__ char smc[];
    float*         F   = (float*)(smc + EN_F);
    __nv_bfloat16* Hhi = (__nv_bfloat16*)(smc + EN_HHI);
    __nv_bfloat16* Hlo = (__nv_bfloat16*)(smc + EN_HLO);
    __nv_bfloat16* Whi = (__nv_bfloat16*)(smc + EN_W);
    __nv_bfloat16* Wlo = (__nv_bfloat16*)(smc + EN_WLO);
    float*         Cf  = (float*)(smc + EN_W);    // aliases W
    const int tid = threadIdx.x;
    const int w = tid >> 5, rt = w & 1, cg = w >> 1;   // 2 x 4 tiling
    const int tile = blockIdx.x;
    const int ebase = tile * 64;
    const uint32_t whi_b = smem_u32(Whi), wlo_b = smem_u32(Wlo);

    for (int i = tid; i < 1024; i += 256) {
        int r = i >> 4, g = i & 15;
        cp_async16(whi_b + (uint32_t)(r * 272 + g * 16), g_we2 + r * 128 + g * 8);
        cp_async16(wlo_b + (uint32_t)(r * 272 + g * 16), g_we2 + 16384 + r * 128 + g * 8);
    }
    cp_commit();
    if (tid < 64) {
        int e = ebase + tid;
        int s = snd[e], r = rcv[e];
        float rp0 = pos[s * 3 + 0] - pos[r * 3 + 0];
        float rp1 = pos[s * 3 + 1] - pos[r * 3 + 1];
        float rp2 = pos[s * 3 + 2] - pos[r * 3 + 2];
        float rv0 = vel[s * 3 + 0] - vel[r * 3 + 0];
        float rv1 = vel[s * 3 + 1] - vel[r * 3 + 1];
        float rv2 = vel[s * 3 + 2] - vel[r * 3 + 2];
        float sq = rp0 * rp0 + rp1 * rp1 + rp2 * rp2;
        float dist = sqrtf(sq);
        float same = (rid[s] == rid[r]) ? 1.f : 0.f;
        float* f = F + tid * 12;
        f[0] = rp0; f[1] = rp1; f[2] = rp2;
        f[3] = rv0; f[4] = rv1; f[5] = rv2;
        f[6] = dist; f[7] = sq; f[8] = same;
    }
    __syncthreads();

    {
        const int j = tid & 127;
        for (int n = tid >> 7; n < 64; n += 2) {
            float acc = eB1[j];
#pragma unroll
            for (int k = 0; k < 9; k++) acc += F[n * 12 + k] * eW1[k * 128 + j];
            acc = fmaxf(acc, 0.f);
            __nv_bfloat16 h = __float2bfloat16(acc);
            Hhi[n * 136 + j] = h;
            Hlo[n * 136 + j] = __float2bfloat16(acc - __bfloat162float(h));
        }
    }
    cp_wait0();
    __syncthreads();

    CF acc[2][2];
#pragma unroll
    for (int sr = 0; sr < 2; sr++)
#pragma unroll
        for (int sc = 0; sc < 2; sc++) wmma::fill_fragment(acc[sr][sc], 0.f);
#pragma unroll 1
    for (int kc = 0; kc < 128; kc += 64) {
        if (kc) {
            __syncthreads();
            for (int i = tid; i < 1024; i += 256) {
                int r = i >> 4, g = i & 15;
                cp_async16(whi_b + (uint32_t)(r * 272 + g * 16), g_we2 + (kc + r) * 128 + g * 8);
                cp_async16(wlo_b + (uint32_t)(r * 272 + g * 16), g_we2 + 16384 + (kc + r) * 128 + g * 8);
            }
            cp_commit_wait();
            __syncthreads();
        }
        for (int kk = 0; kk < 64; kk += 16) {
            AF ah[2], al[2];
#pragma unroll
            for (int sr = 0; sr < 2; sr++) {
                wmma::load_matrix_sync(ah[sr], Hhi + (rt * 32 + sr * 16) * 136 + kc + kk, 136);
                wmma::load_matrix_sync(al[sr], Hlo + (rt * 32 + sr * 16) * 136 + kc + kk, 136);
            }
#pragma unroll
            for (int sc = 0; sc < 2; sc++) {
                BF bh, bl;
                wmma::load_matrix_sync(bh, Whi + kk * 136 + cg * 32 + sc * 16, 136);
                wmma::load_matrix_sync(bl, Wlo + kk * 136 + cg * 32 + sc * 16, 136);
#pragma unroll
                for (int sr = 0; sr < 2; sr++) {
                    wmma::mma_sync(acc[sr][sc], ah[sr], bh, acc[sr][sc]);
                    wmma::mma_sync(acc[sr][sc], ah[sr], bl, acc[sr][sc]);
                    wmma::mma_sync(acc[sr][sc], al[sr], bh, acc[sr][sc]);
                }
            }
        }
    }
    __syncthreads();
#pragma unroll
    for (int sr = 0; sr < 2; sr++)
#pragma unroll
        for (int sc = 0; sc < 2; sc++)
            wmma::store_matrix_sync(Cf + (rt * 32 + sr * 16) * 132 + cg * 32 + sc * 16,
                                    acc[sr][sc], 132, wmma::mem_row_major);
    __syncthreads();

    __nv_bfloat16* elbase = g_el + (size_t)tile * 16384;
    for (int i = tid; i < 2048; i += 256) {
        int row = i >> 5, c4 = i & 31;
        float4 c = *(float4*)(Cf + row * 132 + c4 * 4);
        float4 b = ((const float4*)eB2)[c4];
        float4 nv = make_float4(c.x + b.x, c.y + b.y, c.z + b.z, c.w + b.w);
        __nv_bfloat16* hp = elbase + row * 128 + c4 * 4;
        split_store4(nv, hp, hp + 8192);
    }
}

// ---------------------------------------------------------------- edge processor step (double-buffered 32-K W pipeline)
#define ES_SSH 0
#define ES_RSH 256
#define ES_B1  512
#define ES_B2  1024
#define ES_AHI 1536
#define ES_ALO 18944
#define ES_WB0H 36352
#define ES_WB0L 45056
#define ES_WB1H 53760
#define ES_WB1L 62464
#define ES_SMEM 71168

// stage a 32-K W chunk (hi+lo planes) into a buffer
#define ES_STAGE_W(SRC_HI, SRC_LO, KC, DSTH, DSTL) \
    for (int i = tid; i < 512; i += 256) { \
        int r_ = i >> 4, g_ = i & 15; \
        cp_async16((DSTH) + (uint32_t)(r_ * 272 + g_ * 16), wbase + (SRC_HI) + ((KC) + r_) * 128 + g_ * 8); \
        cp_async16((DSTL) + (uint32_t)(r_ * 272 + g_ * 16), wbase + (SRC_LO) + ((KC) + r_) * 128 + g_ * 8); \
    }

// MMA a 32-K chunk: A cols [KC, KC+32), W buffer planes WH/WL
#define ES_MMA_CHUNK(KC, WH, WL) \
    for (int kk = 0; kk < 32; kk += 16) { \
        AF ah[2], al[2]; \
        _Pragma("unroll") \
        for (int sr = 0; sr < 2; sr++) { \
            wmma::load_matrix_sync(ah[sr], Ahi + (rt * 32 + sr * 16) * 136 + (KC) + kk, 136); \
            wmma::load_matrix_sync(al[sr], Alo + (rt * 32 + sr * 16) * 136 + (KC) + kk, 136); \
        } \
        _Pragma("unroll") \
        for (int sc = 0; sc < 2; sc++) { \
            BF bh, bl; \
            wmma::load_matrix_sync(bh, (WH) + kk * 136 + cg * 32 + sc * 16, 136); \
            wmma::load_matrix_sync(bl, (WL) + kk * 136 + cg * 32 + sc * 16, 136); \
            _Pragma("unroll") \
            for (int sr = 0; sr < 2; sr++) { \
                wmma::mma_sync(acc[sr][sc], ah[sr], bh, acc[sr][sc]); \
                wmma::mma_sync(acc[sr][sc], ah[sr], bl, acc[sr][sc]); \
                wmma::mma_sync(acc[sr][sc], al[sr], bh, acc[sr][sc]); \
            } \
        } \
    }

__global__ void __launch_bounds__(256, 3) k_edge_step(
    const int* __restrict__ snd, const int* __restrict__ rcv, int step,
    const float* __restrict__ B1, const float* __restrict__ B2)
{
    extern __shared__ char smc[];
    int*   ssh = (int*)(smc + ES_SSH);
    int*   rsh = (int*)(smc + ES_RSH);
    float* B1s = (float*)(smc + ES_B1);
    float* B2s = (float*)(smc + ES_B2);
    __nv_bfloat16* Ahi = (__nv_bfloat16*)(smc + ES_AHI);
    __nv_bfloat16* Alo = (__nv_bfloat16*)(smc + ES_ALO);
    __nv_bfloat16* W0h = (__nv_bfloat16*)(smc + ES_WB0H);
    __nv_bfloat16* W0l = (__nv_bfloat16*)(smc + ES_WB0L);
    __nv_bfloat16* W1h = (__nv_bfloat16*)(smc + ES_WB1H);
    __nv_bfloat16* W1l = (__nv_bfloat16*)(smc + ES_WB1L);
    float* Cf1 = (float*)(smc + ES_WB1H);   // 64 x 68 fp32 = 17408 B (GEMM1 C)
    float* Cf2 = (float*)(smc + ES_WB0H);   // (GEMM2 C)
    const int tid = threadIdx.x;
    const int w = tid >> 5, rt = w & 1, cg = w >> 1;
    const int ebase = blockIdx.x * 64;
    const __nv_bfloat16* wbase = g_ws + (size_t)step * STEP_W;
    __nv_bfloat16* elbase = g_el + (size_t)blockIdx.x * 16384;
    const uint32_t w0h_b = smem_u32(W0h), w0l_b = smem_u32(W0l);
    const uint32_t w1h_b = smem_u32(W1h), w1l_b = smem_u32(W1l);
    const uint32_t ahi_b = smem_u32(Ahi), alo_b = smem_u32(Alo);

    if (tid < 64) {
        ssh[tid] = snd[ebase + tid];
        rsh[tid] = rcv[ebase + tid];
    }
    if (tid < 128) {
        B1s[tid] = B1[tid];
        B2s[tid] = B2[tid];
    }
    // group0: el planes + W1a chunk0 -> WB0
    for (int i = tid; i < 1024; i += 256) {
        int r = i >> 4, g = i & 15;
        cp_async16(ahi_b + (uint32_t)(r * 272 + g * 16), elbase + r * 128 + g * 8);
        cp_async16(alo_b + (uint32_t)(r * 272 + g * 16), elbase + 8192 + r * 128 + g * 8);
    }
    ES_STAGE_W(EW1A_HI, EW1A_LO, 0, w0h_b, w0l_b);
    cp_commit();
    // group1: W1a chunk1 -> WB1
    ES_STAGE_W(EW1A_HI, EW1A_LO, 32, w1h_b, w1l_b);
    cp_commit();
    cp_wait1();                 // group0 done
    __syncthreads();

    CF acc[2][2];
#pragma unroll
    for (int sr = 0; sr < 2; sr++)
#pragma unroll
        for (int sc = 0; sc < 2; sc++) wmma::fill_fragment(acc[sr][sc], 0.f);

    // ---- GEMM1 pipeline (chunks 0..3 of W1a)
    ES_MMA_CHUNK(0, W0h, W0l);
    __syncthreads();
    ES_STAGE_W(EW1A_HI, EW1A_LO, 64, w0h_b, w0l_b);   // group2
    cp_commit();
    cp_wait1();                 // group1 done
    __syncthreads();
    ES_MMA_CHUNK(32, W1h, W1l);
    __syncthreads();
    ES_STAGE_W(EW1A_HI, EW1A_LO, 96, w1h_b, w1l_b);   // group3
    cp_commit();
    cp_wait1();                 // group2 done
    __syncthreads();
    ES_MMA_CHUNK(64, W0h, W0l);
    __syncthreads();
    ES_STAGE_W(EW2_HI, EW2_LO, 0, w0h_b, w0l_b);      // group4 = W2 chunk0 (prefetch under epilogue)
    cp_commit();
    cp_wait1();                 // group3 done
    __syncthreads();
    ES_MMA_CHUNK(96, W1h, W1l);
    __syncthreads();            // WB1 free -> Cf1

    // ---- epilogue 1 in column halves (Cf1 = WB1 region, 64x68 fp32)
#pragma unroll 1
    for (int h = 0; h < 2; ++h) {
        if ((cg >> 1) == h) {
            int cgl = cg & 1;
#pragma unroll
            for (int sr = 0; sr < 2; sr++)
#pragma unroll
                for (int sc = 0; sc < 2; sc++)
                    wmma::store_matrix_sync(Cf1 + (rt * 32 + sr * 16) * 68 + cgl * 32 + sc * 16,
                                            acc[sr][sc], 68, wmma::mem_row_major);
        }
        __syncthreads();
        for (int i = tid; i < 1024; i += 256) {
            int row = i >> 4, c4 = i & 15;
            int col = h * 64 + c4 * 4;
            int s = ssh[row], r = rsh[row];
            float4 c = *(float4*)(Cf1 + row * 68 + c4 * 4);
            float4 zb = *(const float4*)(g_z + (size_t)s * 256 + col);
            float4 zc = *(const float4*)(g_z + (size_t)r * 256 + 128 + col);
            float4 b = *(const float4*)(B1s + col);
            float4 v = make_float4(
                fmaxf(c.x + zb.x + zc.x + b.x, 0.f),
                fmaxf(c.y + zb.y + zc.y + b.y, 0.f),
                fmaxf(c.z + zb.z + zc.z + b.z, 0.f),
                fmaxf(c.w + zb.w + zc.w + b.w, 0.f));
            split_store4(v, Ahi + row * 136 + col, Alo + row * 136 + col);
        }
        __syncthreads();
    }

    // ---- GEMM2 pipeline (chunks 0..3 of W2); chunk0 already in flight (group4)
#pragma unroll
    for (int sr = 0; sr < 2; sr++)
#pragma unroll
        for (int sc = 0; sc < 2; sc++) wmma::fill_fragment(acc[sr][sc], 0.f);
    cp_wait0();                 // group4 done
    __syncthreads();
    ES_STAGE_W(EW2_HI, EW2_LO, 32, w1h_b, w1l_b);     // group5 (WB1 free: Cf1 consumed)
    cp_commit();
    ES_MMA_CHUNK(0, W0h, W0l);
    __syncthreads();
    ES_STAGE_W(EW2_HI, EW2_LO, 64, w0h_b, w0l_b);     // group6
    cp_commit();
    cp_wait1();                 // group5 done
    __syncthreads();
    ES_MMA_CHUNK(32, W1h, W1l);
    __syncthreads();
    ES_STAGE_W(EW2_HI, EW2_LO, 96, w1h_b, w1l_b);     // group7
    cp_commit();
    cp_wait1();                 // group6 done
    __syncthreads();
    ES_MMA_CHUNK(64, W0h, W0l);
    __syncthreads();            // WB0 free -> Cf2
    cp_wait0();                 // group7 done
    __syncthreads();
    ES_MMA_CHUNK(96, W1h, W1l);

    // ---- epilogue 2 in column halves (Cf2 = WB0 region)
#pragma unroll 1
    for (int h = 0; h < 2; ++h) {
        if ((cg >> 1) == h) {
            int cgl = cg & 1;
#pragma unroll
            for (int sr = 0; sr < 2; sr++)
#pragma unroll
                for (int sc = 0; sc < 2; sc++)
                    wmma::store_matrix_sync(Cf2 + (rt * 32 + sr * 16) * 68 + cgl * 32 + sc * 16,
                                            acc[sr][sc], 68, wmma::mem_row_major);
        }
        __syncthreads();
        for (int i = tid; i < 1024; i += 256) {
            int row = i >> 4, c4 = i & 15;
            int col = h * 64 + c4 * 4;
            __nv_bfloat16* hp = elbase + row * 128 + col;
            float4 oldv = join4(hp, hp + 8192);
            float4 c = *(float4*)(Cf2 + row * 68 + c4 * 4);
            float4 b = *(const float4*)(B2s + col);
            float4 nv = make_float4(oldv.x + c.x + b.x, oldv.y + c.y + b.y,
                                    oldv.z + c.z + b.z, oldv.w + c.w + b.w);
            split_store4(nv, hp, hp + 8192);
            red_add_v4(g_agg + (size_t)rsh[row] * LL + col, nv);
        }
        if (h == 0) __syncthreads();
    }
}

// ---------------------------------------------------------------- node step (+fused projection), 3 blocks/SM
#define N2_AHI 0
#define N2_ALO 17408
#define N2_W   34816
#define N2_WLO 52224
#define N2_SMEM 69632

__global__ void __launch_bounds__(256, 3) k_node_step(
    int step, const float* __restrict__ B1, const float* __restrict__ B2, int do_proj)
{
    extern __shared__ char smc[];
    __nv_bfloat16* Ahi = (__nv_bfloat16*)(smc + N2_AHI);
    __nv_bfloat16* Alo = (__nv_bfloat16*)(smc + N2_ALO);
    __nv_bfloat16* Whi = (__nv_bfloat16*)(smc + N2_W);
    __nv_bfloat16* Wlo = (__nv_bfloat16*)(smc + N2_WLO);
    float*         Cf  = (float*)(smc + N2_W);
    const int tid = threadIdx.x;
    const int w = tid >> 5, rt = w >> 1, cg = w & 1;
    const int nbase = blockIdx.x * 64;
    const bool full = (nbase + 64 <= NN);
    const __nv_bfloat16* wbase = g_ws + (size_t)step * STEP_W;
    const uint32_t whi_b = smem_u32(Whi), wlo_b = smem_u32(Wlo);

    CF acc[4];
#pragma unroll
    for (int f = 0; f < 4; f++) wmma::fill_fragment(acc[f], 0.f);

    // ---- GEMM1: X[64x256] @ NW1, X staged per 64-K chunk (single-use)
#pragma unroll 1
    for (int kc = 0; kc < 256; kc += 64) {
        __syncthreads();
        for (int i = tid; i < 1024; i += 256) {
            int row = i >> 4, g = i & 15;
            int n = nbase + row;
            float4 v = make_float4(0.f, 0.f, 0.f, 0.f);
            if (n < NN) {
                if (kc < 128) {
                    v = ((const float4*)(g_nl + (size_t)n * LL))[(kc >> 2) + g];
                } else {
                    float4* ap = (float4*)(g_agg + (size_t)n * LL) + (((kc - 128) >> 2) + g);
                    v = *ap;
                    *ap = make_float4(0.f, 0.f, 0.f, 0.f);
                }
            }
            split_store4(v, Ahi + row * 136 + g * 4, Alo + row * 136 + g * 4);
        }
        for (int i = tid; i < 1024; i += 256) {
            int rr = i >> 4, g = i & 15;
            cp_async16(whi_b + (uint32_t)(rr * 272 + g * 16), wbase + NW1_HI + (kc + rr) * 128 + g * 8);
            cp_async16(wlo_b + (uint32_t)(rr * 272 + g * 16), wbase + NW1_LO + (kc + rr) * 128 + g * 8);
        }
        cp_commit_wait();
        __syncthreads();
        for (int kk = 0; kk < 64; kk += 16) {
            AF ah, al;
            wmma::load_matrix_sync(ah, Ahi + rt * 16 * 136 + kk, 136);
            wmma::load_matrix_sync(al, Alo + rt * 16 * 136 + kk, 136);
#pragma unroll
            for (int f = 0; f < 4; f++) {
                BF bh, bl;
                wmma::load_matrix_sync(bh, Whi + kk * 136 + cg * 64 + f * 16, 136);
                wmma::load_matrix_sync(bl, Wlo + kk * 136 + cg * 64 + f * 16, 136);
                wmma::mma_sync(acc[f], ah, bh, acc[f]);
                wmma::mma_sync(acc[f], ah, bl, acc[f]);
                wmma::mma_sync(acc[f], al, bh, acc[f]);
            }
        }
    }
    __syncthreads();
#pragma unroll
    for (int f = 0; f < 4; f++)
        wmma::store_matrix_sync(Cf + rt * 16 * 132 + cg * 64 + f * 16, acc[f], 132, wmma::mem_row_major);
    __syncthreads();
    for (int i = tid; i < 64 * 32; i += 256) {
        int row = i >> 5, c4 = i & 31;
        float4 v = *(float4*)(Cf + row * 132 + c4 * 4);
        float4 bb = ((const float4*)B1)[c4];
        v.x = fmaxf(v.x + bb.x, 0.f);
        v.y = fmaxf(v.y + bb.y, 0.f);
        v.z = fmaxf(v.z + bb.z, 0.f);
        v.w = fmaxf(v.w + bb.w, 0.f);
        split_store4(v, Ahi + row * 136 + c4 * 4, Alo + row * 136 + c4 * 4);
    }
    __syncthreads();

    // ---- GEMM2: H[64x128] @ NW2, K chunked
#pragma unroll
    for (int f = 0; f < 4; f++) wmma::fill_fragment(acc[f], 0.f);
#pragma unroll 1
    for (int kc = 0; kc < 128; kc += 64) {
        for (int i = tid; i < 1024; i += 256) {
            int rr = i >> 4, g = i & 15;
            cp_async16(whi_b + (uint32_t)(rr * 272 + g * 16), wbase + NW2_HI + (kc + rr) * 128 + g * 8);
            cp_async16(wlo_b + (uint32_t)(rr * 272 + g * 16), wbase + NW2_LO + (kc + rr) * 128 + g * 8);
        }
        cp_commit_wait();
        __syncthreads();
        for (int kk = 0; kk < 64; kk += 16) {
            AF ah, al;
            wmma::load_matrix_sync(ah, Ahi + rt * 16 * 136 + kc + kk, 136);
            wmma::load_matrix_sync(al, Alo + rt * 16 * 136 + kc + kk, 136);
#pragma unroll
            for (int f = 0; f < 4; f++) {
                BF bh, bl;
                wmma::load_matrix_sync(bh, Whi + kk * 136 + cg * 64 + f * 16, 136);
                wmma::load_matrix_sync(bl, Wlo + kk * 136 + cg * 64 + f * 16, 136);
                wmma::mma_sync(acc[f], ah, bh, acc[f]);
                wmma::mma_sync(acc[f], ah, bl, acc[f]);
                wmma::mma_sync(acc[f], al, bh, acc[f]);
            }
        }
        __syncthreads();
    }
#pragma unroll
    for (int f = 0; f < 4; f++)
        wmma::store_matrix_sync(Cf + rt * 16 * 132 + cg * 64 + f * 16, acc[f], 132, wmma::mem_row_major);
    __syncthreads();

    for (int i = tid; i < 64 * 32; i += 256) {
        int row = i >> 5, c4 = i & 31;
        int n = nbase + row;
        float4 nv = make_float4(0.f, 0.f, 0.f, 0.f);
        if (n < NN) {
            float4 oldv = ((const float4*)(g_nl + (size_t)n * LL))[c4];
            float4 c2 = *(float4*)(Cf + row * 132 + c4 * 4);
            float4 bb = ((const float4*)B2)[c4];
            nv = make_float4(oldv.x + c2.x + bb.x, oldv.y + c2.y + bb.y,
                             oldv.z + c2.z + bb.z, oldv.w + c2.w + bb.w);
            ((float4*)(g_nl + (size_t)n * LL))[c4] = nv;
        }
        if (do_proj)
            split_store4(nv, Ahi + row * 136 + c4 * 4, Alo + row * 136 + c4 * 4);
    }

    if (do_proj) {
        const __nv_bfloat16* wn = g_ws + (size_t)(step + 1) * STEP_W;
#pragma unroll 1
        for (int half = 0; half < 2; ++half) {
#pragma unroll
            for (int f = 0; f < 4; f++) wmma::fill_fragment(acc[f], 0.f);
#pragma unroll 1
            for (int kc = 0; kc < 128; kc += 64) {
                __syncthreads();
                for (int i = tid; i < 1024; i += 256) {
                    int rr = i >> 4, g = i & 15;
                    cp_async16(whi_b + (uint32_t)(rr * 272 + g * 16),
                               wn + PRJ_HI + (size_t)(kc + rr) * 256 + half * 128 + g * 8);
                    cp_async16(wlo_b + (uint32_t)(rr * 272 + g * 16),
                               wn + PRJ_LO + (size_t)(kc + rr) * 256 + half * 128 + g * 8);
                }
                cp_commit_wait();
                __syncthreads();
                for (int kk = 0; kk < 64; kk += 16) {
                    AF ah, al;
                    wmma::load_matrix_sync(ah, Ahi + rt * 16 * 136 + kc + kk, 136);
                    wmma::load_matrix_sync(al, Alo + rt * 16 * 136 + kc + kk, 136);
#pragma unroll
                    for (int f = 0; f < 4; f++) {
                        BF bh, bl;
                        wmma::load_matrix_sync(bh, Whi + kk * 136 + cg * 64 + f * 16, 136);
                        wmma::load_matrix_sync(bl, Wlo + kk * 136 + cg * 64 + f * 16, 136);
                        wmma::mma_sync(acc[f], ah, bh, acc[f]);
                        wmma::mma_sync(acc[f], ah, bl, acc[f]);
                        wmma::mma_sync(acc[f], al, bh, acc[f]);
                    }
                }
            }
            if (full) {
#pragma unroll
                for (int f = 0; f < 4; f++)
                    wmma::store_matrix_sync(g_z + (size_t)(nbase + rt * 16) * 256 + half * 128 + cg * 64 + f * 16,
                                            acc[f], 256, wmma::mem_row_major);
            } else {
                __syncthreads();
#pragma unroll
                for (int f = 0; f < 4; f++)
                    wmma::store_matrix_sync(Cf + rt * 16 * 132 + cg * 64 + f * 16, acc[f], 132, wmma::mem_row_major);
                __syncthreads();
                for (int i = tid; i < 64 * 32; i += 256) {
                    int row = i >> 5, c4 = i & 31;
                    int n = nbase + row;
                    if (n < NN)
                        ((float4*)(g_z + (size_t)n * 256 + half * 128))[c4] =
                            *(float4*)(Cf + row * 132 + c4 * 4);
                }
            }
        }
    }
}

// ---------------------------------------------------------------- decoder (SIMT fp32; exact)
__global__ void __launch_bounds__(128) k_decoder(
    const float* __restrict__ W1, const float* __restrict__ B1,
    const float* __restrict__ W2, const float* __restrict__ B2,
    float* __restrict__ out)
{
    __shared__ float Xs[32][128];
    __shared__ float H[32][128];
    const int tid = threadIdx.x;
    const int nbase = blockIdx.x * 32;

    for (int i = tid; i < 32 * 32; i += 128) {
        int n = i >> 5, c4 = i & 31;
        int gn = nbase + n;
        float4 v = make_float4(0.f, 0.f, 0.f, 0.f);
        if (gn < NN) v = ((const float4*)(g_nl + (size_t)gn * LL))[c4];
        ((float4*)Xs[n])[c4] = v;
    }
    __syncthreads();

    const int j = tid;
#pragma unroll 1
    for (int n = 0; n < 32; n++) {
        float acc = B1[j];
#pragma unroll 8
        for (int k = 0; k < 128; k++) acc += Xs[n][k] * W1[k * 128 + j];
        H[n][j] = fmaxf(acc, 0.f);
    }
    __syncthreads();

    if (tid < 96) {
        int n = tid / 3, d = tid % 3;
        int gn = nbase + n;
        float acc = B2[d];
#pragma unroll 8
        for (int k = 0; k < 128; k++) acc += H[n][k] * W2[k * 3 + d];
        if (gn < NN) out[gn * 3 + d] = acc;
    }
}

// ---------------------------------------------------------------- launch
extern "C" void kernel_launch(void* const* d_in, const int* in_sizes, int n_in,
                              void* d_out, int out_size)
{
    const float* pos   = (const float*)d_in[0];
    const float* vel   = (const float*)d_in[1];
    const int*   rid   = (const int*)d_in[2];
    const int*   snd   = (const int*)d_in[3];
    const int*   rcv   = (const int*)d_in[4];
    const float* remb  = (const float*)d_in[5];
    const float* ne_w1 = (const float*)d_in[6];
    const float* ne_b1 = (const float*)d_in[7];
    const float* ne_w2 = (const float*)d_in[8];
    const float* ne_b2 = (const float*)d_in[9];
    const float* ee_w1 = (const float*)d_in[10];
    const float* ee_b1 = (const float*)d_in[11];
    const float* ee_w2 = (const float*)d_in[12];
    const float* ee_b2 = (const float*)d_in[13];
    const float* pe_w1 = (const float*)d_in[14];
    const float* pe_b1 = (const float*)d_in[15];
    const float* pe_w2 = (const float*)d_in[16];
    const float* pe_b2 = (const float*)d_in[17];
    const float* pn_w1 = (const float*)d_in[18];
    const float* pn_b1 = (const float*)d_in[19];
    const float* pn_w2 = (const float*)d_in[20];
    const float* pn_b2 = (const float*)d_in[21];
    const float* de_w1 = (const float*)d_in[22];
    const float* de_b1 = (const float*)d_in[23];
    const float* de_w2 = (const float*)d_in[24];
    const float* de_b2 = (const float*)d_in[25];

    cudaFuncSetAttribute(k_edge_step, cudaFuncAttributeMaxDynamicSharedMemorySize, ES_SMEM);
    cudaFuncSetAttribute(k_node_step, cudaFuncAttributeMaxDynamicSharedMemorySize, N2_SMEM);
    cudaFuncSetAttribute(k_node_enc_proj, cudaFuncAttributeMaxDynamicSharedMemorySize, NEP_SMEM);
    cudaFuncSetAttribute(k_edge_enc2, cudaFuncAttributeMaxDynamicSharedMemorySize, EN_SMEM);

    k_setup<<<4740, 256>>>(pe_w1, pe_w2, pn_w1, pn_w2, ee_w2);
    k_degcenter<<<3229, 256>>>(rcv, pos);
    k_node_enc_proj<<<NB_ENC, 256, NEP_SMEM>>>(pos, vel, rid, remb, ne_w1, ne_b1, ne_w2, ne_b2);
    k_edge_enc2<<<EB_ENC, 256, EN_SMEM>>>(pos, vel, rid, snd, rcv, ee_w1, ee_b1, ee_b2);

    for (int st = 0; st < NSTEPS; st++) {
        k_edge_step<<<EE / 64, 256, ES_SMEM>>>(
            snd, rcv, st, pe_b1 + (size_t)st * 128, pe_b2 + (size_t)st * 128);
        k_node_step<<<(NN + 63) / 64, 256, N2_SMEM>>>(
            st, pn_b1 + (size_t)st * 128, pn_b2 + (size_t)st * 128, (st < NSTEPS - 1) ? 1 : 0);
    }

    k_decoder<<<(NN + 31) / 32, 128>>>(de_w1, de_b1, de_w2, de_b2, (float*)d_out);
}

// round 15
// speedup vs baseline: 1.4403x; 1.0108x over previous
#include <cuda_runtime.h>
#include <cuda_bf16.h>
#include <mma.h>
#include <cstdint>

using namespace nvcuda;

#define NN 50000
#define EE 800000
#define LL 128
#define NSTEPS 10
#define NB_ENC 782          // ceil(NN/64)
#define EB_ENC 12500        // EE/64

// ---- scratch (device globals; no allocations allowed) ----
__device__ float g_nl[(size_t)NN * LL];
// el stored as bf16 hi/lo planes, tile-major: [tile(64 edges)][hi 64x128][lo 64x128]
__device__ __nv_bfloat16 g_el[(size_t)EE * 256];
__device__ float g_agg[(size_t)NN * LL];
__device__ float g_z[(size_t)NN * 256];
__device__ float g_deg[NN];
__device__ float g_center[3];

#define EW1A_HI 0
#define EW1A_LO 16384
#define EW2_HI  32768
#define EW2_LO  49152
#define PRJ_HI  65536
#define PRJ_LO  98304
#define NW1_HI  131072
#define NW1_LO  163840
#define NW2_HI  196608
#define NW2_LO  212992
#define STEP_W  229376
__device__ __nv_bfloat16 g_ws[(size_t)NSTEPS * STEP_W];
// encoder W2 planes: hi [0,16384), lo [16384,32768)
__device__ __nv_bfloat16 g_we2[32768];

typedef wmma::fragment<wmma::matrix_a, 16, 16, 16, __nv_bfloat16, wmma::row_major> AF;
typedef wmma::fragment<wmma::matrix_b, 16, 16, 16, __nv_bfloat16, wmma::row_major> BF;
typedef wmma::fragment<wmma::accumulator, 16, 16, 16, float> CF;

__device__ __forceinline__ uint32_t smem_u32(const void* p) {
    uint32_t a;
    asm("{ .reg .u64 t; cvta.to.shared.u64 t, %1; cvt.u32.u64 %0, t; }" : "=r"(a) : "l"(p));
    return a;
}
// .cg: bypass L1 allocation (single-use staging data)
__device__ __forceinline__ void cp_async16(uint32_t dst, const void* src) {
    asm volatile("cp.async.cg.shared.global [%0], [%1], 16;" :: "r"(dst), "l"(src) : "memory");
}
__device__ __forceinline__ void cp_commit() {
    asm volatile("cp.async.commit_group;" ::: "memory");
}
__device__ __forceinline__ void cp_wait0() {
    asm volatile("cp.async.wait_group 0;" ::: "memory");
}
__device__ __forceinline__ void cp_wait1() {
    asm volatile("cp.async.wait_group 1;" ::: "memory");
}
__device__ __forceinline__ void cp_commit_wait() {
    cp_commit();
    cp_wait0();
}

__device__ __forceinline__ void split_store4(float4 v, __nv_bfloat16* hip, __nv_bfloat16* lop) {
    __nv_bfloat162 h0 = __floats2bfloat162_rn(v.x, v.y);
    __nv_bfloat162 h1 = __floats2bfloat162_rn(v.z, v.w);
    float2 f0 = __bfloat1622float2(h0);
    float2 f1 = __bfloat1622float2(h1);
    __nv_bfloat162 l0 = __floats2bfloat162_rn(v.x - f0.x, v.y - f0.y);
    __nv_bfloat162 l1 = __floats2bfloat162_rn(v.z - f1.x, v.w - f1.y);
    *(__nv_bfloat162*)(hip)     = h0;
    *(__nv_bfloat162*)(hip + 2) = h1;
    *(__nv_bfloat162*)(lop)     = l0;
    *(__nv_bfloat162*)(lop + 2) = l1;
}

__device__ __forceinline__ float4 join4(const __nv_bfloat16* hip, const __nv_bfloat16* lop) {
    float2 a = __bfloat1622float2(*(const __nv_bfloat162*)hip);
    float2 b = __bfloat1622float2(*(const __nv_bfloat162*)(hip + 2));
    float2 c = __bfloat1622float2(*(const __nv_bfloat162*)lop);
    float2 d = __bfloat1622float2(*(const __nv_bfloat162*)(lop + 2));
    return make_float4(a.x + c.x, a.y + c.y, b.x + d.x, b.y + d.y);
}

__device__ __forceinline__ void red_add_v4(float* dst, float4 v) {
    asm volatile("red.global.add.v4.f32 [%0], {%1,%2,%3,%4};"
                 :: "l"(dst), "f"(v.x), "f"(v.y), "f"(v.z), "f"(v.w) : "memory");
}

// ---------------------------------------------------------------- launch 0: weight prep + init
__global__ void __launch_bounds__(256) k_setup(
    const float* __restrict__ pe_w1, const float* __restrict__ pe_w2,
    const float* __restrict__ pn_w1, const float* __restrict__ pn_w2,
    const float* __restrict__ ee_w2)
{
    if (blockIdx.x < 4480) {
        int idx = blockIdx.x * 256 + threadIdx.x;
        int s = idx / 114688;
        int e = idx % 114688;
        float v;
        size_t dhi, dlo;
        if (e < 16384) {
            v = pe_w1[(size_t)s * 384 * 128 + e];
            dhi = EW1A_HI + e; dlo = EW1A_LO + e;
        } else if (e < 32768) {
            int e2 = e - 16384;
            v = pe_w2[(size_t)s * 128 * 128 + e2];
            dhi = EW2_HI + e2; dlo = EW2_LO + e2;
        } else if (e < 65536) {
            int e2 = e - 32768;
            int k = e2 >> 8, n = e2 & 255;
            int srcrow = 128 + (n >> 7) * 128 + k;
            v = pe_w1[(size_t)s * 384 * 128 + (size_t)srcrow * 128 + (n & 127)];
            dhi = PRJ_HI + e2; dlo = PRJ_LO + e2;
        } else if (e < 98304) {
            int e2 = e - 65536;
            v = pn_w1[(size_t)s * 256 * 128 + e2];
            dhi = NW1_HI + e2; dlo = NW1_LO + e2;
        } else {
            int e2 = e - 98304;
            v = pn_w2[(size_t)s * 128 * 128 + e2];
            dhi = NW2_HI + e2; dlo = NW2_LO + e2;
        }
        __nv_bfloat16 h = __float2bfloat16(v);
        g_ws[(size_t)s * STEP_W + dhi] = h;
        g_ws[(size_t)s * STEP_W + dlo] = __float2bfloat16(v - __bfloat162float(h));
    } else if (blockIdx.x < 4544) {
        int i = (blockIdx.x - 4480) * 256 + threadIdx.x;   // < 16384
        float v = ee_w2[i];
        __nv_bfloat16 h = __float2bfloat16(v);
        g_we2[i] = h;
        g_we2[16384 + i] = __float2bfloat16(v - __bfloat162float(h));
    } else {
        int i = (blockIdx.x - 4544) * 256 + threadIdx.x;
        if (i < NN) g_deg[i] = 0.f;
        if (i < 3) g_center[i] = 0.f;
    }
}

// ---------------------------------------------------------------- launch 1: degree + center
__global__ void __launch_bounds__(256) k_degcenter(
    const int* __restrict__ rcv, const float* __restrict__ pos)
{
    if (blockIdx.x < 3125) {
        int i = blockIdx.x * 256 + threadIdx.x;
        if (i < EE) atomicAdd(&g_deg[rcv[i]], 1.f);
    } else {
        float sx = 0.f, sy = 0.f, sz = 0.f;
        for (int i = (blockIdx.x - 3125) * 256 + threadIdx.x; i < NN; i += 104 * 256) {
            sx += pos[i * 3 + 0];
            sy += pos[i * 3 + 1];
            sz += pos[i * 3 + 2];
        }
#pragma unroll
        for (int o = 16; o > 0; o >>= 1) {
            sx += __shfl_down_sync(0xffffffffu, sx, o);
            sy += __shfl_down_sync(0xffffffffu, sy, o);
            sz += __shfl_down_sync(0xffffffffu, sz, o);
        }
        if ((threadIdx.x & 31) == 0) {
            atomicAdd(&g_center[0], sx);
            atomicAdd(&g_center[1], sy);
            atomicAdd(&g_center[2], sz);
        }
    }
}

// ---------------------------------------------------------------- launch 2: node encoder + step-0 projection
#define NEP_SMEM 110592

__global__ void __launch_bounds__(256, 2) k_node_enc_proj(
    const float* __restrict__ pos, const float* __restrict__ vel,
    const int* __restrict__ rid, const float* __restrict__ remb,
    const float* __restrict__ nW1, const float* __restrict__ nB1,
    const float* __restrict__ nW2, const float* __restrict__ nB2)
{
    extern __shared__ char smc[];
    const int tid = threadIdx.x;
    float* F = (float*)(smc + 0);
    float* H = (float*)(smc + 8192);
    __nv_bfloat16* Ahi = (__nv_bfloat16*)(smc + 40960);
    __nv_bfloat16* Alo = (__nv_bfloat16*)(smc + 58368);
    __nv_bfloat16* Wch = (__nv_bfloat16*)(smc + 75776);
    __nv_bfloat16* Wcl = (__nv_bfloat16*)(smc + 93184);
    const int nbase = blockIdx.x * 64;
    const float inv = 1.f / (float)NN;
    const float cx = g_center[0] * inv, cy = g_center[1] * inv, cz = g_center[2] * inv;

    for (int i = tid; i < 64 * 23; i += 256) {
        int n = i / 23, k = i % 23;
        int gn = nbase + n;
        float v = 0.f;
        if (gn < NN) {
            if (k < 3) v = vel[gn * 3 + k];
            else if (k < 6) v = pos[gn * 3 + (k - 3)] - ((k == 3) ? cx : (k == 4) ? cy : cz);
            else if (k == 6) v = g_deg[gn];
            else v = remb[rid[gn] * 16 + (k - 7)];
        }
        F[n * 24 + k] = v;
    }
    __syncthreads();

    const int j = tid & 127;
    for (int n = tid >> 7; n < 64; n += 2) {
        float acc = nB1[j];
#pragma unroll
        for (int k = 0; k < 23; k++) acc += F[n * 24 + k] * nW1[k * 128 + j];
        H[n * 128 + j] = fmaxf(acc, 0.f);
    }
    __syncthreads();
    for (int n = tid >> 7; n < 64; n += 2) {
        int gn = nbase + n;
        float acc = nB2[j];
#pragma unroll 8
        for (int k = 0; k < 128; k++) acc += H[n * 128 + k] * nW2[k * 128 + j];
        float v = (gn < NN) ? acc : 0.f;
        if (gn < NN) g_nl[(size_t)gn * LL + j] = v;
        __nv_bfloat16 h = __float2bfloat16(v);
        Ahi[n * 136 + j] = h;
        Alo[n * 136 + j] = __float2bfloat16(v - __bfloat162float(h));
    }
    __syncthreads();

    // projection Z(0) = nl @ PRJ(0)
    const int w = tid >> 5, rt = w >> 1, cg = w & 1;
    const bool full = (nbase + 64 <= NN);
    const __nv_bfloat16* wn = g_ws;
    CF acc[4];
#pragma unroll 1
    for (int half = 0; half < 2; ++half) {
#pragma unroll
        for (int f = 0; f < 4; f++) wmma::fill_fragment(acc[f], 0.f);
        for (int kc = 0; kc < 128; kc += 64) {
            __syncthreads();
            for (int i = tid; i < 1024; i += 256) {
                int rr = i >> 4, g = i & 15;
                *(float4*)(Wch + rr * 136 + g * 8) =
                    ((const float4*)(wn + PRJ_HI + (size_t)(kc + rr) * 256 + half * 128))[g];
                *(float4*)(Wcl + rr * 136 + g * 8) =
                    ((const float4*)(wn + PRJ_LO + (size_t)(kc + rr) * 256 + half * 128))[g];
            }
            __syncthreads();
            for (int kk = 0; kk < 64; kk += 16) {
                AF ah, al;
                wmma::load_matrix_sync(ah, Ahi + rt * 16 * 136 + kc + kk, 136);
                wmma::load_matrix_sync(al, Alo + rt * 16 * 136 + kc + kk, 136);
#pragma unroll
                for (int f = 0; f < 4; f++) {
                    BF bh, bl;
                    wmma::load_matrix_sync(bh, Wch + kk * 136 + cg * 64 + f * 16, 136);
                    wmma::load_matrix_sync(bl, Wcl + kk * 136 + cg * 64 + f * 16, 136);
                    wmma::mma_sync(acc[f], ah, bh, acc[f]);
                    wmma::mma_sync(acc[f], ah, bl, acc[f]);
                    wmma::mma_sync(acc[f], al, bh, acc[f]);
                }
            }
        }
        if (full) {
#pragma unroll
            for (int f = 0; f < 4; f++)
                wmma::store_matrix_sync(g_z + (size_t)(nbase + rt * 16) * 256 + half * 128 + cg * 64 + f * 16,
                                        acc[f], 256, wmma::mem_row_major);
        } else {
            float* Cf = (float*)(smc + 75776);   // dead W region; restaged next half
            __syncthreads();
#pragma unroll
            for (int f = 0; f < 4; f++)
                wmma::store_matrix_sync(Cf + rt * 16 * 132 + cg * 64 + f * 16, acc[f], 132, wmma::mem_row_major);
            __syncthreads();
            for (int i = tid; i < 64 * 32; i += 256) {
                int row = i >> 5, c4 = i & 31;
                int n = nbase + row;
                if (n < NN)
                    ((float4*)(g_z + (size_t)n * 256 + half * 128))[c4] =
                        *(float4*)(Cf + row * 132 + c4 * 4);
            }
        }
    }
}

// ---------------------------------------------------------------- launch 3: edge encoder (3 blocks/SM)
#define EN_F   0        // 64 x 12 fp32
#define EN_HHI 4096     // 64 x 136 bf16
#define EN_HLO 21504
#define EN_W   38912    // 64 x 136 bf16 (K-chunk)
#define EN_WLO 56320
#define EN_SMEM 73728

__global__ void __launch_bounds__(256, 3) k_edge_enc2(
    const float* __restrict__ pos, const float* __restrict__ vel,
    const int* __restrict__ rid,
    const int* __restrict__ snd, const int* __restrict__ rcv,
    const float* __restrict__ eW1, const float* __restrict__ eB1,
    const float* __restrict__ eB2)
{
    extern __shared__ char smc[];
    float*         F   = (float*)(smc + EN_F);
    __nv_bfloat16* Hhi = (__nv_bfloat16*)(smc + EN_HHI);
    __nv_bfloat16* Hlo = (__nv_bfloat16*)(smc + EN_HLO);
    __nv_bfloat16* Whi = (__nv_bfloat16*)(smc + EN_W);
    __nv_bfloat16* Wlo = (__nv_bfloat16*)(smc + EN_WLO);
    float*         Cf  = (float*)(smc + EN_W);    // aliases W
    const int tid = threadIdx.x;
    const int w = tid >> 5, rt = w & 1, cg = w >> 1;   // 2 x 4 tiling
    const int tile = blockIdx.x;
    const int ebase = tile * 64;
    const uint32_t whi_b = smem_u32(Whi), wlo_b = smem_u32(Wlo);

    for (int i = tid; i < 1024; i += 256) {
        int r = i >> 4, g = i & 15;
        cp_async16(whi_b + (uint32_t)(r * 272 + g * 16), g_we2 + r * 128 + g * 8);
        cp_async16(wlo_b + (uint32_t)(r * 272 + g * 16), g_we2 + 16384 + r * 128 + g * 8);
    }
    cp_commit();
    if (tid < 64) {
        int e = ebase + tid;
        int s = snd[e], r = rcv[e];
        float rp0 = pos[s * 3 + 0] - pos[r * 3 + 0];
        float rp1 = pos[s * 3 + 1] - pos[r * 3 + 1];
        float rp2 = pos[s * 3 + 2] - pos[r * 3 + 2];
        float rv0 = vel[s * 3 + 0] - vel[r * 3 + 0];
        float rv1 = vel[s * 3 + 1] - vel[r * 3 + 1];
        float rv2 = vel[s * 3 + 2] - vel[r * 3 + 2];
        float sq = rp0 * rp0 + rp1 * rp1 + rp2 * rp2;
        float dist = sqrtf(sq);
        float same = (rid[s] == rid[r]) ? 1.f : 0.f;
        float* f = F + tid * 12;
        f[0] = rp0; f[1] = rp1; f[2] = rp2;
        f[3] = rv0; f[4] = rv1; f[5] = rv2;
        f[6] = dist; f[7] = sq; f[8] = same;
    }
    __syncthreads();

    {
        const int j = tid & 127;
        for (int n = tid >> 7; n < 64; n += 2) {
            float acc = eB1[j];
#pragma unroll
            for (int k = 0; k < 9; k++) acc += F[n * 12 + k] * eW1[k * 128 + j];
            acc = fmaxf(acc, 0.f);
            __nv_bfloat16 h = __float2bfloat16(acc);
            Hhi[n * 136 + j] = h;
            Hlo[n * 136 + j] = __float2bfloat16(acc - __bfloat162float(h));
        }
    }
    cp_wait0();
    __syncthreads();

    CF acc[2][2];
#pragma unroll
    for (int sr = 0; sr < 2; sr++)
#pragma unroll
        for (int sc = 0; sc < 2; sc++) wmma::fill_fragment(acc[sr][sc], 0.f);
#pragma unroll 1
    for (int kc = 0; kc < 128; kc += 64) {
        if (kc) {
            __syncthreads();
            for (int i = tid; i < 1024; i += 256) {
                int r = i >> 4, g = i & 15;
                cp_async16(whi_b + (uint32_t)(r * 272 + g * 16), g_we2 + (kc + r) * 128 + g * 8);
                cp_async16(wlo_b + (uint32_t)(r * 272 + g * 16), g_we2 + 16384 + (kc + r) * 128 + g * 8);
            }
            cp_commit_wait();
            __syncthreads();
        }
        for (int kk = 0; kk < 64; kk += 16) {
            AF ah[2], al[2];
#pragma unroll
            for (int sr = 0; sr < 2; sr++) {
                wmma::load_matrix_sync(ah[sr], Hhi + (rt * 32 + sr * 16) * 136 + kc + kk, 136);
                wmma::load_matrix_sync(al[sr], Hlo + (rt * 32 + sr * 16) * 136 + kc + kk, 136);
            }
#pragma unroll
            for (int sc = 0; sc < 2; sc++) {
                BF bh, bl;
                wmma::load_matrix_sync(bh, Whi + kk * 136 + cg * 32 + sc * 16, 136);
                wmma::load_matrix_sync(bl, Wlo + kk * 136 + cg * 32 + sc * 16, 136);
#pragma unroll
                for (int sr = 0; sr < 2; sr++) {
                    wmma::mma_sync(acc[sr][sc], ah[sr], bh, acc[sr][sc]);
                    wmma::mma_sync(acc[sr][sc], ah[sr], bl, acc[sr][sc]);
                    wmma::mma_sync(acc[sr][sc], al[sr], bh, acc[sr][sc]);
                }
            }
        }
    }
    __syncthreads();
#pragma unroll
    for (int sr = 0; sr < 2; sr++)
#pragma unroll
        for (int sc = 0; sc < 2; sc++)
            wmma::store_matrix_sync(Cf + (rt * 32 + sr * 16) * 132 + cg * 32 + sc * 16,
                                    acc[sr][sc], 132, wmma::mem_row_major);
    __syncthreads();

    __nv_bfloat16* elbase = g_el + (size_t)tile * 16384;
    for (int i = tid; i < 2048; i += 256) {
        int row = i >> 5, c4 = i & 31;
        float4 c = *(float4*)(Cf + row * 132 + c4 * 4);
        float4 b = ((const float4*)eB2)[c4];
        float4 nv = make_float4(c.x + b.x, c.y + b.y, c.z + b.z, c.w + b.w);
        __nv_bfloat16* hp = elbase + row * 128 + c4 * 4;
        split_store4(nv, hp, hp + 8192);
    }
}

// ---------------------------------------------------------------- edge processor step (double-buffered 32-K W pipeline)
#define ES_SSH 0
#define ES_RSH 256
#define ES_B1  512
#define ES_B2  1024
#define ES_AHI 1536
#define ES_ALO 18944
#define ES_WB0H 36352
#define ES_WB0L 45056
#define ES_WB1H 53760
#define ES_WB1L 62464
#define ES_SMEM 71168

// stage a 32-K W chunk (hi+lo planes) into a buffer
#define ES_STAGE_W(SRC_HI, SRC_LO, KC, DSTH, DSTL) \
    for (int i = tid; i < 512; i += 256) { \
        int r_ = i >> 4, g_ = i & 15; \
        cp_async16((DSTH) + (uint32_t)(r_ * 272 + g_ * 16), wbase + (SRC_HI) + ((KC) + r_) * 128 + g_ * 8); \
        cp_async16((DSTL) + (uint32_t)(r_ * 272 + g_ * 16), wbase + (SRC_LO) + ((KC) + r_) * 128 + g_ * 8); \
    }

// MMA a 32-K chunk: A cols [KC, KC+32), W buffer planes WH/WL
#define ES_MMA_CHUNK(KC, WH, WL) \
    for (int kk = 0; kk < 32; kk += 16) { \
        AF ah[2], al[2]; \
        _Pragma("unroll") \
        for (int sr = 0; sr < 2; sr++) { \
            wmma::load_matrix_sync(ah[sr], Ahi + (rt * 32 + sr * 16) * 136 + (KC) + kk, 136); \
            wmma::load_matrix_sync(al[sr], Alo + (rt * 32 + sr * 16) * 136 + (KC) + kk, 136); \
        } \
        _Pragma("unroll") \
        for (int sc = 0; sc < 2; sc++) { \
            BF bh, bl; \
            wmma::load_matrix_sync(bh, (WH) + kk * 136 + cg * 32 + sc * 16, 136); \
            wmma::load_matrix_sync(bl, (WL) + kk * 136 + cg * 32 + sc * 16, 136); \
            _Pragma("unroll") \
            for (int sr = 0; sr < 2; sr++) { \
                wmma::mma_sync(acc[sr][sc], ah[sr], bh, acc[sr][sc]); \
                wmma::mma_sync(acc[sr][sc], ah[sr], bl, acc[sr][sc]); \
                wmma::mma_sync(acc[sr][sc], al[sr], bh, acc[sr][sc]); \
            } \
        } \
    }

__global__ void __launch_bounds__(256, 3) k_edge_step(
    const int* __restrict__ snd, const int* __restrict__ rcv, int step,
    const float* __restrict__ B1, const float* __restrict__ B2)
{
    extern __shared__ char smc[];
    int*   ssh = (int*)(smc + ES_SSH);
    int*   rsh = (int*)(smc + ES_RSH);
    float* B1s = (float*)(smc + ES_B1);
    float* B2s = (float*)(smc + ES_B2);
    __nv_bfloat16* Ahi = (__nv_bfloat16*)(smc + ES_AHI);
    __nv_bfloat16* Alo = (__nv_bfloat16*)(smc + ES_ALO);
    __nv_bfloat16* W0h = (__nv_bfloat16*)(smc + ES_WB0H);
    __nv_bfloat16* W0l = (__nv_bfloat16*)(smc + ES_WB0L);
    __nv_bfloat16* W1h = (__nv_bfloat16*)(smc + ES_WB1H);
    __nv_bfloat16* W1l = (__nv_bfloat16*)(smc + ES_WB1L);
    float* Cf1 = (float*)(smc + ES_WB1H);   // 64 x 68 fp32 = 17408 B (GEMM1 C)
    float* Cf2 = (float*)(smc + ES_WB0H);   // (GEMM2 C)
    const int tid = threadIdx.x;
    const int w = tid >> 5, rt = w & 1, cg = w >> 1;
    const int ebase = blockIdx.x * 64;
    const __nv_bfloat16* wbase = g_ws + (size_t)step * STEP_W;
    __nv_bfloat16* elbase = g_el + (size_t)blockIdx.x * 16384;
    const uint32_t w0h_b = smem_u32(W0h), w0l_b = smem_u32(W0l);
    const uint32_t w1h_b = smem_u32(W1h), w1l_b = smem_u32(W1l);
    const uint32_t ahi_b = smem_u32(Ahi), alo_b = smem_u32(Alo);

    if (tid < 64) {
        ssh[tid] = snd[ebase + tid];
        rsh[tid] = rcv[ebase + tid];
    }
    if (tid < 128) {
        B1s[tid] = B1[tid];
        B2s[tid] = B2[tid];
    }
    // group0: el planes + W1a chunk0 -> WB0
    for (int i = tid; i < 1024; i += 256) {
        int r = i >> 4, g = i & 15;
        cp_async16(ahi_b + (uint32_t)(r * 272 + g * 16), elbase + r * 128 + g * 8);
        cp_async16(alo_b + (uint32_t)(r * 272 + g * 16), elbase + 8192 + r * 128 + g * 8);
    }
    ES_STAGE_W(EW1A_HI, EW1A_LO, 0, w0h_b, w0l_b);
    cp_commit();
    // group1: W1a chunk1 -> WB1
    ES_STAGE_W(EW1A_HI, EW1A_LO, 32, w1h_b, w1l_b);
    cp_commit();
    cp_wait1();                 // group0 done
    __syncthreads();

    CF acc[2][2];
#pragma unroll
    for (int sr = 0; sr < 2; sr++)
#pragma unroll
        for (int sc = 0; sc < 2; sc++) wmma::fill_fragment(acc[sr][sc], 0.f);

    // ---- GEMM1 pipeline (chunks 0..3 of W1a)
    ES_MMA_CHUNK(0, W0h, W0l);
    __syncthreads();
    ES_STAGE_W(EW1A_HI, EW1A_LO, 64, w0h_b, w0l_b);   // group2
    cp_commit();
    cp_wait1();                 // group1 done
    __syncthreads();
    ES_MMA_CHUNK(32, W1h, W1l);
    __syncthreads();
    ES_STAGE_W(EW1A_HI, EW1A_LO, 96, w1h_b, w1l_b);   // group3
    cp_commit();
    cp_wait1();                 // group2 done
    __syncthreads();
    ES_MMA_CHUNK(64, W0h, W0l);
    __syncthreads();
    ES_STAGE_W(EW2_HI, EW2_LO, 0, w0h_b, w0l_b);      // group4 = W2 chunk0 (prefetch under epilogue)
    cp_commit();
    cp_wait1();                 // group3 done
    __syncthreads();
    ES_MMA_CHUNK(96, W1h, W1l);
    __syncthreads();            // WB1 free -> Cf1

    // ---- epilogue 1 in column halves (Cf1 = WB1 region, 64x68 fp32)
#pragma unroll 1
    for (int h = 0; h < 2; ++h) {
        if ((cg >> 1) == h) {
            int cgl = cg & 1;
#pragma unroll
            for (int sr = 0; sr < 2; sr++)
#pragma unroll
                for (int sc = 0; sc < 2; sc++)
                    wmma::store_matrix_sync(Cf1 + (rt * 32 + sr * 16) * 68 + cgl * 32 + sc * 16,
                                            acc[sr][sc], 68, wmma::mem_row_major);
        }
        __syncthreads();
        for (int i = tid; i < 1024; i += 256) {
            int row = i >> 4, c4 = i & 15;
            int col = h * 64 + c4 * 4;
            int s = ssh[row], r = rsh[row];
            float4 c = *(float4*)(Cf1 + row * 68 + c4 * 4);
            float4 zb = *(const float4*)(g_z + (size_t)s * 256 + col);
            float4 zc = *(const float4*)(g_z + (size_t)r * 256 + 128 + col);
            float4 b = *(const float4*)(B1s + col);
            float4 v = make_float4(
                fmaxf(c.x + zb.x + zc.x + b.x, 0.f),
                fmaxf(c.y + zb.y + zc.y + b.y, 0.f),
                fmaxf(c.z + zb.z + zc.z + b.z, 0.f),
                fmaxf(c.w + zb.w + zc.w + b.w, 0.f));
            split_store4(v, Ahi + row * 136 + col, Alo + row * 136 + col);
        }
        __syncthreads();
    }

    // ---- GEMM2 pipeline (chunks 0..3 of W2); chunk0 already in flight (group4)
#pragma unroll
    for (int sr = 0; sr < 2; sr++)
#pragma unroll
        for (int sc = 0; sc < 2; sc++) wmma::fill_fragment(acc[sr][sc], 0.f);
    cp_wait0();                 // group4 done
    __syncthreads();
    ES_STAGE_W(EW2_HI, EW2_LO, 32, w1h_b, w1l_b);     // group5 (WB1 free: Cf1 consumed)
    cp_commit();
    ES_MMA_CHUNK(0, W0h, W0l);
    __syncthreads();
    ES_STAGE_W(EW2_HI, EW2_LO, 64, w0h_b, w0l_b);     // group6
    cp_commit();
    cp_wait1();                 // group5 done
    __syncthreads();
    ES_MMA_CHUNK(32, W1h, W1l);
    __syncthreads();
    ES_STAGE_W(EW2_HI, EW2_LO, 96, w1h_b, w1l_b);     // group7
    cp_commit();
    cp_wait1();                 // group6 done
    __syncthreads();
    ES_MMA_CHUNK(64, W0h, W0l);
    __syncthreads();            // WB0 free -> Cf2
    cp_wait0();                 // group7 done
    __syncthreads();
    ES_MMA_CHUNK(96, W1h, W1l);

    // ---- epilogue 2 in column halves (Cf2 = WB0 region)
#pragma unroll 1
    for (int h = 0; h < 2; ++h) {
        if ((cg >> 1) == h) {
            int cgl = cg & 1;
#pragma unroll
            for (int sr = 0; sr < 2; sr++)
#pragma unroll
                for (int sc = 0; sc < 2; sc++)
                    wmma::store_matrix_sync(Cf2 + (rt * 32 + sr * 16) * 68 + cgl * 32 + sc * 16,
                                            acc[sr][sc], 68, wmma::mem_row_major);
        }
        __syncthreads();
        for (int i = tid; i < 1024; i += 256) {
            int row = i >> 4, c4 = i & 15;
            int col = h * 64 + c4 * 4;
            __nv_bfloat16* hp = elbase + row * 128 + col;
            float4 oldv = join4(hp, hp + 8192);
            float4 c = *(float4*)(Cf2 + row * 68 + c4 * 4);
            float4 b = *(const float4*)(B2s + col);
            float4 nv = make_float4(oldv.x + c.x + b.x, oldv.y + c.y + b.y,
                                    oldv.z + c.z + b.z, oldv.w + c.w + b.w);
            split_store4(nv, hp, hp + 8192);
            red_add_v4(g_agg + (size_t)rsh[row] * LL + col, nv);
        }
        if (h == 0) __syncthreads();
    }
}

// ---------------------------------------------------------------- node step (+fused projection), 3 blocks/SM
// region A: Ahi @0, Alo @17408 (64x136 planes)
// region B @34816 (34816 B):
//   64-row view: Whi @34816, Wlo @52224 (GEMM1 / proj / Cf full)
//   32-row bufs: N0h @34816, N0l @43520, N1h @52224, N1l @60928 (GEMM2)
#define N2_AHI 0
#define N2_ALO 17408
#define N2_W   34816
#define N2_WLO 52224
#define N2_B0H 34816
#define N2_B0L 43520
#define N2_B1H 52224
#define N2_B1L 60928
#define N2_SMEM 69632

// stage a 32-K NW2 chunk into a buffer
#define NS_STAGE_W2(KC, DSTH, DSTL) \
    for (int i = tid; i < 512; i += 256) { \
        int r_ = i >> 4, g_ = i & 15; \
        cp_async16((DSTH) + (uint32_t)(r_ * 272 + g_ * 16), wbase + NW2_HI + ((KC) + r_) * 128 + g_ * 8); \
        cp_async16((DSTL) + (uint32_t)(r_ * 272 + g_ * 16), wbase + NW2_LO + ((KC) + r_) * 128 + g_ * 8); \
    }

// MMA a 32-K chunk for node tiling (4 row groups x 2 col groups of 64)
#define NS_MMA_CHUNK(KC, WH, WL) \
    for (int kk = 0; kk < 32; kk += 16) { \
        AF ah, al; \
        wmma::load_matrix_sync(ah, Ahi + rt * 16 * 136 + (KC) + kk, 136); \
        wmma::load_matrix_sync(al, Alo + rt * 16 * 136 + (KC) + kk, 136); \
        _Pragma("unroll") \
        for (int f = 0; f < 4; f++) { \
            BF bh, bl; \
            wmma::load_matrix_sync(bh, (WH) + kk * 136 + cg * 64 + f * 16, 136); \
            wmma::load_matrix_sync(bl, (WL) + kk * 136 + cg * 64 + f * 16, 136); \
            wmma::mma_sync(acc[f], ah, bh, acc[f]); \
            wmma::mma_sync(acc[f], ah, bl, acc[f]); \
            wmma::mma_sync(acc[f], al, bh, acc[f]); \
        } \
    }

__global__ void __launch_bounds__(256, 3) k_node_step(
    int step, const float* __restrict__ B1, const float* __restrict__ B2, int do_proj)
{
    extern __shared__ char smc[];
    __nv_bfloat16* Ahi = (__nv_bfloat16*)(smc + N2_AHI);
    __nv_bfloat16* Alo = (__nv_bfloat16*)(smc + N2_ALO);
    __nv_bfloat16* Whi = (__nv_bfloat16*)(smc + N2_W);
    __nv_bfloat16* Wlo = (__nv_bfloat16*)(smc + N2_WLO);
    __nv_bfloat16* N0h = (__nv_bfloat16*)(smc + N2_B0H);
    __nv_bfloat16* N0l = (__nv_bfloat16*)(smc + N2_B0L);
    __nv_bfloat16* N1h = (__nv_bfloat16*)(smc + N2_B1H);
    __nv_bfloat16* N1l = (__nv_bfloat16*)(smc + N2_B1L);
    float*         Cf  = (float*)(smc + N2_W);      // full 64x132 fp32 view
    const int tid = threadIdx.x;
    const int w = tid >> 5, rt = w >> 1, cg = w & 1;
    const int nbase = blockIdx.x * 64;
    const bool full = (nbase + 64 <= NN);
    const __nv_bfloat16* wbase = g_ws + (size_t)step * STEP_W;
    const uint32_t whi_b = smem_u32(Whi), wlo_b = smem_u32(Wlo);
    const uint32_t b0h = smem_u32(N0h), b0l = smem_u32(N0l);
    const uint32_t b1h = smem_u32(N1h), b1l = smem_u32(N1l);

    CF acc[4];
#pragma unroll
    for (int f = 0; f < 4; f++) wmma::fill_fragment(acc[f], 0.f);

    // ---- GEMM1: X[64x256] @ NW1; W staged FIRST so cp.async overlaps the X gather
#pragma unroll 1
    for (int kc = 0; kc < 256; kc += 64) {
        __syncthreads();
        for (int i = tid; i < 1024; i += 256) {
            int rr = i >> 4, g = i & 15;
            cp_async16(whi_b + (uint32_t)(rr * 272 + g * 16), wbase + NW1_HI + (kc + rr) * 128 + g * 8);
            cp_async16(wlo_b + (uint32_t)(rr * 272 + g * 16), wbase + NW1_LO + (kc + rr) * 128 + g * 8);
        }
        cp_commit();
        // X gather overlaps the W transfer
        for (int i = tid; i < 1024; i += 256) {
            int row = i >> 4, g = i & 15;
            int n = nbase + row;
            float4 v = make_float4(0.f, 0.f, 0.f, 0.f);
            if (n < NN) {
                if (kc < 128) {
                    v = ((const float4*)(g_nl + (size_t)n * LL))[(kc >> 2) + g];
                } else {
                    float4* ap = (float4*)(g_agg + (size_t)n * LL) + (((kc - 128) >> 2) + g);
                    v = *ap;
                    *ap = make_float4(0.f, 0.f, 0.f, 0.f);
                }
            }
            split_store4(v, Ahi + row * 136 + g * 4, Alo + row * 136 + g * 4);
        }
        cp_wait0();
        __syncthreads();
        for (int kk = 0; kk < 64; kk += 16) {
            AF ah, al;
            wmma::load_matrix_sync(ah, Ahi + rt * 16 * 136 + kk, 136);
            wmma::load_matrix_sync(al, Alo + rt * 16 * 136 + kk, 136);
#pragma unroll
            for (int f = 0; f < 4; f++) {
                BF bh, bl;
                wmma::load_matrix_sync(bh, Whi + kk * 136 + cg * 64 + f * 16, 136);
                wmma::load_matrix_sync(bl, Wlo + kk * 136 + cg * 64 + f * 16, 136);
                wmma::mma_sync(acc[f], ah, bh, acc[f]);
                wmma::mma_sync(acc[f], ah, bl, acc[f]);
                wmma::mma_sync(acc[f], al, bh, acc[f]);
            }
        }
    }
    __syncthreads();
#pragma unroll
    for (int f = 0; f < 4; f++)
        wmma::store_matrix_sync(Cf + rt * 16 * 132 + cg * 64 + f * 16, acc[f], 132, wmma::mem_row_major);
    __syncthreads();
    // bias + relu -> H planes (region A; X fully consumed)
    for (int i = tid; i < 64 * 32; i += 256) {
        int row = i >> 5, c4 = i & 31;
        float4 v = *(float4*)(Cf + row * 132 + c4 * 4);
        float4 bb = ((const float4*)B1)[c4];
        v.x = fmaxf(v.x + bb.x, 0.f);
        v.y = fmaxf(v.y + bb.y, 0.f);
        v.z = fmaxf(v.z + bb.z, 0.f);
        v.w = fmaxf(v.w + bb.w, 0.f);
        split_store4(v, Ahi + row * 136 + c4 * 4, Alo + row * 136 + c4 * 4);
    }
    __syncthreads();

    // ---- GEMM2: H[64x128] @ NW2, double-buffered 32-K chunks (region B free after Cf consumed)
#pragma unroll
    for (int f = 0; f < 4; f++) wmma::fill_fragment(acc[f], 0.f);
    NS_STAGE_W2(0, b0h, b0l);
    cp_commit();
    NS_STAGE_W2(32, b1h, b1l);
    cp_commit();
    cp_wait1();                 // chunk0 done
    __syncthreads();
    NS_MMA_CHUNK(0, N0h, N0l);
    __syncthreads();
    NS_STAGE_W2(64, b0h, b0l);
    cp_commit();
    cp_wait1();                 // chunk1 done
    __syncthreads();
    NS_MMA_CHUNK(32, N1h, N1l);
    __syncthreads();
    NS_STAGE_W2(96, b1h, b1l);
    cp_commit();
    cp_wait1();                 // chunk2 done
    __syncthreads();
    NS_MMA_CHUNK(64, N0h, N0l);
    cp_wait0();                 // chunk3 done
    __syncthreads();
    NS_MMA_CHUNK(96, N1h, N1l);
    __syncthreads();
#pragma unroll
    for (int f = 0; f < 4; f++)
        wmma::store_matrix_sync(Cf + rt * 16 * 132 + cg * 64 + f * 16, acc[f], 132, wmma::mem_row_major);
    __syncthreads();

    // ---- epilogue: nl += C2 + b2; write back; H planes (region A) for projection
    for (int i = tid; i < 64 * 32; i += 256) {
        int row = i >> 5, c4 = i & 31;
        int n = nbase + row;
        float4 nv = make_float4(0.f, 0.f, 0.f, 0.f);
        if (n < NN) {
            float4 oldv = ((const float4*)(g_nl + (size_t)n * LL))[c4];
            float4 c2 = *(float4*)(Cf + row * 132 + c4 * 4);
            float4 bb = ((const float4*)B2)[c4];
            nv = make_float4(oldv.x + c2.x + bb.x, oldv.y + c2.y + bb.y,
                             oldv.z + c2.z + bb.z, oldv.w + c2.w + bb.w);
            ((float4*)(g_nl + (size_t)n * LL))[c4] = nv;
        }
        if (do_proj)
            split_store4(nv, Ahi + row * 136 + c4 * 4, Alo + row * 136 + c4 * 4);
    }

    if (do_proj) {
        const __nv_bfloat16* wn = g_ws + (size_t)(step + 1) * STEP_W;
#pragma unroll 1
        for (int half = 0; half < 2; ++half) {
#pragma unroll
            for (int f = 0; f < 4; f++) wmma::fill_fragment(acc[f], 0.f);
#pragma unroll 1
            for (int kc = 0; kc < 128; kc += 64) {
                __syncthreads();
                for (int i = tid; i < 1024; i += 256) {
                    int rr = i >> 4, g = i & 15;
                    cp_async16(whi_b + (uint32_t)(rr * 272 + g * 16),
                               wn + PRJ_HI + (size_t)(kc + rr) * 256 + half * 128 + g * 8);
                    cp_async16(wlo_b + (uint32_t)(rr * 272 + g * 16),
                               wn + PRJ_LO + (size_t)(kc + rr) * 256 + half * 128 + g * 8);
                }
                cp_commit_wait();
                __syncthreads();
                for (int kk = 0; kk < 64; kk += 16) {
                    AF ah, al;
                    wmma::load_matrix_sync(ah, Ahi + rt * 16 * 136 + kc + kk, 136);
                    wmma::load_matrix_sync(al, Alo + rt * 16 * 136 + kc + kk, 136);
#pragma unroll
                    for (int f = 0; f < 4; f++) {
                        BF bh, bl;
                        wmma::load_matrix_sync(bh, Whi + kk * 136 + cg * 64 + f * 16, 136);
                        wmma::load_matrix_sync(bl, Wlo + kk * 136 + cg * 64 + f * 16, 136);
                        wmma::mma_sync(acc[f], ah, bh, acc[f]);
                        wmma::mma_sync(acc[f], ah, bl, acc[f]);
                        wmma::mma_sync(acc[f], al, bh, acc[f]);
                    }
                }
            }
            if (full) {
#pragma unroll
                for (int f = 0; f < 4; f++)
                    wmma::store_matrix_sync(g_z + (size_t)(nbase + rt * 16) * 256 + half * 128 + cg * 64 + f * 16,
                                            acc[f], 256, wmma::mem_row_major);
            } else {
                __syncthreads();
#pragma unroll
                for (int f = 0; f < 4; f++)
                    wmma::store_matrix_sync(Cf + rt * 16 * 132 + cg * 64 + f * 16, acc[f], 132, wmma::mem_row_major);
                __syncthreads();
                for (int i = tid; i < 64 * 32; i += 256) {
                    int row = i >> 5, c4 = i & 31;
                    int n = nbase + row;
                    if (n < NN)
                        ((float4*)(g_z + (size_t)n * 256 + half * 128))[c4] =
                            *(float4*)(Cf + row * 132 + c4 * 4);
                }
            }
        }
    }
}

// ---------------------------------------------------------------- decoder (SIMT fp32; exact)
__global__ void __launch_bounds__(128) k_decoder(
    const float* __restrict__ W1, const float* __restrict__ B1,
    const float* __restrict__ W2, const float* __restrict__ B2,
    float* __restrict__ out)
{
    __shared__ float Xs[32][128];
    __shared__ float H[32][128];
    const int tid = threadIdx.x;
    const int nbase = blockIdx.x * 32;

    for (int i = tid; i < 32 * 32; i += 128) {
        int n = i >> 5, c4 = i & 31;
        int gn = nbase + n;
        float4 v = make_float4(0.f, 0.f, 0.f, 0.f);
        if (gn < NN) v = ((const float4*)(g_nl + (size_t)gn * LL))[c4];
        ((float4*)Xs[n])[c4] = v;
    }
    __syncthreads();

    const int j = tid;
#pragma unroll 1
    for (int n = 0; n < 32; n++) {
        float acc = B1[j];
#pragma unroll 8
        for (int k = 0; k < 128; k++) acc += Xs[n][k] * W1[k * 128 + j];
        H[n][j] = fmaxf(acc, 0.f);
    }
    __syncthreads();

    if (tid < 96) {
        int n = tid / 3, d = tid % 3;
        int gn = nbase + n;
        float acc = B2[d];
#pragma unroll 8
        for (int k = 0; k < 128; k++) acc += H[n][k] * W2[k * 3 + d];
        if (gn < NN) out[gn * 3 + d] = acc;
    }
}

// ---------------------------------------------------------------- launch
extern "C" void kernel_launch(void* const* d_in, const int* in_sizes, int n_in,
                              void* d_out, int out_size)
{
    const float* pos   = (const float*)d_in[0];
    const float* vel   = (const float*)d_in[1];
    const int*   rid   = (const int*)d_in[2];
    const int*   snd   = (const int*)d_in[3];
    const int*   rcv   = (const int*)d_in[4];
    const float* remb  = (const float*)d_in[5];
    const float* ne_w1 = (const float*)d_in[6];
    const float* ne_b1 = (const float*)d_in[7];
    const float* ne_w2 = (const float*)d_in[8];
    const float* ne_b2 = (const float*)d_in[9];
    const float* ee_w1 = (const float*)d_in[10];
    const float* ee_b1 = (const float*)d_in[11];
    const float* ee_w2 = (const float*)d_in[12];
    const float* ee_b2 = (const float*)d_in[13];
    const float* pe_w1 = (const float*)d_in[14];
    const float* pe_b1 = (const float*)d_in[15];
    const float* pe_w2 = (const float*)d_in[16];
    const float* pe_b2 = (const float*)d_in[17];
    const float* pn_w1 = (const float*)d_in[18];
    const float* pn_b1 = (const float*)d_in[19];
    const float* pn_w2 = (const float*)d_in[20];
    const float* pn_b2 = (const float*)d_in[21];
    const float* de_w1 = (const float*)d_in[22];
    const float* de_b1 = (const float*)d_in[23];
    const float* de_w2 = (const float*)d_in[24];
    const float* de_b2 = (const float*)d_in[25];

    cudaFuncSetAttribute(k_edge_step, cudaFuncAttributeMaxDynamicSharedMemorySize, ES_SMEM);
    cudaFuncSetAttribute(k_node_step, cudaFuncAttributeMaxDynamicSharedMemorySize, N2_SMEM);
    cudaFuncSetAttribute(k_node_enc_proj, cudaFuncAttributeMaxDynamicSharedMemorySize, NEP_SMEM);
    cudaFuncSetAttribute(k_edge_enc2, cudaFuncAttributeMaxDynamicSharedMemorySize, EN_SMEM);

    k_setup<<<4740, 256>>>(pe_w1, pe_w2, pn_w1, pn_w2, ee_w2);
    k_degcenter<<<3229, 256>>>(rcv, pos);
    k_node_enc_proj<<<NB_ENC, 256, NEP_SMEM>>>(pos, vel, rid, remb, ne_w1, ne_b1, ne_w2, ne_b2);
    k_edge_enc2<<<EB_ENC, 256, EN_SMEM>>>(pos, vel, rid, snd, rcv, ee_w1, ee_b1, ee_b2);

    for (int st = 0; st < NSTEPS; st++) {
        k_edge_step<<<EE / 64, 256, ES_SMEM>>>(
            snd, rcv, st, pe_b1 + (size_t)st * 128, pe_b2 + (size_t)st * 128);
        k_node_step<<<(NN + 63) / 64, 256, N2_SMEM>>>(
            st, pn_b1 + (size_t)st * 128, pn_b2 + (size_t)st * 128, (st < NSTEPS - 1) ? 1 : 0);
    }

    k_decoder<<<(NN + 31) / 32, 128>>>(de_w1, de_b1, de_w2, de_b2, (float*)d_out);
}